// round 2
// baseline (speedup 1.0000x reference)
#include <cuda_runtime.h>
#include <math.h>

#define BB 32
#define LL 1024
#define MN 512
#define SD 256
#define VD 64
#define D3 192
#define DM 256
#define NH 8
#define DK 32

typedef unsigned long long u64;

// packed fp32x2 FMA (SASS FFMA2) — bitwise identical to 2 scalar FFMAs
__device__ __forceinline__ u64 ffma2(u64 a, u64 b, u64 c) {
    u64 d;
    asm("fma.rn.f32x2 %0, %1, %2, %3;" : "=l"(d) : "l"(a), "l"(b), "l"(c));
    return d;
}
__device__ __forceinline__ u64 pack2(float lo, float hi) {
    u64 d;
    asm("mov.b64 %0, {%1, %2};" : "=l"(d) : "r"(__float_as_uint(lo)), "r"(__float_as_uint(hi)));
    return d;
}
__device__ __forceinline__ float lo2(u64 v) { return __uint_as_float((unsigned)v); }
__device__ __forceinline__ float hi2(u64 v) { return __uint_as_float((unsigned)(v >> 32)); }

// ---------------- scratch (device globals; no allocation allowed) ----------------
__device__ float g_pos_sum[MN * D3];
__device__ float g_gamma[BB * MN * DM];
__device__ float g_xm[BB * MN * D3];
__device__ float g_pe[BB * MN * D3];
__device__ float g_Q[BB * LL * DM];
__device__ float g_K[BB * MN * DM];
__device__ float g_V[BB * MN * DM];
__device__ float g_attn[BB * LL * DM];
__device__ float g_fc[BB * LL * DM];

// ---------------- pos_sum[j,d] = sum_i emb[clip(j-i,-30,30)+30, d] ----------------
__global__ void possum_kernel(const float* __restrict__ emb) {
    int j = blockIdx.x;
    int d = threadIdx.x;   // 192 threads
    float acc = 0.f;
    #pragma unroll
    for (int delta = -29; delta <= 29; delta++) {
        int i = j - delta;
        if (i >= 0 && i < MN) acc += emb[(delta + 30) * D3 + d];
    }
    int cpos = j - 29;        // count for delta = +30
    if (cpos > 0) acc += (float)cpos * emb[60 * D3 + d];
    int cneg = 482 - j;       // count for delta = -30
    if (cneg > 0) acc += (float)cneg * emb[0 * D3 + d];
    g_pos_sum[j * D3 + d] = acc;
}

// ---------------- GEMM (f32x2): C[M,N] = A[M,K] * W[N,K]^T (+bias, opt sigmoid) ----
// accumulator paired along m; B staged duplicated (b,b) so each FFMA2 does 2 rows
__global__ void gemm_kernel(const float* __restrict__ A, const float* __restrict__ W,
                            const float* __restrict__ bias, float* __restrict__ C,
                            int M, int N, int Kd, int sigmoidFlag) {
    __shared__ float As[16][68];
    __shared__ float2 Bd[16][65];   // dup pairs, slot = (n&3)*16 + (n>>2)
    int tid = threadIdx.x;
    int tx = tid & 15, ty = tid >> 4;
    int m0 = blockIdx.y * 64, n0 = blockIdx.x * 64;

    u64 acc[2][4];
    #pragma unroll
    for (int i = 0; i < 2; i++)
        #pragma unroll
        for (int j = 0; j < 4; j++) acc[i][j] = 0ull;

    for (int kk = 0; kk < Kd; kk += 16) {
        #pragma unroll
        for (int l = 0; l < 4; l++) {
            int idx = tid + l * 256;
            int m = idx >> 4, k = idx & 15;
            As[k][m] = A[(size_t)(m0 + m) * Kd + kk + k];
            float v = W[(size_t)(n0 + m) * Kd + kk + k];
            Bd[k][(m & 3) * 16 + (m >> 2)] = make_float2(v, v);
        }
        __syncthreads();
        #pragma unroll
        for (int k = 0; k < 16; k++) {
            ulonglong2 av = *(const ulonglong2*)&As[k][ty * 4];   // 4 rows as 2 packed pairs
            #pragma unroll
            for (int j = 0; j < 4; j++) {
                u64 bv = *(const u64*)&Bd[k][j * 16 + tx];
                acc[0][j] = ffma2(av.x, bv, acc[0][j]);
                acc[1][j] = ffma2(av.y, bv, acc[1][j]);
            }
        }
        __syncthreads();
    }

    #pragma unroll
    for (int i2 = 0; i2 < 2; i2++) {
        float olo[4], ohi[4];
        #pragma unroll
        for (int j = 0; j < 4; j++) {
            float vl = lo2(acc[i2][j]);
            float vh = hi2(acc[i2][j]);
            if (bias) { float bb = bias[n0 + tx * 4 + j]; vl += bb; vh += bb; }
            if (sigmoidFlag) {
                vl = 1.f / (1.f + __expf(-vl));
                vh = 1.f / (1.f + __expf(-vh));
            }
            olo[j] = vl; ohi[j] = vh;
        }
        int r = m0 + ty * 4 + 2 * i2;
        *(float4*)&C[(size_t)r * N + n0 + tx * 4]       = make_float4(olo[0], olo[1], olo[2], olo[3]);
        *(float4*)&C[(size_t)(r + 1) * N + n0 + tx * 4] = make_float4(ohi[0], ohi[1], ohi[2], ohi[3]);
    }
}

// ---------------- multi-scale conv: xm[b,s,0:64|64:128|128:192] = conv3|5|7 --------
template <int K>
__device__ __forceinline__ void conv_do(float* xs, float* ws,
                                        const float* __restrict__ w,
                                        const float* __restrict__ bias,
                                        int coff, int b, int s0, int tid) {
    __syncthreads();   // previous users of ws done
    // stage weights transposed: ws[(i*K + t)*64 + oc] = w[oc][i][t]
    for (int idx = tid; idx < 64 * 64 * K; idx += 256) {
        int t = idx % K;
        int i = (idx / K) & 63;
        int o = idx / (K * 64);
        ws[(i * K + t) * 64 + o] = w[idx];
    }
    __syncthreads();

    int oc = tid & 63;
    int pbase = (tid >> 6) * 16;
    float acc[16];
    float bv = bias[oc];
    #pragma unroll
    for (int pp = 0; pp < 16; pp++) acc[pp] = bv;

    for (int i = 0; i < 64; i++) {
        float xvr[16 + K - 1];
        #pragma unroll
        for (int j = 0; j < 16 + K - 1; j++)
            xvr[j] = xs[(pbase + j + 3 - K / 2) * 64 + i];
        #pragma unroll
        for (int t = 0; t < K; t++) {
            float wv = ws[(i * K + t) * 64 + oc];
            #pragma unroll
            for (int pp = 0; pp < 16; pp++) acc[pp] += xvr[pp + t] * wv;
        }
    }
    #pragma unroll
    for (int pp = 0; pp < 16; pp++)
        g_xm[((size_t)b * MN + s0 + pbase + pp) * D3 + coff + oc] = acc[pp];
}

__global__ void conv_kernel(const float* __restrict__ xv,
                            const float* __restrict__ w3, const float* __restrict__ b3,
                            const float* __restrict__ w5, const float* __restrict__ b5,
                            const float* __restrict__ w7, const float* __restrict__ b7) {
    extern __shared__ float sh[];
    float* xs = sh;             // [70][64] halo tile
    float* ws = sh + 70 * 64;   // weight stage (max 64*64*7)
    int blk = blockIdx.x;
    int b = blk >> 3;
    int s0 = (blk & 7) * 64;
    int tid = threadIdx.x;

    for (int idx = tid; idx < 70 * 64; idx += 256) {
        int r = idx >> 6, i = idx & 63;
        int s = s0 - 3 + r;
        xs[idx] = (s >= 0 && s < MN) ? xv[((size_t)b * MN + s) * VD + i] : 0.f;
    }
    conv_do<3>(xs, ws, w3, b3, 0, b, s0, tid);
    conv_do<5>(xs, ws, w5, b5, 64, b, s0, tid);
    conv_do<7>(xs, ws, w7, b7, 128, b, s0, tid);
}

// ---------------- rel-pos encoding (closed form, elementwise) ----------------------
__global__ void pe_kernel(const float* __restrict__ emb,
                          const float* __restrict__ dww, const float* __restrict__ dwb) {
    int idx = blockIdx.x * 256 + threadIdx.x;
    if (idx >= BB * MN * D3) return;
    int d = idx % D3;
    int j = (idx / D3) & (MN - 1);
    float xc = g_xm[idx];
    float fC = xc + emb[30 * D3 + d];
    float fL = 0.f, fR = 0.f;
    if (j > 0)      fL = g_xm[idx - D3] + emb[29 * D3 + d];
    if (j < MN - 1) fR = g_xm[idx + D3] + emb[31 * D3 + d];
    float diag = fL * dww[d * 3 + 0] + fC * dww[d * 3 + 1] + fR * dww[d * 3 + 2] + dwb[d];
    g_pe[idx] = xc + (g_pos_sum[j * D3 + d] - fC + diag) * (1.0f / (float)MN);
}

// ---------------- attention (f32x2): per (b,h), K/V resident in smem ---------------
__global__ void attn_kernel() {
    extern __shared__ float sh[];
    float* Ks = sh;             // [512][32]
    float* Vs = sh + MN * DK;   // [512][32]
    int blk = blockIdx.x;       // b*32 + h*4 + qt
    int qt = blk & 3;
    int h = (blk >> 2) & 7;
    int b = blk >> 5;
    int tid = threadIdx.x;

    const float* Kg = g_K + (size_t)b * MN * DM + h * DK;
    const float* Vg = g_V + (size_t)b * MN * DM + h * DK;
    for (int idx = tid; idx < MN * 8; idx += 256) {
        int s = idx >> 3, d4 = idx & 7;
        *(float4*)&Ks[s * DK + d4 * 4] = *(const float4*)&Kg[(size_t)s * DM + d4 * 4];
        *(float4*)&Vs[s * DK + d4 * 4] = *(const float4*)&Vg[(size_t)s * DM + d4 * 4];
    }
    __syncthreads();

    int l = qt * 256 + tid;
    const float* Qg = g_Q + ((size_t)b * LL + l) * DM + h * DK;
    u64 q2[16];   // q paired along d, pre-scaled by 1/sqrt(dk)
    #pragma unroll
    for (int d4 = 0; d4 < 8; d4++) {
        float4 v = *(const float4*)&Qg[d4 * 4];
        const float sc = 0.17677669529663687f;
        q2[d4 * 2 + 0] = pack2(v.x * sc, v.y * sc);
        q2[d4 * 2 + 1] = pack2(v.z * sc, v.w * sc);
    }
    float lsum = 0.f;
    u64 o2[16];
    #pragma unroll
    for (int d = 0; d < 16; d++) o2[d] = 0ull;

    // scores are bounded well inside expf's range: no max-tracking needed
    #pragma unroll 2
    for (int s = 0; s < MN; s++) {
        const ulonglong2* K4 = (const ulonglong2*)(Ks + s * DK);
        u64 xa = 0ull, xb = 0ull;   // two chains for ILP
        #pragma unroll
        for (int t = 0; t < 8; t++) {
            ulonglong2 kv = K4[t];
            xa = ffma2(q2[t * 2 + 0], kv.x, xa);
            xb = ffma2(q2[t * 2 + 1], kv.y, xb);
        }
        float x = lo2(xa) + hi2(xa) + lo2(xb) + hi2(xb);
        float p = __expf(x);
        lsum += p;
        u64 p2 = pack2(p, p);
        const ulonglong2* V4 = (const ulonglong2*)(Vs + s * DK);
        #pragma unroll
        for (int t = 0; t < 8; t++) {
            ulonglong2 vv = V4[t];
            o2[t * 2 + 0] = ffma2(p2, vv.x, o2[t * 2 + 0]);
            o2[t * 2 + 1] = ffma2(p2, vv.y, o2[t * 2 + 1]);
        }
    }
    float inv = 1.f / lsum;
    float* Og = g_attn + ((size_t)b * LL + l) * DM + h * DK;
    #pragma unroll
    for (int t = 0; t < 8; t++) {
        *(float4*)&Og[t * 4] = make_float4(lo2(o2[t * 2]) * inv, hi2(o2[t * 2]) * inv,
                                           lo2(o2[t * 2 + 1]) * inv, hi2(o2[t * 2 + 1]) * inv);
    }
}

// ---------------- gate * fc + residual + LayerNorm ---------------------------------
__global__ void final_kernel(const float* __restrict__ xs,
                             const float* __restrict__ lnw, const float* __restrict__ lnb,
                             float* __restrict__ out) {
    __shared__ float red[16];
    int row = blockIdx.x;          // b*1024 + l
    int b = row >> 10;
    int l = row & 1023;
    int c = threadIdx.x;
    size_t off = (size_t)row * DM + c;
    float fcv = g_fc[off];
    float gam = g_gamma[((size_t)b * MN + (l & (MN - 1))) * DM + c];
    float v = xs[off] + gam * fcv;

    float s1 = v, s2 = v * v;
    #pragma unroll
    for (int d = 16; d; d >>= 1) {
        s1 += __shfl_xor_sync(0xFFFFFFFFu, s1, d);
        s2 += __shfl_xor_sync(0xFFFFFFFFu, s2, d);
    }
    int warp = c >> 5, lane = c & 31;
    if (lane == 0) { red[warp] = s1; red[8 + warp] = s2; }
    __syncthreads();
    float t1 = 0.f, t2 = 0.f;
    #pragma unroll
    for (int w = 0; w < 8; w++) { t1 += red[w]; t2 += red[8 + w]; }
    float mu = t1 * (1.f / 256.f);
    float var = t2 * (1.f / 256.f) - mu * mu;
    out[off] = (v - mu) * rsqrtf(var + 1e-5f) * lnw[c] + lnb[c];
}

// ---------------- launch -----------------------------------------------------------
extern "C" void kernel_launch(void* const* d_in, const int* in_sizes, int n_in,
                              void* d_out, int out_size) {
    const float* x_spatial  = (const float*)d_in[0];
    const float* x_velocity = (const float*)d_in[1];
    const float* Wg    = (const float*)d_in[2];
    const float* ms_w3 = (const float*)d_in[3];
    const float* ms_b3 = (const float*)d_in[4];
    const float* ms_w5 = (const float*)d_in[5];
    const float* ms_b5 = (const float*)d_in[6];
    const float* ms_w7 = (const float*)d_in[7];
    const float* ms_b7 = (const float*)d_in[8];
    const float* rel_emb = (const float*)d_in[9];
    const float* dw_w  = (const float*)d_in[10];
    const float* dw_b  = (const float*)d_in[11];
    const float* Wq    = (const float*)d_in[12];
    const float* Wk    = (const float*)d_in[13];
    const float* Wv    = (const float*)d_in[14];
    const float* fc_w  = (const float*)d_in[15];
    const float* fc_b  = (const float*)d_in[16];
    const float* ln_w  = (const float*)d_in[17];
    const float* ln_b  = (const float*)d_in[18];
    float* out = (float*)d_out;

    float *p_gamma, *p_pe, *p_Q, *p_K, *p_V, *p_attn, *p_fc;
    cudaGetSymbolAddress((void**)&p_gamma, g_gamma);
    cudaGetSymbolAddress((void**)&p_pe,    g_pe);
    cudaGetSymbolAddress((void**)&p_Q,     g_Q);
    cudaGetSymbolAddress((void**)&p_K,     g_K);
    cudaGetSymbolAddress((void**)&p_V,     g_V);
    cudaGetSymbolAddress((void**)&p_attn,  g_attn);
    cudaGetSymbolAddress((void**)&p_fc,    g_fc);

    const int CONV_SMEM = (70 * 64 + 64 * 64 * 7) * 4;   // 132,608 B
    const int ATTN_SMEM = 2 * MN * DK * 4;               // 131,072 B
    cudaFuncSetAttribute(conv_kernel, cudaFuncAttributeMaxDynamicSharedMemorySize, CONV_SMEM);
    cudaFuncSetAttribute(attn_kernel, cudaFuncAttributeMaxDynamicSharedMemorySize, ATTN_SMEM);

    possum_kernel<<<MN, D3>>>(rel_emb);

    // Gamma = sigmoid(x_velocity @ Wg^T)   [16384, 256]
    gemm_kernel<<<dim3(DM / 64, BB * MN / 64), 256>>>(x_velocity, Wg, nullptr, p_gamma,
                                                      BB * MN, DM, VD, 1);
    conv_kernel<<<BB * (MN / 64), 256, CONV_SMEM>>>(x_velocity, ms_w3, ms_b3,
                                                    ms_w5, ms_b5, ms_w7, ms_b7);
    pe_kernel<<<(BB * MN * D3 + 255) / 256, 256>>>(rel_emb, dw_w, dw_b);

    // Q / K / V projections
    gemm_kernel<<<dim3(DM / 64, BB * LL / 64), 256>>>(x_spatial, Wq, nullptr, p_Q,
                                                      BB * LL, DM, SD, 0);
    gemm_kernel<<<dim3(DM / 64, BB * MN / 64), 256>>>(p_pe, Wk, nullptr, p_K,
                                                      BB * MN, DM, D3, 0);
    gemm_kernel<<<dim3(DM / 64, BB * MN / 64), 256>>>(p_pe, Wv, nullptr, p_V,
                                                      BB * MN, DM, D3, 0);

    attn_kernel<<<BB * NH * (LL / 256), 256, ATTN_SMEM>>>();

    gemm_kernel<<<dim3(DM / 64, BB * LL / 64), 256>>>(p_attn, fc_w, fc_b, p_fc,
                                                      BB * LL, DM, DM, 0);
    final_kernel<<<BB * LL, 256>>>(x_spatial, ln_w, ln_b, out);
}

// round 4
// speedup vs baseline: 1.2827x; 1.2827x over previous
#include <cuda_runtime.h>
#include <math.h>
#include <stdint.h>

#define BB 32
#define LL 1024
#define MN 512
#define SD 256
#define VD 64
#define D3 192
#define DM 256
#define NH 8
#define DK 32

// ---------------- scratch (device globals; no allocation allowed) ----------------
__device__ float g_pos_sum[MN * D3];
__device__ float g_gamma[BB * MN * DM];
__device__ float g_xm[BB * MN * D3];
__device__ float g_pe[BB * MN * D3];
__device__ float g_Q[BB * LL * DM];
__device__ float g_K[BB * MN * DM];
__device__ float g_V[BB * MN * DM];
__device__ float g_attn[BB * LL * DM];
__device__ float g_fc[BB * LL * DM];

// ================= mma.sync tf32 helpers (sm_80+ features, no 'a' target) =========
__device__ __forceinline__ uint32_t f2tf32(float f) {
    uint32_t u;
    asm("cvt.rna.tf32.f32 %0, %1;" : "=r"(u) : "f"(f));
    return u;
}
__device__ __forceinline__ void mma_tf32(float* c, uint4 a, uint2 b) {
    asm("mma.sync.aligned.m16n8k8.row.col.f32.tf32.tf32.f32 "
        "{%0,%1,%2,%3}, {%4,%5,%6,%7}, {%8,%9}, {%0,%1,%2,%3};"
        : "+f"(c[0]), "+f"(c[1]), "+f"(c[2]), "+f"(c[3])
        : "r"(a.x), "r"(a.y), "r"(a.z), "r"(a.w), "r"(b.x), "r"(b.y));
}

// dynamic smem layout (uint32 indices): double-buffered fragment-ordered A and B
#define GSM_A0 0
#define GSM_A1 4096
#define GSM_B0 8192
#define GSM_B1 12288
#define GSM_BYTES (16384 * 4)

// ---------------- tensor-core GEMM: C[M,256] = A[M,Kd] * W[256,Kd]^T ---------------
// block = 128 rows x 128 cols; 8 warps as 2(m) x 4(n); warp = 64x32; tf32 HMMA
__global__ void __launch_bounds__(256, 1) mgemm_kernel(
    const float* __restrict__ A, const float* __restrict__ W,
    const float* __restrict__ bias, float* __restrict__ C,
    int Kd, int sigmoidFlag) {
    extern __shared__ uint32_t gsm[];
    int tid = threadIdx.x;
    int lane = tid & 31, wid = tid >> 5;
    int mw = wid & 1, nw = wid >> 1;
    int m0 = blockIdx.y * 128;
    int n0b = blockIdx.x * 128;
    int NC = Kd >> 5;

    float acc[4][4][4];
    #pragma unroll
    for (int t = 0; t < 4; t++)
        #pragma unroll
        for (int u = 0; u < 4; u++)
            #pragma unroll
            for (int j = 0; j < 4; j++) acc[t][u][j] = 0.f;

    // ---- stage chunk 0 (fragment-order permutation + tf32 convert) ----
    {
        #pragma unroll
        for (int i = 0; i < 4; i++) {
            int g = tid + i * 256;
            int row = g >> 3, kq = g & 7;
            float4 va = *(const float4*)&A[(size_t)(m0 + row) * Kd + kq * 4];
            float4 vb = *(const float4*)&W[(size_t)(n0b + row) * Kd + kq * 4];
            float fa[4] = {va.x, va.y, va.z, va.w};
            float fb[4] = {vb.x, vb.y, vb.z, vb.w};
            #pragma unroll
            for (int e = 0; e < 4; e++) {
                int k = kq * 4 + e;
                int cc = k >> 3, ln = ((row & 7) << 2) | (k & 3);
                int t = row >> 4, j = ((k >> 2) & 1) * 2 + ((row >> 3) & 1);
                gsm[GSM_A0 + ((((t * 4 + cc) * 32 + ln) << 2) + j)] = f2tf32(fa[e]);
                int u = row >> 3, f = (k >> 2) & 1;
                gsm[GSM_B0 + ((((u * 4 + cc) * 32 + ln) << 1) + f)] = f2tf32(fb[e]);
            }
        }
    }
    __syncthreads();

    for (int c = 0; c < NC; c++) {
        const uint32_t* As = gsm + ((c & 1) ? GSM_A1 : GSM_A0);
        const uint32_t* Bs = gsm + ((c & 1) ? GSM_B1 : GSM_B0);

        // prefetch next chunk into registers (overlaps HMMA below)
        float4 pa[4], pb[4];
        if (c + 1 < NC) {
            int kk = (c + 1) * 32;
            #pragma unroll
            for (int i = 0; i < 4; i++) {
                int g = tid + i * 256;
                int row = g >> 3, kq = g & 7;
                pa[i] = *(const float4*)&A[(size_t)(m0 + row) * Kd + kk + kq * 4];
                pb[i] = *(const float4*)&W[(size_t)(n0b + row) * Kd + kk + kq * 4];
            }
        }

        // compute: 4 k8-steps x 16 mma
        #pragma unroll
        for (int c8 = 0; c8 < 4; c8++) {
            uint4 av[4];
            uint2 bv[4];
            #pragma unroll
            for (int t = 0; t < 4; t++)
                av[t] = *(const uint4*)&As[(((mw * 4 + t) * 4 + c8) * 32 + lane) << 2];
            #pragma unroll
            for (int u = 0; u < 4; u++)
                bv[u] = *(const uint2*)&Bs[(((nw * 4 + u) * 4 + c8) * 32 + lane) << 1];
            #pragma unroll
            for (int t = 0; t < 4; t++)
                #pragma unroll
                for (int u = 0; u < 4; u++)
                    mma_tf32(acc[t][u], av[t], bv[u]);
        }

        if (c + 1 < NC) {
            __syncthreads();   // all warps done reading the buffer we are about to overwrite
            uint32_t* Ad = gsm + (((c + 1) & 1) ? GSM_A1 : GSM_A0);
            uint32_t* Bd = gsm + (((c + 1) & 1) ? GSM_B1 : GSM_B0);
            #pragma unroll
            for (int i = 0; i < 4; i++) {
                int g = tid + i * 256;
                int row = g >> 3, kq = g & 7;
                float fa[4] = {pa[i].x, pa[i].y, pa[i].z, pa[i].w};
                float fb[4] = {pb[i].x, pb[i].y, pb[i].z, pb[i].w};
                #pragma unroll
                for (int e = 0; e < 4; e++) {
                    int k = kq * 4 + e;
                    int cc = k >> 3, ln = ((row & 7) << 2) | (k & 3);
                    int t = row >> 4, j = ((k >> 2) & 1) * 2 + ((row >> 3) & 1);
                    Ad[(((t * 4 + cc) * 32 + ln) << 2) + j] = f2tf32(fa[e]);
                    int u = row >> 3, f = (k >> 2) & 1;
                    Bd[(((u * 4 + cc) * 32 + ln) << 1) + f] = f2tf32(fb[e]);
                }
            }
            __syncthreads();
        }
    }

    // ---- epilogue: C-fragment layout -> gmem, fused bias / sigmoid ----
    #pragma unroll
    for (int t = 0; t < 4; t++) {
        int r0 = m0 + mw * 64 + t * 16 + (lane >> 2);
        #pragma unroll
        for (int u = 0; u < 4; u++) {
            int col = n0b + nw * 32 + u * 8 + (lane & 3) * 2;
            float v0 = acc[t][u][0], v1 = acc[t][u][1];
            float v2 = acc[t][u][2], v3 = acc[t][u][3];
            if (bias) {
                float b0 = bias[col], b1 = bias[col + 1];
                v0 += b0; v1 += b1; v2 += b0; v3 += b1;
            }
            if (sigmoidFlag) {
                v0 = 1.f / (1.f + __expf(-v0));
                v1 = 1.f / (1.f + __expf(-v1));
                v2 = 1.f / (1.f + __expf(-v2));
                v3 = 1.f / (1.f + __expf(-v3));
            }
            *(float2*)&C[(size_t)r0 * DM + col]       = make_float2(v0, v1);
            *(float2*)&C[(size_t)(r0 + 8) * DM + col] = make_float2(v2, v3);
        }
    }
}

// ---------------- pos_sum[j,d] = sum_i emb[clip(j-i,-30,30)+30, d] ----------------
__global__ void possum_kernel(const float* __restrict__ emb) {
    int j = blockIdx.x;
    int d = threadIdx.x;   // 192 threads
    float acc = 0.f;
    #pragma unroll
    for (int delta = -29; delta <= 29; delta++) {
        int i = j - delta;
        if (i >= 0 && i < MN) acc += emb[(delta + 30) * D3 + d];
    }
    int cpos = j - 29;
    if (cpos > 0) acc += (float)cpos * emb[60 * D3 + d];
    int cneg = 482 - j;
    if (cneg > 0) acc += (float)cneg * emb[0 * D3 + d];
    g_pos_sum[j * D3 + d] = acc;
}

// ---------------- multi-scale conv: xm[b,s,0:64|64:128|128:192] = conv3|5|7 --------
template <int K>
__device__ __forceinline__ void conv_do(float* xs, float* ws,
                                        const float* __restrict__ w,
                                        const float* __restrict__ bias,
                                        int coff, int b, int s0, int tid) {
    __syncthreads();
    for (int idx = tid; idx < 64 * 64 * K; idx += 256) {
        int t = idx % K;
        int i = (idx / K) & 63;
        int o = idx / (K * 64);
        ws[(i * K + t) * 64 + o] = w[idx];
    }
    __syncthreads();

    int oc = tid & 63;
    int pbase = (tid >> 6) * 16;
    float acc[16];
    float bv = bias[oc];
    #pragma unroll
    for (int pp = 0; pp < 16; pp++) acc[pp] = bv;

    for (int i = 0; i < 64; i++) {
        float xvr[16 + K - 1];
        #pragma unroll
        for (int j = 0; j < 16 + K - 1; j++)
            xvr[j] = xs[(pbase + j + 3 - K / 2) * 64 + i];
        #pragma unroll
        for (int t = 0; t < K; t++) {
            float wv = ws[(i * K + t) * 64 + oc];
            #pragma unroll
            for (int pp = 0; pp < 16; pp++) acc[pp] += xvr[pp + t] * wv;
        }
    }
    #pragma unroll
    for (int pp = 0; pp < 16; pp++)
        g_xm[((size_t)b * MN + s0 + pbase + pp) * D3 + coff + oc] = acc[pp];
}

__global__ void conv_kernel(const float* __restrict__ xv,
                            const float* __restrict__ w3, const float* __restrict__ b3,
                            const float* __restrict__ w5, const float* __restrict__ b5,
                            const float* __restrict__ w7, const float* __restrict__ b7) {
    extern __shared__ float sh[];
    float* xs = sh;             // [70][64] halo tile
    float* ws = sh + 70 * 64;   // weight stage (max 64*64*7)
    int blk = blockIdx.x;
    int b = blk >> 3;
    int s0 = (blk & 7) * 64;
    int tid = threadIdx.x;

    for (int idx = tid; idx < 70 * 64; idx += 256) {
        int r = idx >> 6, i = idx & 63;
        int s = s0 - 3 + r;
        xs[idx] = (s >= 0 && s < MN) ? xv[((size_t)b * MN + s) * VD + i] : 0.f;
    }
    conv_do<3>(xs, ws, w3, b3, 0, b, s0, tid);
    conv_do<5>(xs, ws, w5, b5, 64, b, s0, tid);
    conv_do<7>(xs, ws, w7, b7, 128, b, s0, tid);
}

// ---------------- rel-pos encoding (closed form, elementwise) ----------------------
__global__ void pe_kernel(const float* __restrict__ emb,
                          const float* __restrict__ dww, const float* __restrict__ dwb) {
    int idx = blockIdx.x * 256 + threadIdx.x;
    if (idx >= BB * MN * D3) return;
    int d = idx % D3;
    int j = (idx / D3) & (MN - 1);
    float xc = g_xm[idx];
    float fC = xc + emb[30 * D3 + d];
    float fL = 0.f, fR = 0.f;
    if (j > 0)      fL = g_xm[idx - D3] + emb[29 * D3 + d];
    if (j < MN - 1) fR = g_xm[idx + D3] + emb[31 * D3 + d];
    float diag = fL * dww[d * 3 + 0] + fC * dww[d * 3 + 1] + fR * dww[d * 3 + 2] + dwb[d];
    g_pe[idx] = xc + (g_pos_sum[j * D3 + d] - fC + diag) * (1.0f / (float)MN);
}

// ---------------- attention: per (b,h), K/V resident in smem -----------------------
__global__ void attn_kernel() {
    extern __shared__ float sh[];
    float* Ks = sh;             // [512][32]
    float* Vs = sh + MN * DK;   // [512][32]
    int blk = blockIdx.x;       // b*32 + h*4 + qt
    int qt = blk & 3;
    int h = (blk >> 2) & 7;
    int b = blk >> 5;
    int tid = threadIdx.x;

    const float* Kg = g_K + (size_t)b * MN * DM + h * DK;
    const float* Vg = g_V + (size_t)b * MN * DM + h * DK;
    for (int idx = tid; idx < MN * 8; idx += 256) {
        int s = idx >> 3, d4 = idx & 7;
        *(float4*)&Ks[s * DK + d4 * 4] = *(const float4*)&Kg[(size_t)s * DM + d4 * 4];
        *(float4*)&Vs[s * DK + d4 * 4] = *(const float4*)&Vg[(size_t)s * DM + d4 * 4];
    }
    __syncthreads();

    int l = qt * 256 + tid;
    const float* Qg = g_Q + ((size_t)b * LL + l) * DM + h * DK;
    float q[DK];
    #pragma unroll
    for (int d4 = 0; d4 < 8; d4++) {
        float4 v = *(const float4*)&Qg[d4 * 4];
        q[d4 * 4 + 0] = v.x * 0.17677669529663687f;   // 1/sqrt(32)
        q[d4 * 4 + 1] = v.y * 0.17677669529663687f;
        q[d4 * 4 + 2] = v.z * 0.17677669529663687f;
        q[d4 * 4 + 3] = v.w * 0.17677669529663687f;
    }
    float lsum = 0.f;
    float o[DK];
    #pragma unroll
    for (int d = 0; d < DK; d++) o[d] = 0.f;

    // scores are bounded well inside expf's range: no max-tracking needed
    for (int s = 0; s < MN; s++) {
        float x = 0.f;
        const float4* K4 = (const float4*)(Ks + s * DK);
        #pragma unroll
        for (int d4 = 0; d4 < 8; d4++) {
            float4 kv = K4[d4];
            x += q[d4 * 4 + 0] * kv.x + q[d4 * 4 + 1] * kv.y
               + q[d4 * 4 + 2] * kv.z + q[d4 * 4 + 3] * kv.w;
        }
        float p = __expf(x);
        lsum += p;
        const float4* V4 = (const float4*)(Vs + s * DK);
        #pragma unroll
        for (int d4 = 0; d4 < 8; d4++) {
            float4 vv = V4[d4];
            o[d4 * 4 + 0] += p * vv.x;
            o[d4 * 4 + 1] += p * vv.y;
            o[d4 * 4 + 2] += p * vv.z;
            o[d4 * 4 + 3] += p * vv.w;
        }
    }
    float inv = 1.f / lsum;
    float* Og = g_attn + ((size_t)b * LL + l) * DM + h * DK;
    #pragma unroll
    for (int d4 = 0; d4 < 8; d4++) {
        *(float4*)&Og[d4 * 4] = make_float4(o[d4 * 4] * inv, o[d4 * 4 + 1] * inv,
                                            o[d4 * 4 + 2] * inv, o[d4 * 4 + 3] * inv);
    }
}

// ---------------- gate * fc + residual + LayerNorm ---------------------------------
__global__ void final_kernel(const float* __restrict__ xs,
                             const float* __restrict__ lnw, const float* __restrict__ lnb,
                             float* __restrict__ out) {
    __shared__ float red[16];
    int row = blockIdx.x;          // b*1024 + l
    int b = row >> 10;
    int l = row & 1023;
    int c = threadIdx.x;
    size_t off = (size_t)row * DM + c;
    float fcv = g_fc[off];
    float gam = g_gamma[((size_t)b * MN + (l & (MN - 1))) * DM + c];
    float v = xs[off] + gam * fcv;

    float s1 = v, s2 = v * v;
    #pragma unroll
    for (int d = 16; d; d >>= 1) {
        s1 += __shfl_xor_sync(0xFFFFFFFFu, s1, d);
        s2 += __shfl_xor_sync(0xFFFFFFFFu, s2, d);
    }
    int warp = c >> 5, lane = c & 31;
    if (lane == 0) { red[warp] = s1; red[8 + warp] = s2; }
    __syncthreads();
    float t1 = 0.f, t2 = 0.f;
    #pragma unroll
    for (int w = 0; w < 8; w++) { t1 += red[w]; t2 += red[8 + w]; }
    float mu = t1 * (1.f / 256.f);
    float var = t2 * (1.f / 256.f) - mu * mu;
    out[off] = (v - mu) * rsqrtf(var + 1e-5f) * lnw[c] + lnb[c];
}

// ---------------- launch -----------------------------------------------------------
extern "C" void kernel_launch(void* const* d_in, const int* in_sizes, int n_in,
                              void* d_out, int out_size) {
    const float* x_spatial  = (const float*)d_in[0];
    const float* x_velocity = (const float*)d_in[1];
    const float* Wg    = (const float*)d_in[2];
    const float* ms_w3 = (const float*)d_in[3];
    const float* ms_b3 = (const float*)d_in[4];
    const float* ms_w5 = (const float*)d_in[5];
    const float* ms_b5 = (const float*)d_in[6];
    const float* ms_w7 = (const float*)d_in[7];
    const float* ms_b7 = (const float*)d_in[8];
    const float* rel_emb = (const float*)d_in[9];
    const float* dw_w  = (const float*)d_in[10];
    const float* dw_b  = (const float*)d_in[11];
    const float* Wq    = (const float*)d_in[12];
    const float* Wk    = (const float*)d_in[13];
    const float* Wv    = (const float*)d_in[14];
    const float* fc_w  = (const float*)d_in[15];
    const float* fc_b  = (const float*)d_in[16];
    const float* ln_w  = (const float*)d_in[17];
    const float* ln_b  = (const float*)d_in[18];
    float* out = (float*)d_out;

    float *p_gamma, *p_pe, *p_Q, *p_K, *p_V, *p_attn, *p_fc;
    cudaGetSymbolAddress((void**)&p_gamma, g_gamma);
    cudaGetSymbolAddress((void**)&p_pe,    g_pe);
    cudaGetSymbolAddress((void**)&p_Q,     g_Q);
    cudaGetSymbolAddress((void**)&p_K,     g_K);
    cudaGetSymbolAddress((void**)&p_V,     g_V);
    cudaGetSymbolAddress((void**)&p_attn,  g_attn);
    cudaGetSymbolAddress((void**)&p_fc,    g_fc);

    const int CONV_SMEM = (70 * 64 + 64 * 64 * 7) * 4;   // 132,608 B
    const int ATTN_SMEM = 2 * MN * DK * 4;               // 131,072 B
    cudaFuncSetAttribute(conv_kernel,  cudaFuncAttributeMaxDynamicSharedMemorySize, CONV_SMEM);
    cudaFuncSetAttribute(attn_kernel,  cudaFuncAttributeMaxDynamicSharedMemorySize, ATTN_SMEM);
    cudaFuncSetAttribute(mgemm_kernel, cudaFuncAttributeMaxDynamicSharedMemorySize, GSM_BYTES);

    possum_kernel<<<MN, D3>>>(rel_emb);

    // Gamma = sigmoid(x_velocity @ Wg^T)   [16384, 256]
    mgemm_kernel<<<dim3(2, BB * MN / 128), 256, GSM_BYTES>>>(x_velocity, Wg, nullptr,
                                                             p_gamma, VD, 1);
    conv_kernel<<<BB * (MN / 64), 256, CONV_SMEM>>>(x_velocity, ms_w3, ms_b3,
                                                    ms_w5, ms_b5, ms_w7, ms_b7);
    pe_kernel<<<(BB * MN * D3 + 255) / 256, 256>>>(rel_emb, dw_w, dw_b);

    // Q / K / V projections
    mgemm_kernel<<<dim3(2, BB * LL / 128), 256, GSM_BYTES>>>(x_spatial, Wq, nullptr,
                                                             p_Q, SD, 0);
    mgemm_kernel<<<dim3(2, BB * MN / 128), 256, GSM_BYTES>>>(p_pe, Wk, nullptr,
                                                             p_K, D3, 0);
    mgemm_kernel<<<dim3(2, BB * MN / 128), 256, GSM_BYTES>>>(p_pe, Wv, nullptr,
                                                             p_V, D3, 0);

    attn_kernel<<<BB * NH * (LL / 256), 256, ATTN_SMEM>>>();

    mgemm_kernel<<<dim3(2, BB * LL / 128), 256, GSM_BYTES>>>(p_attn, fc_w, fc_b,
                                                             p_fc, DM, 0);
    final_kernel<<<BB * LL, 256>>>(x_spatial, ln_w, ln_b, out);
}

// round 5
// speedup vs baseline: 2.1992x; 1.7144x over previous
#include <cuda_runtime.h>
#include <math.h>
#include <stdint.h>

#define BB 32
#define LL 1024
#define MN 512
#define SD 256
#define VD 64
#define D3 192
#define DM 256
#define NH 8
#define DK 32

// ---------------- scratch (device globals; no allocation allowed) ----------------
__device__ float g_pos_sum[MN * D3];
__device__ float g_gamma[BB * MN * DM];
__device__ float g_xm[BB * MN * D3];
__device__ float g_pe[BB * MN * D3];
__device__ float g_Q[BB * LL * DM];
__device__ float g_K[BB * MN * DM];
__device__ float g_V[BB * MN * DM];
__device__ float g_attn[BB * LL * DM];
__device__ float g_fc[BB * LL * DM];

// ================= mma.sync tf32 helpers (sm_80+ features, no 'a' target) =========
__device__ __forceinline__ uint32_t f2tf32(float f) {
    uint32_t u;
    asm("cvt.rna.tf32.f32 %0, %1;" : "=r"(u) : "f"(f));
    return u;
}
__device__ __forceinline__ void mma_tf32(float* c, uint4 a, uint2 b) {
    asm("mma.sync.aligned.m16n8k8.row.col.f32.tf32.tf32.f32 "
        "{%0,%1,%2,%3}, {%4,%5,%6,%7}, {%8,%9}, {%0,%1,%2,%3};"
        : "+f"(c[0]), "+f"(c[1]), "+f"(c[2]), "+f"(c[3])
        : "r"(a.x), "r"(a.y), "r"(a.z), "r"(a.w), "r"(b.x), "r"(b.y));
}

// dynamic smem layout (uint32 indices): double-buffered fragment-ordered A and B
#define GSM_A0 0
#define GSM_A1 4096
#define GSM_B0 8192
#define GSM_B1 12288
#define GSM_BYTES (16384 * 4)

// ---------------- tensor-core GEMM: C[M,256] = A[M,Kd] * W[256,Kd]^T ---------------
// block = 128 rows x 128 cols; 8 warps as 2(m) x 4(n); warp = 64x32; tf32 HMMA
__global__ void __launch_bounds__(256, 1) mgemm_kernel(
    const float* __restrict__ A, const float* __restrict__ W,
    const float* __restrict__ bias, float* __restrict__ C,
    int Kd, int sigmoidFlag) {
    extern __shared__ uint32_t gsm[];
    int tid = threadIdx.x;
    int lane = tid & 31, wid = tid >> 5;
    int mw = wid & 1, nw = wid >> 1;
    int m0 = blockIdx.y * 128;
    int n0b = blockIdx.x * 128;
    int NC = Kd >> 5;

    float acc[4][4][4];
    #pragma unroll
    for (int t = 0; t < 4; t++)
        #pragma unroll
        for (int u = 0; u < 4; u++)
            #pragma unroll
            for (int j = 0; j < 4; j++) acc[t][u][j] = 0.f;

    // ---- stage chunk 0 (fragment-order permutation + tf32 convert) ----
    {
        #pragma unroll
        for (int i = 0; i < 4; i++) {
            int g = tid + i * 256;
            int row = g >> 3, kq = g & 7;
            float4 va = *(const float4*)&A[(size_t)(m0 + row) * Kd + kq * 4];
            float4 vb = *(const float4*)&W[(size_t)(n0b + row) * Kd + kq * 4];
            float fa[4] = {va.x, va.y, va.z, va.w};
            float fb[4] = {vb.x, vb.y, vb.z, vb.w};
            #pragma unroll
            for (int e = 0; e < 4; e++) {
                int k = kq * 4 + e;
                int cc = k >> 3, ln = ((row & 7) << 2) | (k & 3);
                int t = row >> 4, j = ((k >> 2) & 1) * 2 + ((row >> 3) & 1);
                gsm[GSM_A0 + ((((t * 4 + cc) * 32 + ln) << 2) + j)] = f2tf32(fa[e]);
                int u = row >> 3, f = (k >> 2) & 1;
                gsm[GSM_B0 + ((((u * 4 + cc) * 32 + ln) << 1) + f)] = f2tf32(fb[e]);
            }
        }
    }
    __syncthreads();

    for (int c = 0; c < NC; c++) {
        const uint32_t* As = gsm + ((c & 1) ? GSM_A1 : GSM_A0);
        const uint32_t* Bs = gsm + ((c & 1) ? GSM_B1 : GSM_B0);

        // prefetch next chunk into registers (overlaps HMMA below)
        float4 pa[4], pb[4];
        if (c + 1 < NC) {
            int kk = (c + 1) * 32;
            #pragma unroll
            for (int i = 0; i < 4; i++) {
                int g = tid + i * 256;
                int row = g >> 3, kq = g & 7;
                pa[i] = *(const float4*)&A[(size_t)(m0 + row) * Kd + kk + kq * 4];
                pb[i] = *(const float4*)&W[(size_t)(n0b + row) * Kd + kk + kq * 4];
            }
        }

        // compute: 4 k8-steps x 16 mma
        #pragma unroll
        for (int c8 = 0; c8 < 4; c8++) {
            uint4 av[4];
            uint2 bv[4];
            #pragma unroll
            for (int t = 0; t < 4; t++)
                av[t] = *(const uint4*)&As[(((mw * 4 + t) * 4 + c8) * 32 + lane) << 2];
            #pragma unroll
            for (int u = 0; u < 4; u++)
                bv[u] = *(const uint2*)&Bs[(((nw * 4 + u) * 4 + c8) * 32 + lane) << 1];
            #pragma unroll
            for (int t = 0; t < 4; t++)
                #pragma unroll
                for (int u = 0; u < 4; u++)
                    mma_tf32(acc[t][u], av[t], bv[u]);
        }

        if (c + 1 < NC) {
            __syncthreads();   // all warps done reading the buffer we are about to overwrite
            uint32_t* Ad = gsm + (((c + 1) & 1) ? GSM_A1 : GSM_A0);
            uint32_t* Bd = gsm + (((c + 1) & 1) ? GSM_B1 : GSM_B0);
            #pragma unroll
            for (int i = 0; i < 4; i++) {
                int g = tid + i * 256;
                int row = g >> 3, kq = g & 7;
                float fa[4] = {pa[i].x, pa[i].y, pa[i].z, pa[i].w};
                float fb[4] = {pb[i].x, pb[i].y, pb[i].z, pb[i].w};
                #pragma unroll
                for (int e = 0; e < 4; e++) {
                    int k = kq * 4 + e;
                    int cc = k >> 3, ln = ((row & 7) << 2) | (k & 3);
                    int t = row >> 4, j = ((k >> 2) & 1) * 2 + ((row >> 3) & 1);
                    Ad[(((t * 4 + cc) * 32 + ln) << 2) + j] = f2tf32(fa[e]);
                    int u = row >> 3, f = (k >> 2) & 1;
                    Bd[(((u * 4 + cc) * 32 + ln) << 1) + f] = f2tf32(fb[e]);
                }
            }
            __syncthreads();
        }
    }

    // ---- epilogue: C-fragment layout -> gmem, fused bias / sigmoid ----
    #pragma unroll
    for (int t = 0; t < 4; t++) {
        int r0 = m0 + mw * 64 + t * 16 + (lane >> 2);
        #pragma unroll
        for (int u = 0; u < 4; u++) {
            int col = n0b + nw * 32 + u * 8 + (lane & 3) * 2;
            float v0 = acc[t][u][0], v1 = acc[t][u][1];
            float v2 = acc[t][u][2], v3 = acc[t][u][3];
            if (bias) {
                float b0 = bias[col], b1 = bias[col + 1];
                v0 += b0; v1 += b1; v2 += b0; v3 += b1;
            }
            if (sigmoidFlag) {
                v0 = 1.f / (1.f + __expf(-v0));
                v1 = 1.f / (1.f + __expf(-v1));
                v2 = 1.f / (1.f + __expf(-v2));
                v3 = 1.f / (1.f + __expf(-v3));
            }
            *(float2*)&C[(size_t)r0 * DM + col]       = make_float2(v0, v1);
            *(float2*)&C[(size_t)(r0 + 8) * DM + col] = make_float2(v2, v3);
        }
    }
}

// ---------------- pos_sum[j,d] = sum_i emb[clip(j-i,-30,30)+30, d] ----------------
__global__ void possum_kernel(const float* __restrict__ emb) {
    int j = blockIdx.x;
    int d = threadIdx.x;   // 192 threads
    float acc = 0.f;
    #pragma unroll
    for (int delta = -29; delta <= 29; delta++) {
        int i = j - delta;
        if (i >= 0 && i < MN) acc += emb[(delta + 30) * D3 + d];
    }
    int cpos = j - 29;
    if (cpos > 0) acc += (float)cpos * emb[60 * D3 + d];
    int cneg = 482 - j;
    if (cneg > 0) acc += (float)cneg * emb[0 * D3 + d];
    g_pos_sum[j * D3 + d] = acc;
}

// ---------------- multi-scale conv: xm[b,s,0:64|64:128|128:192] = conv3|5|7 --------
template <int K>
__device__ __forceinline__ void conv_do(float* xs, float* ws,
                                        const float* __restrict__ w,
                                        const float* __restrict__ bias,
                                        int coff, int b, int s0, int tid) {
    __syncthreads();
    for (int idx = tid; idx < 64 * 64 * K; idx += 256) {
        int t = idx % K;
        int i = (idx / K) & 63;
        int o = idx / (K * 64);
        ws[(i * K + t) * 64 + o] = w[idx];
    }
    __syncthreads();

    int oc = tid & 63;
    int pbase = (tid >> 6) * 16;
    float acc[16];
    float bv = bias[oc];
    #pragma unroll
    for (int pp = 0; pp < 16; pp++) acc[pp] = bv;

    for (int i = 0; i < 64; i++) {
        float xvr[16 + K - 1];
        #pragma unroll
        for (int j = 0; j < 16 + K - 1; j++)
            xvr[j] = xs[(pbase + j + 3 - K / 2) * 64 + i];
        #pragma unroll
        for (int t = 0; t < K; t++) {
            float wv = ws[(i * K + t) * 64 + oc];
            #pragma unroll
            for (int pp = 0; pp < 16; pp++) acc[pp] += xvr[pp + t] * wv;
        }
    }
    #pragma unroll
    for (int pp = 0; pp < 16; pp++)
        g_xm[((size_t)b * MN + s0 + pbase + pp) * D3 + coff + oc] = acc[pp];
}

__global__ void conv_kernel(const float* __restrict__ xv,
                            const float* __restrict__ w3, const float* __restrict__ b3,
                            const float* __restrict__ w5, const float* __restrict__ b5,
                            const float* __restrict__ w7, const float* __restrict__ b7) {
    extern __shared__ float sh[];
    float* xs = sh;             // [70][64] halo tile
    float* ws = sh + 70 * 64;   // weight stage (max 64*64*7)
    int blk = blockIdx.x;
    int b = blk >> 3;
    int s0 = (blk & 7) * 64;
    int tid = threadIdx.x;

    for (int idx = tid; idx < 70 * 64; idx += 256) {
        int r = idx >> 6, i = idx & 63;
        int s = s0 - 3 + r;
        xs[idx] = (s >= 0 && s < MN) ? xv[((size_t)b * MN + s) * VD + i] : 0.f;
    }
    conv_do<3>(xs, ws, w3, b3, 0, b, s0, tid);
    conv_do<5>(xs, ws, w5, b5, 64, b, s0, tid);
    conv_do<7>(xs, ws, w7, b7, 128, b, s0, tid);
}

// ---------------- rel-pos encoding (closed form, elementwise) ----------------------
__global__ void pe_kernel(const float* __restrict__ emb,
                          const float* __restrict__ dww, const float* __restrict__ dwb) {
    int idx = blockIdx.x * 256 + threadIdx.x;
    if (idx >= BB * MN * D3) return;
    int d = idx % D3;
    int j = (idx / D3) & (MN - 1);
    float xc = g_xm[idx];
    float fC = xc + emb[30 * D3 + d];
    float fL = 0.f, fR = 0.f;
    if (j > 0)      fL = g_xm[idx - D3] + emb[29 * D3 + d];
    if (j < MN - 1) fR = g_xm[idx + D3] + emb[31 * D3 + d];
    float diag = fL * dww[d * 3 + 0] + fC * dww[d * 3 + 1] + fR * dww[d * 3 + 2] + dwb[d];
    g_pe[idx] = xc + (g_pos_sum[j * D3 + d] - fC + diag) * (1.0f / (float)MN);
}

// ---------------- attention on mma.sync tf32: per (b,h), K/V tf32 in smem ---------
// smem rows padded to 36 words -> conflict-free B-frag reads for both K and V maps
#define AS_STRIDE 36
#define ATT_SMEM (2 * MN * AS_STRIDE * 4)   // 147456 B

__global__ void __launch_bounds__(256, 1) attn_kernel() {
    extern __shared__ uint32_t ash[];
    uint32_t* Ks = ash;                 // [512][36] tf32
    uint32_t* Vs = ash + MN * AS_STRIDE;
    int blk = blockIdx.x;               // b*32 + h*4 + qblk
    int qblk = blk & 3;
    int h = (blk >> 2) & 7;
    int b = blk >> 5;
    int tid = threadIdx.x;
    int lane = tid & 31, wid = tid >> 5;
    int q = lane >> 2, p = lane & 3;

    // ---- stage K/V as tf32 into padded smem ----
    const float* Kg = g_K + (size_t)b * MN * DM + h * DK;
    const float* Vg = g_V + (size_t)b * MN * DM + h * DK;
    for (int i = tid; i < MN * 8; i += 256) {
        int s = i >> 3, c4 = i & 7;
        float4 kv = *(const float4*)&Kg[(size_t)s * DM + c4 * 4];
        float4 vv = *(const float4*)&Vg[(size_t)s * DM + c4 * 4];
        uint4 ku = make_uint4(f2tf32(kv.x), f2tf32(kv.y), f2tf32(kv.z), f2tf32(kv.w));
        uint4 vu = make_uint4(f2tf32(vv.x), f2tf32(vv.y), f2tf32(vv.z), f2tf32(vv.w));
        *(uint4*)&Ks[s * AS_STRIDE + c4 * 4] = ku;
        *(uint4*)&Vs[s * AS_STRIDE + c4 * 4] = vu;
    }
    __syncthreads();

    // ---- Q fragments (2 m-tiles x 4 k-steps), pre-scaled, tf32 ----
    int m0 = qblk * 256 + wid * 32;
    const float* Qg = g_Q + ((size_t)b * LL + m0) * DM + h * DK;
    const float sc = 0.17677669529663687f;   // 1/sqrt(32)
    uint4 aq[2][4];
    #pragma unroll
    for (int t = 0; t < 2; t++)
        #pragma unroll
        for (int ks = 0; ks < 4; ks++) {
            int r0 = t * 16 + q;
            int c0 = ks * 8 + p;
            aq[t][ks] = make_uint4(
                f2tf32(Qg[(size_t)r0 * DM + c0] * sc),
                f2tf32(Qg[(size_t)(r0 + 8) * DM + c0] * sc),
                f2tf32(Qg[(size_t)r0 * DM + c0 + 4] * sc),
                f2tf32(Qg[(size_t)(r0 + 8) * DM + c0 + 4] * sc));
        }

    float o[2][4][4];
    #pragma unroll
    for (int t = 0; t < 2; t++)
        #pragma unroll
        for (int nv = 0; nv < 4; nv++)
            #pragma unroll
            for (int j = 0; j < 4; j++) o[t][nv][j] = 0.f;
    float rs[2][2] = {{0.f, 0.f}, {0.f, 0.f}};

    int srcl  = (lane & 28) | (p >> 1);
    int srcl2 = srcl + 2;
    bool odd = lane & 1;

    for (int s0 = 0; s0 < MN; s0 += 16) {
        // K B-frags: 2 n-tiles x 4 k-steps
        uint2 bk[2][4];
        #pragma unroll
        for (int n = 0; n < 2; n++)
            #pragma unroll
            for (int ks = 0; ks < 4; ks++) {
                const uint32_t* kr = &Ks[(s0 + n * 8 + q) * AS_STRIDE + ks * 8 + p];
                bk[n][ks] = make_uint2(kr[0], kr[4]);
            }

        // S = Q K^T  (16 mma)
        float c[2][2][4];
        #pragma unroll
        for (int t = 0; t < 2; t++)
            #pragma unroll
            for (int n = 0; n < 2; n++) {
                #pragma unroll
                for (int j = 0; j < 4; j++) c[t][n][j] = 0.f;
                #pragma unroll
                for (int ks = 0; ks < 4; ks++)
                    mma_tf32(c[t][n], aq[t][ks], bk[n][ks]);
            }

        // exp + rowsum + C->A rearrange (quad shuffles)
        uint4 ap[2][2];
        #pragma unroll
        for (int t = 0; t < 2; t++)
            #pragma unroll
            for (int n = 0; n < 2; n++) {
                float p0 = __expf(c[t][n][0]);
                float p1 = __expf(c[t][n][1]);
                float p2 = __expf(c[t][n][2]);
                float p3 = __expf(c[t][n][3]);
                rs[t][0] += p0 + p1;
                rs[t][1] += p2 + p3;
                uint32_t u0 = f2tf32(p0), u1 = f2tf32(p1);
                uint32_t u2 = f2tf32(p2), u3 = f2tf32(p3);
                uint32_t e0 = __shfl_sync(0xFFFFFFFFu, u0, srcl);
                uint32_t f0 = __shfl_sync(0xFFFFFFFFu, u1, srcl);
                uint32_t e1 = __shfl_sync(0xFFFFFFFFu, u2, srcl);
                uint32_t f1 = __shfl_sync(0xFFFFFFFFu, u3, srcl);
                uint32_t e2 = __shfl_sync(0xFFFFFFFFu, u0, srcl2);
                uint32_t f2 = __shfl_sync(0xFFFFFFFFu, u1, srcl2);
                uint32_t e3 = __shfl_sync(0xFFFFFFFFu, u2, srcl2);
                uint32_t f3 = __shfl_sync(0xFFFFFFFFu, u3, srcl2);
                ap[t][n] = make_uint4(odd ? f0 : e0, odd ? f1 : e1,
                                      odd ? f2 : e2, odd ? f3 : e3);
            }

        // V B-frags: 4 n-tiles (dk) x 2 k-steps (s)
        uint2 bv[4][2];
        #pragma unroll
        for (int nv = 0; nv < 4; nv++)
            #pragma unroll
            for (int kn = 0; kn < 2; kn++) {
                const uint32_t* vr = &Vs[(s0 + kn * 8 + p) * AS_STRIDE + nv * 8 + q];
                bv[nv][kn] = make_uint2(vr[0], vr[4 * AS_STRIDE]);
            }

        // O += P V  (16 mma)
        #pragma unroll
        for (int t = 0; t < 2; t++)
            #pragma unroll
            for (int nv = 0; nv < 4; nv++)
                #pragma unroll
                for (int kn = 0; kn < 2; kn++)
                    mma_tf32(o[t][nv], ap[t][kn], bv[nv][kn]);
    }

    // ---- rowsum reduce across quad, normalize, store ----
    #pragma unroll
    for (int t = 0; t < 2; t++) {
        #pragma unroll
        for (int r = 0; r < 2; r++) {
            rs[t][r] += __shfl_xor_sync(0xFFFFFFFFu, rs[t][r], 1);
            rs[t][r] += __shfl_xor_sync(0xFFFFFFFFu, rs[t][r], 2);
        }
        float inv0 = 1.f / rs[t][0];
        float inv1 = 1.f / rs[t][1];
        int r0 = m0 + t * 16 + q;
        #pragma unroll
        for (int nv = 0; nv < 4; nv++) {
            int col = h * DK + nv * 8 + p * 2;
            *(float2*)&g_attn[((size_t)b * LL + r0) * DM + col] =
                make_float2(o[t][nv][0] * inv0, o[t][nv][1] * inv0);
            *(float2*)&g_attn[((size_t)b * LL + r0 + 8) * DM + col] =
                make_float2(o[t][nv][2] * inv1, o[t][nv][3] * inv1);
        }
    }
}

// ---------------- gate * fc + residual + LayerNorm ---------------------------------
__global__ void final_kernel(const float* __restrict__ xs,
                             const float* __restrict__ lnw, const float* __restrict__ lnb,
                             float* __restrict__ out) {
    __shared__ float red[16];
    int row = blockIdx.x;          // b*1024 + l
    int b = row >> 10;
    int l = row & 1023;
    int c = threadIdx.x;
    size_t off = (size_t)row * DM + c;
    float fcv = g_fc[off];
    float gam = g_gamma[((size_t)b * MN + (l & (MN - 1))) * DM + c];
    float v = xs[off] + gam * fcv;

    float s1 = v, s2 = v * v;
    #pragma unroll
    for (int d = 16; d; d >>= 1) {
        s1 += __shfl_xor_sync(0xFFFFFFFFu, s1, d);
        s2 += __shfl_xor_sync(0xFFFFFFFFu, s2, d);
    }
    int warp = c >> 5, lane = c & 31;
    if (lane == 0) { red[warp] = s1; red[8 + warp] = s2; }
    __syncthreads();
    float t1 = 0.f, t2 = 0.f;
    #pragma unroll
    for (int w = 0; w < 8; w++) { t1 += red[w]; t2 += red[8 + w]; }
    float mu = t1 * (1.f / 256.f);
    float var = t2 * (1.f / 256.f) - mu * mu;
    out[off] = (v - mu) * rsqrtf(var + 1e-5f) * lnw[c] + lnb[c];
}

// ---------------- launch -----------------------------------------------------------
extern "C" void kernel_launch(void* const* d_in, const int* in_sizes, int n_in,
                              void* d_out, int out_size) {
    const float* x_spatial  = (const float*)d_in[0];
    const float* x_velocity = (const float*)d_in[1];
    const float* Wg    = (const float*)d_in[2];
    const float* ms_w3 = (const float*)d_in[3];
    const float* ms_b3 = (const float*)d_in[4];
    const float* ms_w5 = (const float*)d_in[5];
    const float* ms_b5 = (const float*)d_in[6];
    const float* ms_w7 = (const float*)d_in[7];
    const float* ms_b7 = (const float*)d_in[8];
    const float* rel_emb = (const float*)d_in[9];
    const float* dw_w  = (const float*)d_in[10];
    const float* dw_b  = (const float*)d_in[11];
    const float* Wq    = (const float*)d_in[12];
    const float* Wk    = (const float*)d_in[13];
    const float* Wv    = (const float*)d_in[14];
    const float* fc_w  = (const float*)d_in[15];
    const float* fc_b  = (const float*)d_in[16];
    const float* ln_w  = (const float*)d_in[17];
    const float* ln_b  = (const float*)d_in[18];
    float* out = (float*)d_out;

    float *p_gamma, *p_pe, *p_Q, *p_K, *p_V, *p_attn, *p_fc;
    cudaGetSymbolAddress((void**)&p_gamma, g_gamma);
    cudaGetSymbolAddress((void**)&p_pe,    g_pe);
    cudaGetSymbolAddress((void**)&p_Q,     g_Q);
    cudaGetSymbolAddress((void**)&p_K,     g_K);
    cudaGetSymbolAddress((void**)&p_V,     g_V);
    cudaGetSymbolAddress((void**)&p_attn,  g_attn);
    cudaGetSymbolAddress((void**)&p_fc,    g_fc);

    const int CONV_SMEM = (70 * 64 + 64 * 64 * 7) * 4;   // 132,608 B
    cudaFuncSetAttribute(conv_kernel,  cudaFuncAttributeMaxDynamicSharedMemorySize, CONV_SMEM);
    cudaFuncSetAttribute(attn_kernel,  cudaFuncAttributeMaxDynamicSharedMemorySize, ATT_SMEM);
    cudaFuncSetAttribute(mgemm_kernel, cudaFuncAttributeMaxDynamicSharedMemorySize, GSM_BYTES);

    possum_kernel<<<MN, D3>>>(rel_emb);

    // Gamma = sigmoid(x_velocity @ Wg^T)   [16384, 256]
    mgemm_kernel<<<dim3(2, BB * MN / 128), 256, GSM_BYTES>>>(x_velocity, Wg, nullptr,
                                                             p_gamma, VD, 1);
    conv_kernel<<<BB * (MN / 64), 256, CONV_SMEM>>>(x_velocity, ms_w3, ms_b3,
                                                    ms_w5, ms_b5, ms_w7, ms_b7);
    pe_kernel<<<(BB * MN * D3 + 255) / 256, 256>>>(rel_emb, dw_w, dw_b);

    // Q / K / V projections
    mgemm_kernel<<<dim3(2, BB * LL / 128), 256, GSM_BYTES>>>(x_spatial, Wq, nullptr,
                                                             p_Q, SD, 0);
    mgemm_kernel<<<dim3(2, BB * MN / 128), 256, GSM_BYTES>>>(p_pe, Wk, nullptr,
                                                             p_K, D3, 0);
    mgemm_kernel<<<dim3(2, BB * MN / 128), 256, GSM_BYTES>>>(p_pe, Wv, nullptr,
                                                             p_V, D3, 0);

    attn_kernel<<<BB * NH * 4, 256, ATT_SMEM>>>();

    mgemm_kernel<<<dim3(2, BB * LL / 128), 256, GSM_BYTES>>>(p_attn, fc_w, fc_b,
                                                             p_fc, DM, 0);
    final_kernel<<<BB * LL, 256>>>(x_spatial, ln_w, ln_b, out);
}

// round 6
// speedup vs baseline: 3.1344x; 1.4253x over previous
#include <cuda_runtime.h>
#include <cuda_fp16.h>
#include <math.h>
#include <stdint.h>

#define BB 32
#define LL 1024
#define MN 512
#define SD 256
#define VD 64
#define D3 192
#define DM 256
#define NH 8
#define DK 32

// ---------------- scratch (device globals; no allocation allowed) ----------------
__device__ float g_pos_sum[MN * D3];
__device__ float g_gamma[BB * MN * DM];
__device__ float g_xm[BB * MN * D3];
__device__ float g_pe[BB * MN * D3];
__device__ float g_Q[BB * LL * DM];
__device__ float g_K[BB * MN * DM];
__device__ float g_V[BB * MN * DM];
__device__ float g_attn[BB * LL * DM];
__device__ float g_fc[BB * LL * DM];

// ================= fp16 mma helpers (sm_80+ features, base target OK) =============
__device__ __forceinline__ uint32_t h2u(float a, float b) {
    __half2 h = __floats2half2_rn(a, b);
    return *(uint32_t*)&h;
}
__device__ __forceinline__ void mma_f16(float* c, uint4 a, uint2 b) {
    asm("mma.sync.aligned.m16n8k16.row.col.f32.f16.f16.f32 "
        "{%0,%1,%2,%3}, {%4,%5,%6,%7}, {%8,%9}, {%0,%1,%2,%3};"
        : "+f"(c[0]), "+f"(c[1]), "+f"(c[2]), "+f"(c[3])
        : "r"(a.x), "r"(a.y), "r"(a.z), "r"(a.w), "r"(b.x), "r"(b.y));
}

// GEMM smem: A/B half tiles, 128 rows x 32 halves, padded to 40 halves (20 words)
#define GS_AS 20                    // words per row
#define GS_TILE (128 * GS_AS)       // 2560 words per tile
#define GSM_BYTES (4 * GS_TILE * 4) // A0,A1,B0,B1 = 40960 B

// ---------------- tensor-core GEMM: C[M,256] = A[M,Kd] * W[256,Kd]^T ---------------
// block = 128 rows x 128 cols; 8 warps as 2(m) x 4(n); warp = 64x32; fp16 m16n8k16
__global__ void __launch_bounds__(256, 1) mgemm_kernel(
    const float* __restrict__ A, const float* __restrict__ W,
    const float* __restrict__ bias, float* __restrict__ C,
    int Kd, int sigmoidFlag) {
    extern __shared__ uint32_t gsm[];
    int tid = threadIdx.x;
    int lane = tid & 31, wid = tid >> 5;
    int mw = wid & 1, nw = wid >> 1;
    int qd = lane >> 2, pd = lane & 3;
    int m0 = blockIdx.y * 128;
    int n0b = blockIdx.x * 128;
    int NC = Kd >> 5;

    float acc[4][4][4];
    #pragma unroll
    for (int t = 0; t < 4; t++)
        #pragma unroll
        for (int u = 0; u < 4; u++)
            #pragma unroll
            for (int j = 0; j < 4; j++) acc[t][u][j] = 0.f;

    // ---- stage chunk 0 ----
    {
        uint32_t* Ad = gsm;
        uint32_t* Bd = gsm + 2 * GS_TILE;
        #pragma unroll
        for (int i = 0; i < 4; i++) {
            int g = tid + i * 256;
            int row = g >> 3, q = g & 7;
            float4 va = *(const float4*)&A[(size_t)(m0 + row) * Kd + q * 4];
            float4 vb = *(const float4*)&W[(size_t)(n0b + row) * Kd + q * 4];
            *(uint2*)&Ad[row * GS_AS + q * 2] = make_uint2(h2u(va.x, va.y), h2u(va.z, va.w));
            *(uint2*)&Bd[row * GS_AS + q * 2] = make_uint2(h2u(vb.x, vb.y), h2u(vb.z, vb.w));
        }
    }
    __syncthreads();

    for (int c = 0; c < NC; c++) {
        const uint32_t* As = gsm + (c & 1) * GS_TILE;
        const uint32_t* Bs = gsm + 2 * GS_TILE + (c & 1) * GS_TILE;

        // prefetch next chunk into registers (overlaps mma below)
        float4 pa[4], pb[4];
        if (c + 1 < NC) {
            int kk = (c + 1) * 32;
            #pragma unroll
            for (int i = 0; i < 4; i++) {
                int g = tid + i * 256;
                int row = g >> 3, q = g & 7;
                pa[i] = *(const float4*)&A[(size_t)(m0 + row) * Kd + kk + q * 4];
                pb[i] = *(const float4*)&W[(size_t)(n0b + row) * Kd + kk + q * 4];
            }
        }

        // compute: 2 k16-steps x 16 mma
        #pragma unroll
        for (int ks = 0; ks < 2; ks++) {
            int kw = ks * 8 + pd;
            uint4 av[4];
            uint2 bv[4];
            #pragma unroll
            for (int t = 0; t < 4; t++) {
                int r = mw * 64 + t * 16 + qd;
                av[t].x = As[r * GS_AS + kw];
                av[t].y = As[(r + 8) * GS_AS + kw];
                av[t].z = As[r * GS_AS + kw + 4];
                av[t].w = As[(r + 8) * GS_AS + kw + 4];
            }
            #pragma unroll
            for (int u = 0; u < 4; u++) {
                int cl = nw * 32 + u * 8 + qd;
                bv[u].x = Bs[cl * GS_AS + kw];
                bv[u].y = Bs[cl * GS_AS + kw + 4];
            }
            #pragma unroll
            for (int t = 0; t < 4; t++)
                #pragma unroll
                for (int u = 0; u < 4; u++)
                    mma_f16(acc[t][u], av[t], bv[u]);
        }

        if (c + 1 < NC) {
            __syncthreads();   // all warps done reading the buffer about to be overwritten
            uint32_t* Ad = gsm + ((c + 1) & 1) * GS_TILE;
            uint32_t* Bd = gsm + 2 * GS_TILE + ((c + 1) & 1) * GS_TILE;
            #pragma unroll
            for (int i = 0; i < 4; i++) {
                int g = tid + i * 256;
                int row = g >> 3, q = g & 7;
                *(uint2*)&Ad[row * GS_AS + q * 2] =
                    make_uint2(h2u(pa[i].x, pa[i].y), h2u(pa[i].z, pa[i].w));
                *(uint2*)&Bd[row * GS_AS + q * 2] =
                    make_uint2(h2u(pb[i].x, pb[i].y), h2u(pb[i].z, pb[i].w));
            }
            __syncthreads();
        }
    }

    // ---- epilogue: C-fragment layout -> gmem, fused bias / sigmoid ----
    #pragma unroll
    for (int t = 0; t < 4; t++) {
        int r0 = m0 + mw * 64 + t * 16 + qd;
        #pragma unroll
        for (int u = 0; u < 4; u++) {
            int col = n0b + nw * 32 + u * 8 + pd * 2;
            float v0 = acc[t][u][0], v1 = acc[t][u][1];
            float v2 = acc[t][u][2], v3 = acc[t][u][3];
            if (bias) {
                float b0 = bias[col], b1 = bias[col + 1];
                v0 += b0; v1 += b1; v2 += b0; v3 += b1;
            }
            if (sigmoidFlag) {
                v0 = 1.f / (1.f + __expf(-v0));
                v1 = 1.f / (1.f + __expf(-v1));
                v2 = 1.f / (1.f + __expf(-v2));
                v3 = 1.f / (1.f + __expf(-v3));
            }
            *(float2*)&C[(size_t)r0 * DM + col]       = make_float2(v0, v1);
            *(float2*)&C[(size_t)(r0 + 8) * DM + col] = make_float2(v2, v3);
        }
    }
}

// ---------------- pos_sum[j,d] = sum_i emb[clip(j-i,-30,30)+30, d] ----------------
__global__ void possum_kernel(const float* __restrict__ emb) {
    int j = blockIdx.x;
    int d = threadIdx.x;   // 192 threads
    float acc = 0.f;
    #pragma unroll
    for (int delta = -29; delta <= 29; delta++) {
        int i = j - delta;
        if (i >= 0 && i < MN) acc += emb[(delta + 30) * D3 + d];
    }
    int cpos = j - 29;
    if (cpos > 0) acc += (float)cpos * emb[60 * D3 + d];
    int cneg = 482 - j;
    if (cneg > 0) acc += (float)cneg * emb[0 * D3 + d];
    g_pos_sum[j * D3 + d] = acc;
}

// ---------------- multi-scale conv: xm[b,s,0:64|64:128|128:192] = conv3|5|7 --------
template <int K>
__device__ __forceinline__ void conv_do(float* xs, float* ws,
                                        const float* __restrict__ w,
                                        const float* __restrict__ bias,
                                        int coff, int b, int s0, int tid) {
    __syncthreads();
    for (int idx = tid; idx < 64 * 64 * K; idx += 256) {
        int t = idx % K;
        int i = (idx / K) & 63;
        int o = idx / (K * 64);
        ws[(i * K + t) * 64 + o] = w[idx];
    }
    __syncthreads();

    int oc = tid & 63;
    int pbase = (tid >> 6) * 16;
    float acc[16];
    float bv = bias[oc];
    #pragma unroll
    for (int pp = 0; pp < 16; pp++) acc[pp] = bv;

    for (int i = 0; i < 64; i++) {
        float xvr[16 + K - 1];
        #pragma unroll
        for (int j = 0; j < 16 + K - 1; j++)
            xvr[j] = xs[(pbase + j + 3 - K / 2) * 64 + i];
        #pragma unroll
        for (int t = 0; t < K; t++) {
            float wv = ws[(i * K + t) * 64 + oc];
            #pragma unroll
            for (int pp = 0; pp < 16; pp++) acc[pp] += xvr[pp + t] * wv;
        }
    }
    #pragma unroll
    for (int pp = 0; pp < 16; pp++)
        g_xm[((size_t)b * MN + s0 + pbase + pp) * D3 + coff + oc] = acc[pp];
}

__global__ void conv_kernel(const float* __restrict__ xv,
                            const float* __restrict__ w3, const float* __restrict__ b3,
                            const float* __restrict__ w5, const float* __restrict__ b5,
                            const float* __restrict__ w7, const float* __restrict__ b7) {
    extern __shared__ float sh[];
    float* xs = sh;             // [70][64] halo tile
    float* ws = sh + 70 * 64;   // weight stage (max 64*64*7)
    int blk = blockIdx.x;
    int b = blk >> 3;
    int s0 = (blk & 7) * 64;
    int tid = threadIdx.x;

    for (int idx = tid; idx < 70 * 64; idx += 256) {
        int r = idx >> 6, i = idx & 63;
        int s = s0 - 3 + r;
        xs[idx] = (s >= 0 && s < MN) ? xv[((size_t)b * MN + s) * VD + i] : 0.f;
    }
    conv_do<3>(xs, ws, w3, b3, 0, b, s0, tid);
    conv_do<5>(xs, ws, w5, b5, 64, b, s0, tid);
    conv_do<7>(xs, ws, w7, b7, 128, b, s0, tid);
}

// ---------------- rel-pos encoding (closed form, elementwise) ----------------------
__global__ void pe_kernel(const float* __restrict__ emb,
                          const float* __restrict__ dww, const float* __restrict__ dwb) {
    int idx = blockIdx.x * 256 + threadIdx.x;
    if (idx >= BB * MN * D3) return;
    int d = idx % D3;
    int j = (idx / D3) & (MN - 1);
    float xc = g_xm[idx];
    float fC = xc + emb[30 * D3 + d];
    float fL = 0.f, fR = 0.f;
    if (j > 0)      fL = g_xm[idx - D3] + emb[29 * D3 + d];
    if (j < MN - 1) fR = g_xm[idx + D3] + emb[31 * D3 + d];
    float diag = fL * dww[d * 3 + 0] + fC * dww[d * 3 + 1] + fR * dww[d * 3 + 2] + dwb[d];
    g_pe[idx] = xc + (g_pos_sum[j * D3 + d] - fC + diag) * (1.0f / (float)MN);
}

// ---------------- attention on fp16 m16n8k16: K [s][d], V transposed [d][s] -------
// K rows padded to 40 halves (20 words); VT rows padded to 520 halves (260 words)
#define AK_STRIDE 20    // words per K row
#define AV_STRIDE 260   // words per VT row
#define ATT_SMEM ((MN * AK_STRIDE + DK * AV_STRIDE) * 4)   // 74240 B

__global__ void __launch_bounds__(256, 2) attn_kernel() {
    extern __shared__ uint32_t ash[];
    uint32_t* Ks = ash;                    // [512][20 words] half2 pairs along d
    uint32_t* VT = ash + MN * AK_STRIDE;   // [32][260 words] half2 pairs along s
    int blk = blockIdx.x;                  // b*32 + h*4 + qblk
    int qblk = blk & 3;
    int h = (blk >> 2) & 7;
    int b = blk >> 5;
    int tid = threadIdx.x;
    int lane = tid & 31, wid = tid >> 5;
    int qd = lane >> 2, pd = lane & 3;

    // ---- stage K as half [s][d] ----
    const float* Kg = g_K + (size_t)b * MN * DM + h * DK;
    for (int i = tid; i < MN * 8; i += 256) {
        int s = i >> 3, c4 = i & 7;
        float4 kv = *(const float4*)&Kg[(size_t)s * DM + c4 * 4];
        *(uint2*)&Ks[s * AK_STRIDE + c4 * 2] = make_uint2(h2u(kv.x, kv.y), h2u(kv.z, kv.w));
    }
    // ---- stage V transposed: VT[d][spair] = half2(V[2sp][d], V[2sp+1][d]) ----
    const float* Vg = g_V + (size_t)b * MN * DM + h * DK;
    for (int g = tid; g < 2048; g += 256) {
        int spair = g >> 3, d4 = g & 7;
        int s = spair * 2;
        float4 v0 = *(const float4*)&Vg[(size_t)s * DM + d4 * 4];
        float4 v1 = *(const float4*)&Vg[(size_t)(s + 1) * DM + d4 * 4];
        VT[(d4 * 4 + 0) * AV_STRIDE + spair] = h2u(v0.x, v1.x);
        VT[(d4 * 4 + 1) * AV_STRIDE + spair] = h2u(v0.y, v1.y);
        VT[(d4 * 4 + 2) * AV_STRIDE + spair] = h2u(v0.z, v1.z);
        VT[(d4 * 4 + 3) * AV_STRIDE + spair] = h2u(v0.w, v1.w);
    }
    __syncthreads();

    // ---- Q fragments (2 m-tiles x 2 k16-steps), pre-scaled, fp16 ----
    int m0 = qblk * 256 + wid * 32;
    const float* Qg = g_Q + ((size_t)b * LL + m0) * DM + h * DK;
    const float sc = 0.17677669529663687f;   // 1/sqrt(32)
    uint4 aq[2][2];
    #pragma unroll
    for (int t = 0; t < 2; t++)
        #pragma unroll
        for (int ks = 0; ks < 2; ks++) {
            int r = t * 16 + qd;
            int c = ks * 16 + pd * 2;
            float2 x0 = *(const float2*)&Qg[(size_t)r * DM + c];
            float2 x1 = *(const float2*)&Qg[(size_t)(r + 8) * DM + c];
            float2 x2 = *(const float2*)&Qg[(size_t)r * DM + c + 8];
            float2 x3 = *(const float2*)&Qg[(size_t)(r + 8) * DM + c + 8];
            aq[t][ks] = make_uint4(h2u(x0.x * sc, x0.y * sc), h2u(x1.x * sc, x1.y * sc),
                                   h2u(x2.x * sc, x2.y * sc), h2u(x3.x * sc, x3.y * sc));
        }

    float o[2][4][4];
    #pragma unroll
    for (int t = 0; t < 2; t++)
        #pragma unroll
        for (int nv = 0; nv < 4; nv++)
            #pragma unroll
            for (int j = 0; j < 4; j++) o[t][nv][j] = 0.f;
    float rs[2][2] = {{0.f, 0.f}, {0.f, 0.f}};

    // scores bounded well inside exp/fp16 range: no max-tracking needed
    for (int s0 = 0; s0 < MN; s0 += 16) {
        // K B-frags: 2 n-tiles (s) x 2 k16-steps (d)
        uint2 bk[2][2];
        #pragma unroll
        for (int n = 0; n < 2; n++)
            #pragma unroll
            for (int ks = 0; ks < 2; ks++) {
                int w = (s0 + n * 8 + qd) * AK_STRIDE + ks * 8 + pd;
                bk[n][ks] = make_uint2(Ks[w], Ks[w + 4]);
            }

        // S = Q K^T  (8 mma)
        float c[2][2][4];
        #pragma unroll
        for (int t = 0; t < 2; t++)
            #pragma unroll
            for (int n = 0; n < 2; n++) {
                #pragma unroll
                for (int j = 0; j < 4; j++) c[t][n][j] = 0.f;
                #pragma unroll
                for (int ks = 0; ks < 2; ks++)
                    mma_f16(c[t][n], aq[t][ks], bk[n][ks]);
            }

        // exp + rowsum; QK C-frag packs directly into PV A-frag (no shuffles)
        uint4 ap[2];
        #pragma unroll
        for (int t = 0; t < 2; t++) {
            float p00 = __expf(c[t][0][0]), p01 = __expf(c[t][0][1]);
            float p02 = __expf(c[t][0][2]), p03 = __expf(c[t][0][3]);
            float p10 = __expf(c[t][1][0]), p11 = __expf(c[t][1][1]);
            float p12 = __expf(c[t][1][2]), p13 = __expf(c[t][1][3]);
            rs[t][0] += p00 + p01 + p10 + p11;
            rs[t][1] += p02 + p03 + p12 + p13;
            ap[t] = make_uint4(h2u(p00, p01), h2u(p02, p03),
                               h2u(p10, p11), h2u(p12, p13));
        }

        // V B-frags: 4 n-tiles (dk), 1 k16-step (s)
        uint2 bv[4];
        #pragma unroll
        for (int nv = 0; nv < 4; nv++) {
            int w = (nv * 8 + qd) * AV_STRIDE + (s0 >> 1) + pd;
            bv[nv] = make_uint2(VT[w], VT[w + 4]);
        }

        // O += P V  (8 mma)
        #pragma unroll
        for (int t = 0; t < 2; t++)
            #pragma unroll
            for (int nv = 0; nv < 4; nv++)
                mma_f16(o[t][nv], ap[t], bv[nv]);
    }

    // ---- rowsum reduce across quad, normalize, store ----
    #pragma unroll
    for (int t = 0; t < 2; t++) {
        #pragma unroll
        for (int r = 0; r < 2; r++) {
            rs[t][r] += __shfl_xor_sync(0xFFFFFFFFu, rs[t][r], 1);
            rs[t][r] += __shfl_xor_sync(0xFFFFFFFFu, rs[t][r], 2);
        }
        float inv0 = 1.f / rs[t][0];
        float inv1 = 1.f / rs[t][1];
        int r0 = m0 + t * 16 + qd;
        #pragma unroll
        for (int nv = 0; nv < 4; nv++) {
            int col = h * DK + nv * 8 + pd * 2;
            *(float2*)&g_attn[((size_t)b * LL + r0) * DM + col] =
                make_float2(o[t][nv][0] * inv0, o[t][nv][1] * inv0);
            *(float2*)&g_attn[((size_t)b * LL + r0 + 8) * DM + col] =
                make_float2(o[t][nv][2] * inv1, o[t][nv][3] * inv1);
        }
    }
}

// ---------------- gate * fc + residual + LayerNorm ---------------------------------
__global__ void final_kernel(const float* __restrict__ xs,
                             const float* __restrict__ lnw, const float* __restrict__ lnb,
                             float* __restrict__ out) {
    __shared__ float red[16];
    int row = blockIdx.x;          // b*1024 + l
    int b = row >> 10;
    int l = row & 1023;
    int c = threadIdx.x;
    size_t off = (size_t)row * DM + c;
    float fcv = g_fc[off];
    float gam = g_gamma[((size_t)b * MN + (l & (MN - 1))) * DM + c];
    float v = xs[off] + gam * fcv;

    float s1 = v, s2 = v * v;
    #pragma unroll
    for (int d = 16; d; d >>= 1) {
        s1 += __shfl_xor_sync(0xFFFFFFFFu, s1, d);
        s2 += __shfl_xor_sync(0xFFFFFFFFu, s2, d);
    }
    int warp = c >> 5, lane = c & 31;
    if (lane == 0) { red[warp] = s1; red[8 + warp] = s2; }
    __syncthreads();
    float t1 = 0.f, t2 = 0.f;
    #pragma unroll
    for (int w = 0; w < 8; w++) { t1 += red[w]; t2 += red[8 + w]; }
    float mu = t1 * (1.f / 256.f);
    float var = t2 * (1.f / 256.f) - mu * mu;
    out[off] = (v - mu) * rsqrtf(var + 1e-5f) * lnw[c] + lnb[c];
}

// ---------------- launch -----------------------------------------------------------
extern "C" void kernel_launch(void* const* d_in, const int* in_sizes, int n_in,
                              void* d_out, int out_size) {
    const float* x_spatial  = (const float*)d_in[0];
    const float* x_velocity = (const float*)d_in[1];
    const float* Wg    = (const float*)d_in[2];
    const float* ms_w3 = (const float*)d_in[3];
    const float* ms_b3 = (const float*)d_in[4];
    const float* ms_w5 = (const float*)d_in[5];
    const float* ms_b5 = (const float*)d_in[6];
    const float* ms_w7 = (const float*)d_in[7];
    const float* ms_b7 = (const float*)d_in[8];
    const float* rel_emb = (const float*)d_in[9];
    const float* dw_w  = (const float*)d_in[10];
    const float* dw_b  = (const float*)d_in[11];
    const float* Wq    = (const float*)d_in[12];
    const float* Wk    = (const float*)d_in[13];
    const float* Wv    = (const float*)d_in[14];
    const float* fc_w  = (const float*)d_in[15];
    const float* fc_b  = (const float*)d_in[16];
    const float* ln_w  = (const float*)d_in[17];
    const float* ln_b  = (const float*)d_in[18];
    float* out = (float*)d_out;

    float *p_gamma, *p_pe, *p_Q, *p_K, *p_V, *p_attn, *p_fc;
    cudaGetSymbolAddress((void**)&p_gamma, g_gamma);
    cudaGetSymbolAddress((void**)&p_pe,    g_pe);
    cudaGetSymbolAddress((void**)&p_Q,     g_Q);
    cudaGetSymbolAddress((void**)&p_K,     g_K);
    cudaGetSymbolAddress((void**)&p_V,     g_V);
    cudaGetSymbolAddress((void**)&p_attn,  g_attn);
    cudaGetSymbolAddress((void**)&p_fc,    g_fc);

    const int CONV_SMEM = (70 * 64 + 64 * 64 * 7) * 4;   // 132,608 B
    cudaFuncSetAttribute(conv_kernel,  cudaFuncAttributeMaxDynamicSharedMemorySize, CONV_SMEM);
    cudaFuncSetAttribute(attn_kernel,  cudaFuncAttributeMaxDynamicSharedMemorySize, ATT_SMEM);
    cudaFuncSetAttribute(mgemm_kernel, cudaFuncAttributeMaxDynamicSharedMemorySize, GSM_BYTES);

    possum_kernel<<<MN, D3>>>(rel_emb);

    // Gamma = sigmoid(x_velocity @ Wg^T)   [16384, 256]
    mgemm_kernel<<<dim3(2, BB * MN / 128), 256, GSM_BYTES>>>(x_velocity, Wg, nullptr,
                                                             p_gamma, VD, 1);
    conv_kernel<<<BB * (MN / 64), 256, CONV_SMEM>>>(x_velocity, ms_w3, ms_b3,
                                                    ms_w5, ms_b5, ms_w7, ms_b7);
    pe_kernel<<<(BB * MN * D3 + 255) / 256, 256>>>(rel_emb, dw_w, dw_b);

    // Q / K / V projections
    mgemm_kernel<<<dim3(2, BB * LL / 128), 256, GSM_BYTES>>>(x_spatial, Wq, nullptr,
                                                             p_Q, SD, 0);
    mgemm_kernel<<<dim3(2, BB * MN / 128), 256, GSM_BYTES>>>(p_pe, Wk, nullptr,
                                                             p_K, D3, 0);
    mgemm_kernel<<<dim3(2, BB * MN / 128), 256, GSM_BYTES>>>(p_pe, Wv, nullptr,
                                                             p_V, D3, 0);

    attn_kernel<<<BB * NH * 4, 256, ATT_SMEM>>>();

    mgemm_kernel<<<dim3(2, BB * LL / 128), 256, GSM_BYTES>>>(p_attn, fc_w, fc_b,
                                                             p_fc, DM, 0);
    final_kernel<<<BB * LL, 256>>>(x_spatial, ln_w, ln_b, out);
}

// round 7
// speedup vs baseline: 4.7496x; 1.5153x over previous
#include <cuda_runtime.h>
#include <cuda_fp16.h>
#include <math.h>
#include <stdint.h>

#define BB 32
#define LL 1024
#define MN 512
#define SD 256
#define VD 64
#define D3 192
#define DM 256
#define NH 8
#define DK 32

// ---------------- scratch (device globals; no allocation allowed) ----------------
__device__ float g_pos_sum[MN * D3];
__device__ float g_gamma[BB * MN * DM];
__device__ float g_xm[BB * MN * D3];
__device__ float g_pe[BB * MN * D3];
__device__ float g_Q[BB * LL * DM];
__device__ float g_K[BB * MN * DM];
__device__ float g_V[BB * MN * DM];
__device__ float g_attn[BB * LL * DM];
__device__ uint4 g_wh4[12096];   // conv weights: [7 taps][192 ch][72 halves] fp16

// ================= fp16 mma helpers (sm_80+ features, base target OK) =============
__device__ __forceinline__ uint32_t h2u(float a, float b) {
    __half2 h = __floats2half2_rn(a, b);
    return *(uint32_t*)&h;
}
__device__ __forceinline__ void mma_f16(float* c, uint4 a, uint2 b) {
    asm("mma.sync.aligned.m16n8k16.row.col.f32.f16.f16.f32 "
        "{%0,%1,%2,%3}, {%4,%5,%6,%7}, {%8,%9}, {%0,%1,%2,%3};"
        : "+f"(c[0]), "+f"(c[1]), "+f"(c[2]), "+f"(c[3])
        : "r"(a.x), "r"(a.y), "r"(a.z), "r"(a.w), "r"(b.x), "r"(b.y));
}

// GEMM smem: A/B half tiles, 128 rows x 32 halves, padded to 40 halves (20 words)
#define GS_AS 20                    // words per row
#define GS_TILE (128 * GS_AS)       // 2560 words per tile
#define GSM_BYTES (4 * GS_TILE * 4) // A0,A1,B0,B1 = 40960 B

// ---------------- tensor-core GEMM: C[M,256] = A[M,Kd] * W[256,Kd]^T ---------------
__global__ void __launch_bounds__(256, 1) mgemm_kernel(
    const float* __restrict__ A, const float* __restrict__ W,
    const float* __restrict__ bias, float* __restrict__ C,
    int Kd, int sigmoidFlag) {
    extern __shared__ uint32_t gsm[];
    int tid = threadIdx.x;
    int lane = tid & 31, wid = tid >> 5;
    int mw = wid & 1, nw = wid >> 1;
    int qd = lane >> 2, pd = lane & 3;
    int m0 = blockIdx.y * 128;
    int n0b = blockIdx.x * 128;
    int NC = Kd >> 5;

    float acc[4][4][4];
    #pragma unroll
    for (int t = 0; t < 4; t++)
        #pragma unroll
        for (int u = 0; u < 4; u++)
            #pragma unroll
            for (int j = 0; j < 4; j++) acc[t][u][j] = 0.f;

    {
        uint32_t* Ad = gsm;
        uint32_t* Bd = gsm + 2 * GS_TILE;
        #pragma unroll
        for (int i = 0; i < 4; i++) {
            int g = tid + i * 256;
            int row = g >> 3, q = g & 7;
            float4 va = *(const float4*)&A[(size_t)(m0 + row) * Kd + q * 4];
            float4 vb = *(const float4*)&W[(size_t)(n0b + row) * Kd + q * 4];
            *(uint2*)&Ad[row * GS_AS + q * 2] = make_uint2(h2u(va.x, va.y), h2u(va.z, va.w));
            *(uint2*)&Bd[row * GS_AS + q * 2] = make_uint2(h2u(vb.x, vb.y), h2u(vb.z, vb.w));
        }
    }
    __syncthreads();

    for (int c = 0; c < NC; c++) {
        const uint32_t* As = gsm + (c & 1) * GS_TILE;
        const uint32_t* Bs = gsm + 2 * GS_TILE + (c & 1) * GS_TILE;

        float4 pa[4], pb[4];
        if (c + 1 < NC) {
            int kk = (c + 1) * 32;
            #pragma unroll
            for (int i = 0; i < 4; i++) {
                int g = tid + i * 256;
                int row = g >> 3, q = g & 7;
                pa[i] = *(const float4*)&A[(size_t)(m0 + row) * Kd + kk + q * 4];
                pb[i] = *(const float4*)&W[(size_t)(n0b + row) * Kd + kk + q * 4];
            }
        }

        #pragma unroll
        for (int ks = 0; ks < 2; ks++) {
            int kw = ks * 8 + pd;
            uint4 av[4];
            uint2 bv[4];
            #pragma unroll
            for (int t = 0; t < 4; t++) {
                int r = mw * 64 + t * 16 + qd;
                av[t].x = As[r * GS_AS + kw];
                av[t].y = As[(r + 8) * GS_AS + kw];
                av[t].z = As[r * GS_AS + kw + 4];
                av[t].w = As[(r + 8) * GS_AS + kw + 4];
            }
            #pragma unroll
            for (int u = 0; u < 4; u++) {
                int cl = nw * 32 + u * 8 + qd;
                bv[u].x = Bs[cl * GS_AS + kw];
                bv[u].y = Bs[cl * GS_AS + kw + 4];
            }
            #pragma unroll
            for (int t = 0; t < 4; t++)
                #pragma unroll
                for (int u = 0; u < 4; u++)
                    mma_f16(acc[t][u], av[t], bv[u]);
        }

        if (c + 1 < NC) {
            __syncthreads();
            uint32_t* Ad = gsm + ((c + 1) & 1) * GS_TILE;
            uint32_t* Bd = gsm + 2 * GS_TILE + ((c + 1) & 1) * GS_TILE;
            #pragma unroll
            for (int i = 0; i < 4; i++) {
                int g = tid + i * 256;
                int row = g >> 3, q = g & 7;
                *(uint2*)&Ad[row * GS_AS + q * 2] =
                    make_uint2(h2u(pa[i].x, pa[i].y), h2u(pa[i].z, pa[i].w));
                *(uint2*)&Bd[row * GS_AS + q * 2] =
                    make_uint2(h2u(pb[i].x, pb[i].y), h2u(pb[i].z, pb[i].w));
            }
            __syncthreads();
        }
    }

    #pragma unroll
    for (int t = 0; t < 4; t++) {
        int r0 = m0 + mw * 64 + t * 16 + qd;
        #pragma unroll
        for (int u = 0; u < 4; u++) {
            int col = n0b + nw * 32 + u * 8 + pd * 2;
            float v0 = acc[t][u][0], v1 = acc[t][u][1];
            float v2 = acc[t][u][2], v3 = acc[t][u][3];
            if (bias) {
                float b0 = bias[col], b1 = bias[col + 1];
                v0 += b0; v1 += b1; v2 += b0; v3 += b1;
            }
            if (sigmoidFlag) {
                v0 = 1.f / (1.f + __expf(-v0));
                v1 = 1.f / (1.f + __expf(-v1));
                v2 = 1.f / (1.f + __expf(-v2));
                v3 = 1.f / (1.f + __expf(-v3));
            }
            *(float2*)&C[(size_t)r0 * DM + col]       = make_float2(v0, v1);
            *(float2*)&C[(size_t)(r0 + 8) * DM + col] = make_float2(v2, v3);
        }
    }
}

// ---------------- conv weight prep: W'[tap][192][72 halves], zero-padded ----------
__global__ void wprep_kernel(const float* __restrict__ w3, const float* __restrict__ w5,
                             const float* __restrict__ w7) {
    int idx = blockIdx.x * 256 + threadIdx.x;
    if (idx >= 7 * 192 * 72) return;
    int t = idx / (192 * 72);
    int rem = idx % (192 * 72);
    int c = rem / 72;
    int i = rem % 72;
    float v = 0.f;
    if (i < 64) {
        if (c < 64)       { if (t >= 2 && t <= 4) v = w3[(c * 64 + i) * 3 + (t - 2)]; }
        else if (c < 128) { int cc = c - 64; if (t >= 1 && t <= 5) v = w5[(cc * 64 + i) * 5 + (t - 1)]; }
        else              { int cc = c - 128; v = w7[(cc * 64 + i) * 7 + t]; }
    }
    ((__half*)g_wh4)[idx] = __float2half_rn(v);
}

// ---------------- multi-scale conv as fp16 HMMA over im2col --------------------
// block = 128 positions x 192 channels; 8 warps 2m x 4n (warp 64x48)
#define CXR 134                 // 128 + 6 halo rows
#define CXS 36                  // words per xv row (64 halves + pad)
#define CWS 36                  // words per W' row
#define CSLAB (192 * CWS)       // 6912 words per tap
#define CONV_SMEM ((CXR * CXS + 7 * CSLAB) * 4)   // 212832 B

__global__ void __launch_bounds__(256, 1) conv_kernel(
    const float* __restrict__ xv, const float* __restrict__ b3,
    const float* __restrict__ b5, const float* __restrict__ b7) {
    extern __shared__ uint32_t csm[];
    uint32_t* xvs = csm;               // [134][36 words] halo tile fp16
    uint32_t* ws = csm + CXR * CXS;    // [7][192][36 words]
    int blk = blockIdx.x;
    int b = blk >> 2;
    int s0 = (blk & 3) * 128;
    int tid = threadIdx.x;
    int lane = tid & 31, wid = tid >> 5;
    int mw = wid & 1, nw = wid >> 1;
    int qd = lane >> 2, pd = lane & 3;

    // stage xv tile (rows s0-3 .. s0+130), fp16, zero outside sequence
    for (int g = tid; g < CXR * 16; g += 256) {
        int row = g >> 4, c4 = g & 15;
        int s = s0 - 3 + row;
        float4 v = make_float4(0.f, 0.f, 0.f, 0.f);
        if (s >= 0 && s < MN) v = *(const float4*)&xv[((size_t)b * MN + s) * VD + c4 * 4];
        *(uint2*)&xvs[row * CXS + c4 * 2] = make_uint2(h2u(v.x, v.y), h2u(v.z, v.w));
    }
    // stage all 7 weight slabs
    {
        uint4* wd = (uint4*)ws;
        for (int g = tid; g < 12096; g += 256) wd[g] = g_wh4[g];
    }
    __syncthreads();

    float acc[4][6][4];
    #pragma unroll
    for (int t = 0; t < 4; t++)
        #pragma unroll
        for (int u = 0; u < 6; u++)
            #pragma unroll
            for (int j = 0; j < 4; j++) acc[t][u][j] = 0.f;

    #pragma unroll
    for (int tp = 0; tp < 7; tp++) {
        const int abase = (tp >= 2 && tp <= 4) ? 0 : ((tp == 1 || tp == 5) ? 64 : 128);
        const uint32_t* wt = ws + tp * CSLAB;
        #pragma unroll
        for (int ks = 0; ks < 4; ks++) {
            uint4 av[4];
            #pragma unroll
            for (int t = 0; t < 4; t++) {
                int r = mw * 64 + t * 16 + qd + tp;
                av[t].x = xvs[r * CXS + ks * 8 + pd];
                av[t].z = xvs[r * CXS + ks * 8 + pd + 4];
                av[t].y = xvs[(r + 8) * CXS + ks * 8 + pd];
                av[t].w = xvs[(r + 8) * CXS + ks * 8 + pd + 4];
            }
            uint2 bv[6];
            #pragma unroll
            for (int u = 0; u < 6; u++) {
                int c0 = nw * 48 + u * 8;
                if (c0 >= abase) {
                    int cl = c0 + qd;
                    bv[u].x = wt[cl * CWS + ks * 8 + pd];
                    bv[u].y = wt[cl * CWS + ks * 8 + pd + 4];
                }
            }
            #pragma unroll
            for (int u = 0; u < 6; u++) {
                int c0 = nw * 48 + u * 8;
                if (c0 >= abase) {
                    #pragma unroll
                    for (int t = 0; t < 4; t++)
                        mma_f16(acc[t][u], av[t], bv[u]);
                }
            }
        }
    }

    // epilogue: add per-scale bias, write g_xm float
    #pragma unroll
    for (int t = 0; t < 4; t++) {
        int s = s0 + mw * 64 + t * 16 + qd;
        #pragma unroll
        for (int u = 0; u < 6; u++) {
            int col = nw * 48 + u * 8 + pd * 2;
            float bb0 = col < 64 ? b3[col] : (col < 128 ? b5[col - 64] : b7[col - 128]);
            int c1 = col + 1;
            float bb1 = c1 < 64 ? b3[c1] : (c1 < 128 ? b5[c1 - 64] : b7[c1 - 128]);
            *(float2*)&g_xm[((size_t)b * MN + s) * D3 + col] =
                make_float2(acc[t][u][0] + bb0, acc[t][u][1] + bb1);
            *(float2*)&g_xm[((size_t)b * MN + s + 8) * D3 + col] =
                make_float2(acc[t][u][2] + bb0, acc[t][u][3] + bb1);
        }
    }
}

// ---------------- pos_sum[j,d] = sum_i emb[clip(j-i,-30,30)+30, d] ----------------
__global__ void possum_kernel(const float* __restrict__ emb) {
    int j = blockIdx.x;
    int d = threadIdx.x;   // 192 threads
    float acc = 0.f;
    #pragma unroll
    for (int delta = -29; delta <= 29; delta++) {
        int i = j - delta;
        if (i >= 0 && i < MN) acc += emb[(delta + 30) * D3 + d];
    }
    int cpos = j - 29;
    if (cpos > 0) acc += (float)cpos * emb[60 * D3 + d];
    int cneg = 482 - j;
    if (cneg > 0) acc += (float)cneg * emb[0 * D3 + d];
    g_pos_sum[j * D3 + d] = acc;
}

// ---------------- rel-pos encoding (closed form, elementwise) ----------------------
__global__ void pe_kernel(const float* __restrict__ emb,
                          const float* __restrict__ dww, const float* __restrict__ dwb) {
    int idx = blockIdx.x * 256 + threadIdx.x;
    if (idx >= BB * MN * D3) return;
    int d = idx % D3;
    int j = (idx / D3) & (MN - 1);
    float xc = g_xm[idx];
    float fC = xc + emb[30 * D3 + d];
    float fL = 0.f, fR = 0.f;
    if (j > 0)      fL = g_xm[idx - D3] + emb[29 * D3 + d];
    if (j < MN - 1) fR = g_xm[idx + D3] + emb[31 * D3 + d];
    float diag = fL * dww[d * 3 + 0] + fC * dww[d * 3 + 1] + fR * dww[d * 3 + 2] + dwb[d];
    g_pe[idx] = xc + (g_pos_sum[j * D3 + d] - fC + diag) * (1.0f / (float)MN);
}

// ---------------- attention on fp16 m16n8k16: K [s][d], V transposed [d][s] -------
#define AK_STRIDE 20    // words per K row
#define AV_STRIDE 260   // words per VT row
#define ATT_SMEM ((MN * AK_STRIDE + DK * AV_STRIDE) * 4)   // 74240 B

__global__ void __launch_bounds__(256, 2) attn_kernel() {
    extern __shared__ uint32_t ash[];
    uint32_t* Ks = ash;                    // [512][20 words]
    uint32_t* VT = ash + MN * AK_STRIDE;   // [32][260 words]
    int blk = blockIdx.x;                  // b*32 + h*4 + qblk
    int qblk = blk & 3;
    int h = (blk >> 2) & 7;
    int b = blk >> 5;
    int tid = threadIdx.x;
    int lane = tid & 31, wid = tid >> 5;
    int qd = lane >> 2, pd = lane & 3;

    const float* Kg = g_K + (size_t)b * MN * DM + h * DK;
    for (int i = tid; i < MN * 8; i += 256) {
        int s = i >> 3, c4 = i & 7;
        float4 kv = *(const float4*)&Kg[(size_t)s * DM + c4 * 4];
        *(uint2*)&Ks[s * AK_STRIDE + c4 * 2] = make_uint2(h2u(kv.x, kv.y), h2u(kv.z, kv.w));
    }
    const float* Vg = g_V + (size_t)b * MN * DM + h * DK;
    for (int g = tid; g < 2048; g += 256) {
        int spair = g >> 3, d4 = g & 7;
        int s = spair * 2;
        float4 v0 = *(const float4*)&Vg[(size_t)s * DM + d4 * 4];
        float4 v1 = *(const float4*)&Vg[(size_t)(s + 1) * DM + d4 * 4];
        VT[(d4 * 4 + 0) * AV_STRIDE + spair] = h2u(v0.x, v1.x);
        VT[(d4 * 4 + 1) * AV_STRIDE + spair] = h2u(v0.y, v1.y);
        VT[(d4 * 4 + 2) * AV_STRIDE + spair] = h2u(v0.z, v1.z);
        VT[(d4 * 4 + 3) * AV_STRIDE + spair] = h2u(v0.w, v1.w);
    }
    __syncthreads();

    int m0 = qblk * 256 + wid * 32;
    const float* Qg = g_Q + ((size_t)b * LL + m0) * DM + h * DK;
    const float sc = 0.17677669529663687f;   // 1/sqrt(32)
    uint4 aq[2][2];
    #pragma unroll
    for (int t = 0; t < 2; t++)
        #pragma unroll
        for (int ks = 0; ks < 2; ks++) {
            int r = t * 16 + qd;
            int c = ks * 16 + pd * 2;
            float2 x0 = *(const float2*)&Qg[(size_t)r * DM + c];
            float2 x1 = *(const float2*)&Qg[(size_t)(r + 8) * DM + c];
            float2 x2 = *(const float2*)&Qg[(size_t)r * DM + c + 8];
            float2 x3 = *(const float2*)&Qg[(size_t)(r + 8) * DM + c + 8];
            aq[t][ks] = make_uint4(h2u(x0.x * sc, x0.y * sc), h2u(x1.x * sc, x1.y * sc),
                                   h2u(x2.x * sc, x2.y * sc), h2u(x3.x * sc, x3.y * sc));
        }

    float o[2][4][4];
    #pragma unroll
    for (int t = 0; t < 2; t++)
        #pragma unroll
        for (int nv = 0; nv < 4; nv++)
            #pragma unroll
            for (int j = 0; j < 4; j++) o[t][nv][j] = 0.f;
    float rs[2][2] = {{0.f, 0.f}, {0.f, 0.f}};

    for (int s0 = 0; s0 < MN; s0 += 16) {
        uint2 bk[2][2];
        #pragma unroll
        for (int n = 0; n < 2; n++)
            #pragma unroll
            for (int ks = 0; ks < 2; ks++) {
                int w = (s0 + n * 8 + qd) * AK_STRIDE + ks * 8 + pd;
                bk[n][ks] = make_uint2(Ks[w], Ks[w + 4]);
            }

        float c[2][2][4];
        #pragma unroll
        for (int t = 0; t < 2; t++)
            #pragma unroll
            for (int n = 0; n < 2; n++) {
                #pragma unroll
                for (int j = 0; j < 4; j++) c[t][n][j] = 0.f;
                #pragma unroll
                for (int ks = 0; ks < 2; ks++)
                    mma_f16(c[t][n], aq[t][ks], bk[n][ks]);
            }

        uint4 ap[2];
        #pragma unroll
        for (int t = 0; t < 2; t++) {
            float p00 = __expf(c[t][0][0]), p01 = __expf(c[t][0][1]);
            float p02 = __expf(c[t][0][2]), p03 = __expf(c[t][0][3]);
            float p10 = __expf(c[t][1][0]), p11 = __expf(c[t][1][1]);
            float p12 = __expf(c[t][1][2]), p13 = __expf(c[t][1][3]);
            rs[t][0] += p00 + p01 + p10 + p11;
            rs[t][1] += p02 + p03 + p12 + p13;
            ap[t] = make_uint4(h2u(p00, p01), h2u(p02, p03),
                               h2u(p10, p11), h2u(p12, p13));
        }

        uint2 bv[4];
        #pragma unroll
        for (int nv = 0; nv < 4; nv++) {
            int w = (nv * 8 + qd) * AV_STRIDE + (s0 >> 1) + pd;
            bv[nv] = make_uint2(VT[w], VT[w + 4]);
        }

        #pragma unroll
        for (int t = 0; t < 2; t++)
            #pragma unroll
            for (int nv = 0; nv < 4; nv++)
                mma_f16(o[t][nv], ap[t], bv[nv]);
    }

    #pragma unroll
    for (int t = 0; t < 2; t++) {
        #pragma unroll
        for (int r = 0; r < 2; r++) {
            rs[t][r] += __shfl_xor_sync(0xFFFFFFFFu, rs[t][r], 1);
            rs[t][r] += __shfl_xor_sync(0xFFFFFFFFu, rs[t][r], 2);
        }
        float inv0 = 1.f / rs[t][0];
        float inv1 = 1.f / rs[t][1];
        int r0 = m0 + t * 16 + qd;
        #pragma unroll
        for (int nv = 0; nv < 4; nv++) {
            int col = h * DK + nv * 8 + pd * 2;
            *(float2*)&g_attn[((size_t)b * LL + r0) * DM + col] =
                make_float2(o[t][nv][0] * inv0, o[t][nv][1] * inv0);
            *(float2*)&g_attn[((size_t)b * LL + r0 + 8) * DM + col] =
                make_float2(o[t][nv][2] * inv1, o[t][nv][3] * inv1);
        }
    }
}

// ---------------- fc GEMM fused with gate + residual + LayerNorm ------------------
// block = 64 rows x 256 cols; 8 warps 2m x 4n (warp 32x64)
#define FA_TILE (64 * GS_AS)     // 1280 words
#define FB_TILE (256 * GS_AS)    // 5120 words
#define FSM_BYTES ((2 * FA_TILE + 2 * FB_TILE + 512) * 4)   // 53248 B

__global__ void __launch_bounds__(256, 1) fcln_kernel(
    const float* __restrict__ Wf, const float* __restrict__ fb,
    const float* __restrict__ xs, const float* __restrict__ lnw,
    const float* __restrict__ lnb, float* __restrict__ out) {
    extern __shared__ uint32_t fsm[];
    float* red = (float*)(fsm + 2 * FA_TILE + 2 * FB_TILE);
    const float* A = g_attn;
    int tid = threadIdx.x;
    int lane = tid & 31, wid = tid >> 5;
    int mw = wid & 1, nw = wid >> 1;
    int qd = lane >> 2, pd = lane & 3;
    int row0 = blockIdx.x * 64;
    int b = row0 >> 10;
    const int NC = 8;   // K = 256

    float acc[2][8][4];
    #pragma unroll
    for (int t = 0; t < 2; t++)
        #pragma unroll
        for (int u = 0; u < 8; u++)
            #pragma unroll
            for (int j = 0; j < 4; j++) acc[t][u][j] = 0.f;

    {
        uint32_t* Ad = fsm;
        uint32_t* Bd = fsm + 2 * FA_TILE;
        #pragma unroll
        for (int i = 0; i < 10; i++) {
            int g = tid + i * 256;
            if (g < 512) {
                int row = g >> 3, q = g & 7;
                float4 v = *(const float4*)&A[(size_t)(row0 + row) * DM + q * 4];
                *(uint2*)&Ad[row * GS_AS + q * 2] = make_uint2(h2u(v.x, v.y), h2u(v.z, v.w));
            } else {
                int j = g - 512;
                int row = j >> 3, q = j & 7;
                float4 v = *(const float4*)&Wf[(size_t)row * DM + q * 4];
                *(uint2*)&Bd[row * GS_AS + q * 2] = make_uint2(h2u(v.x, v.y), h2u(v.z, v.w));
            }
        }
    }
    __syncthreads();

    for (int c = 0; c < NC; c++) {
        const uint32_t* As = fsm + (c & 1) * FA_TILE;
        const uint32_t* Bs = fsm + 2 * FA_TILE + (c & 1) * FB_TILE;

        float4 pa[10];
        if (c + 1 < NC) {
            int kk = (c + 1) * 32;
            #pragma unroll
            for (int i = 0; i < 10; i++) {
                int g = tid + i * 256;
                if (g < 512) {
                    int row = g >> 3, q = g & 7;
                    pa[i] = *(const float4*)&A[(size_t)(row0 + row) * DM + kk + q * 4];
                } else {
                    int j = g - 512;
                    int row = j >> 3, q = j & 7;
                    pa[i] = *(const float4*)&Wf[(size_t)row * DM + kk + q * 4];
                }
            }
        }

        #pragma unroll
        for (int ks = 0; ks < 2; ks++) {
            int kw = ks * 8 + pd;
            uint4 av[2];
            uint2 bv[8];
            #pragma unroll
            for (int t = 0; t < 2; t++) {
                int r = mw * 32 + t * 16 + qd;
                av[t].x = As[r * GS_AS + kw];
                av[t].y = As[(r + 8) * GS_AS + kw];
                av[t].z = As[r * GS_AS + kw + 4];
                av[t].w = As[(r + 8) * GS_AS + kw + 4];
            }
            #pragma unroll
            for (int u = 0; u < 8; u++) {
                int cl = nw * 64 + u * 8 + qd;
                bv[u].x = Bs[cl * GS_AS + kw];
                bv[u].y = Bs[cl * GS_AS + kw + 4];
            }
            #pragma unroll
            for (int t = 0; t < 2; t++)
                #pragma unroll
                for (int u = 0; u < 8; u++)
                    mma_f16(acc[t][u], av[t], bv[u]);
        }

        if (c + 1 < NC) {
            __syncthreads();
            uint32_t* Ad = fsm + ((c + 1) & 1) * FA_TILE;
            uint32_t* Bd = fsm + 2 * FA_TILE + ((c + 1) & 1) * FB_TILE;
            #pragma unroll
            for (int i = 0; i < 10; i++) {
                int g = tid + i * 256;
                if (g < 512) {
                    int row = g >> 3, q = g & 7;
                    *(uint2*)&Ad[row * GS_AS + q * 2] =
                        make_uint2(h2u(pa[i].x, pa[i].y), h2u(pa[i].z, pa[i].w));
                } else {
                    int j = g - 512;
                    int row = j >> 3, q = j & 7;
                    *(uint2*)&Bd[row * GS_AS + q * 2] =
                        make_uint2(h2u(pa[i].x, pa[i].y), h2u(pa[i].z, pa[i].w));
                }
            }
            __syncthreads();
        }
    }

    // ---- epilogue: v = xs + gamma * (fc + bias); LayerNorm over 256 cols ----
    __syncthreads();   // staging buffers done; red region free
    #pragma unroll
    for (int t = 0; t < 2; t++) {
        #pragma unroll
        for (int hf = 0; hf < 2; hf++) {
            int lr = mw * 32 + t * 16 + qd + hf * 8;
            int r = row0 + lr;
            int l = r & 1023;
            const float* gam = g_gamma + ((size_t)b * MN + (l & (MN - 1))) * DM;
            const float* xr = xs + (size_t)r * DM;
            float s1 = 0.f, s2 = 0.f;
            #pragma unroll
            for (int u = 0; u < 8; u++) {
                int col = nw * 64 + u * 8 + pd * 2;
                int j0 = hf * 2;
                float v0 = xr[col] + gam[col] * (acc[t][u][j0] + fb[col]);
                float v1 = xr[col + 1] + gam[col + 1] * (acc[t][u][j0 + 1] + fb[col + 1]);
                acc[t][u][j0] = v0;
                acc[t][u][j0 + 1] = v1;
                s1 += v0 + v1;
                s2 += v0 * v0 + v1 * v1;
            }
            s1 += __shfl_xor_sync(0xFFFFFFFFu, s1, 1);
            s1 += __shfl_xor_sync(0xFFFFFFFFu, s1, 2);
            s2 += __shfl_xor_sync(0xFFFFFFFFu, s2, 1);
            s2 += __shfl_xor_sync(0xFFFFFFFFu, s2, 2);
            if (pd == 0) {
                red[nw * 64 + lr] = s1;
                red[256 + nw * 64 + lr] = s2;
            }
        }
    }
    __syncthreads();
    #pragma unroll
    for (int t = 0; t < 2; t++) {
        #pragma unroll
        for (int hf = 0; hf < 2; hf++) {
            int lr = mw * 32 + t * 16 + qd + hf * 8;
            int r = row0 + lr;
            float t1 = red[lr] + red[64 + lr] + red[128 + lr] + red[192 + lr];
            float t2 = red[256 + lr] + red[320 + lr] + red[384 + lr] + red[448 + lr];
            float mu = t1 * (1.f / 256.f);
            float var = t2 * (1.f / 256.f) - mu * mu;
            float rstd = rsqrtf(var + 1e-5f);
            #pragma unroll
            for (int u = 0; u < 8; u++) {
                int col = nw * 64 + u * 8 + pd * 2;
                int j0 = hf * 2;
                float v0 = (acc[t][u][j0] - mu) * rstd * lnw[col] + lnb[col];
                float v1 = (acc[t][u][j0 + 1] - mu) * rstd * lnw[col + 1] + lnb[col + 1];
                *(float2*)&out[(size_t)r * DM + col] = make_float2(v0, v1);
            }
        }
    }
}

// ---------------- launch -----------------------------------------------------------
extern "C" void kernel_launch(void* const* d_in, const int* in_sizes, int n_in,
                              void* d_out, int out_size) {
    const float* x_spatial  = (const float*)d_in[0];
    const float* x_velocity = (const float*)d_in[1];
    const float* Wg    = (const float*)d_in[2];
    const float* ms_w3 = (const float*)d_in[3];
    const float* ms_b3 = (const float*)d_in[4];
    const float* ms_w5 = (const float*)d_in[5];
    const float* ms_b5 = (const float*)d_in[6];
    const float* ms_w7 = (const float*)d_in[7];
    const float* ms_b7 = (const float*)d_in[8];
    const float* rel_emb = (const float*)d_in[9];
    const float* dw_w  = (const float*)d_in[10];
    const float* dw_b  = (const float*)d_in[11];
    const float* Wq    = (const float*)d_in[12];
    const float* Wk    = (const float*)d_in[13];
    const float* Wv    = (const float*)d_in[14];
    const float* fc_w  = (const float*)d_in[15];
    const float* fc_b  = (const float*)d_in[16];
    const float* ln_w  = (const float*)d_in[17];
    const float* ln_b  = (const float*)d_in[18];
    float* out = (float*)d_out;

    float *p_gamma, *p_pe, *p_Q, *p_K, *p_V;
    cudaGetSymbolAddress((void**)&p_gamma, g_gamma);
    cudaGetSymbolAddress((void**)&p_pe,    g_pe);
    cudaGetSymbolAddress((void**)&p_Q,     g_Q);
    cudaGetSymbolAddress((void**)&p_K,     g_K);
    cudaGetSymbolAddress((void**)&p_V,     g_V);

    cudaFuncSetAttribute(conv_kernel,  cudaFuncAttributeMaxDynamicSharedMemorySize, CONV_SMEM);
    cudaFuncSetAttribute(attn_kernel,  cudaFuncAttributeMaxDynamicSharedMemorySize, ATT_SMEM);
    cudaFuncSetAttribute(mgemm_kernel, cudaFuncAttributeMaxDynamicSharedMemorySize, GSM_BYTES);
    cudaFuncSetAttribute(fcln_kernel,  cudaFuncAttributeMaxDynamicSharedMemorySize, FSM_BYTES);

    wprep_kernel<<<(7 * 192 * 72 + 255) / 256, 256>>>(ms_w3, ms_w5, ms_w7);
    possum_kernel<<<MN, D3>>>(rel_emb);

    // Gamma = sigmoid(x_velocity @ Wg^T)
    mgemm_kernel<<<dim3(2, BB * MN / 128), 256, GSM_BYTES>>>(x_velocity, Wg, nullptr,
                                                             p_gamma, VD, 1);
    conv_kernel<<<BB * 4, 256, CONV_SMEM>>>(x_velocity, ms_b3, ms_b5, ms_b7);
    pe_kernel<<<(BB * MN * D3 + 255) / 256, 256>>>(rel_emb, dw_w, dw_b);

    // Q / K / V projections
    mgemm_kernel<<<dim3(2, BB * LL / 128), 256, GSM_BYTES>>>(x_spatial, Wq, nullptr,
                                                             p_Q, SD, 0);
    mgemm_kernel<<<dim3(2, BB * MN / 128), 256, GSM_BYTES>>>(p_pe, Wk, nullptr,
                                                             p_K, D3, 0);
    mgemm_kernel<<<dim3(2, BB * MN / 128), 256, GSM_BYTES>>>(p_pe, Wv, nullptr,
                                                             p_V, D3, 0);

    attn_kernel<<<BB * NH * 4, 256, ATT_SMEM>>>();

    fcln_kernel<<<BB * LL / 64, 256, FSM_BYTES>>>(fc_w, fc_b, x_spatial, ln_w, ln_b, out);
}

// round 8
// speedup vs baseline: 4.9916x; 1.0509x over previous
#include <cuda_runtime.h>
#include <cuda_fp16.h>
#include <math.h>
#include <stdint.h>

#define BB 32
#define LL 1024
#define MN 512
#define SD 256
#define VD 64
#define D3 192
#define DM 256
#define NH 8
#define DK 32

// ---------------- scratch (device globals; no allocation allowed) ----------------
__device__ float g_pos_sum[MN * D3];
__device__ float g_gamma[BB * MN * DM];
__device__ float g_xm[BB * MN * D3];
__device__ float g_pe[BB * MN * D3];
__device__ __half g_Qh[BB * LL * DM];
__device__ __half g_Kh[BB * MN * DM];
__device__ __half g_Vh[BB * MN * DM];
__device__ __half g_attnh[BB * LL * DM];
__device__ uint32_t g_wh[7 * 192 * 36];   // conv weights fp16: [tap][192 ch][72 halves]

// ================= fp16 mma helpers (sm_80+ features, base target OK) =============
__device__ __forceinline__ uint32_t h2u(float a, float b) {
    __half2 h = __floats2half2_rn(a, b);
    return *(uint32_t*)&h;
}
__device__ __forceinline__ void mma_f16(float* c, uint4 a, uint2 b) {
    asm("mma.sync.aligned.m16n8k16.row.col.f32.f16.f16.f32 "
        "{%0,%1,%2,%3}, {%4,%5,%6,%7}, {%8,%9}, {%0,%1,%2,%3};"
        : "+f"(c[0]), "+f"(c[1]), "+f"(c[2]), "+f"(c[3])
        : "r"(a.x), "r"(a.y), "r"(a.z), "r"(a.w), "r"(b.x), "r"(b.y));
}

// GEMM smem: A/B half tiles, 128 rows x 32 halves, padded to 40 halves (20 words)
#define GS_AS 20                    // words per row
#define GS_TILE (128 * GS_AS)       // 2560 words per tile
#define GSM_BYTES (4 * GS_TILE * 4) // A0,A1,B0,B1 = 40960 B

// ---------------- tensor-core GEMM: C[M,256] = A[M,Kd] * W[256,Kd]^T ---------------
// Cf != null -> float out (optional sigmoid); Ch != null -> fp16 out scaled by outScale
__global__ void __launch_bounds__(256, 1) mgemm_kernel(
    const float* __restrict__ A, const float* __restrict__ W,
    float* __restrict__ Cf, __half* __restrict__ Ch,
    int Kd, int sigmoidFlag, float outScale) {
    extern __shared__ uint32_t gsm[];
    int tid = threadIdx.x;
    int lane = tid & 31, wid = tid >> 5;
    int mw = wid & 1, nw = wid >> 1;
    int qd = lane >> 2, pd = lane & 3;
    int m0 = blockIdx.y * 128;
    int n0b = blockIdx.x * 128;
    int NC = Kd >> 5;

    float acc[4][4][4];
    #pragma unroll
    for (int t = 0; t < 4; t++)
        #pragma unroll
        for (int u = 0; u < 4; u++)
            #pragma unroll
            for (int j = 0; j < 4; j++) acc[t][u][j] = 0.f;

    {
        uint32_t* Ad = gsm;
        uint32_t* Bd = gsm + 2 * GS_TILE;
        #pragma unroll
        for (int i = 0; i < 4; i++) {
            int g = tid + i * 256;
            int row = g >> 3, q = g & 7;
            float4 va = *(const float4*)&A[(size_t)(m0 + row) * Kd + q * 4];
            float4 vb = *(const float4*)&W[(size_t)(n0b + row) * Kd + q * 4];
            *(uint2*)&Ad[row * GS_AS + q * 2] = make_uint2(h2u(va.x, va.y), h2u(va.z, va.w));
            *(uint2*)&Bd[row * GS_AS + q * 2] = make_uint2(h2u(vb.x, vb.y), h2u(vb.z, vb.w));
        }
    }
    __syncthreads();

    for (int c = 0; c < NC; c++) {
        const uint32_t* As = gsm + (c & 1) * GS_TILE;
        const uint32_t* Bs = gsm + 2 * GS_TILE + (c & 1) * GS_TILE;

        float4 pa[4], pb[4];
        if (c + 1 < NC) {
            int kk = (c + 1) * 32;
            #pragma unroll
            for (int i = 0; i < 4; i++) {
                int g = tid + i * 256;
                int row = g >> 3, q = g & 7;
                pa[i] = *(const float4*)&A[(size_t)(m0 + row) * Kd + kk + q * 4];
                pb[i] = *(const float4*)&W[(size_t)(n0b + row) * Kd + kk + q * 4];
            }
        }

        #pragma unroll
        for (int ks = 0; ks < 2; ks++) {
            int kw = ks * 8 + pd;
            uint4 av[4];
            uint2 bv[4];
            #pragma unroll
            for (int t = 0; t < 4; t++) {
                int r = mw * 64 + t * 16 + qd;
                av[t].x = As[r * GS_AS + kw];
                av[t].y = As[(r + 8) * GS_AS + kw];
                av[t].z = As[r * GS_AS + kw + 4];
                av[t].w = As[(r + 8) * GS_AS + kw + 4];
            }
            #pragma unroll
            for (int u = 0; u < 4; u++) {
                int cl = nw * 32 + u * 8 + qd;
                bv[u].x = Bs[cl * GS_AS + kw];
                bv[u].y = Bs[cl * GS_AS + kw + 4];
            }
            #pragma unroll
            for (int t = 0; t < 4; t++)
                #pragma unroll
                for (int u = 0; u < 4; u++)
                    mma_f16(acc[t][u], av[t], bv[u]);
        }

        if (c + 1 < NC) {
            __syncthreads();
            uint32_t* Ad = gsm + ((c + 1) & 1) * GS_TILE;
            uint32_t* Bd = gsm + 2 * GS_TILE + ((c + 1) & 1) * GS_TILE;
            #pragma unroll
            for (int i = 0; i < 4; i++) {
                int g = tid + i * 256;
                int row = g >> 3, q = g & 7;
                *(uint2*)&Ad[row * GS_AS + q * 2] =
                    make_uint2(h2u(pa[i].x, pa[i].y), h2u(pa[i].z, pa[i].w));
                *(uint2*)&Bd[row * GS_AS + q * 2] =
                    make_uint2(h2u(pb[i].x, pb[i].y), h2u(pb[i].z, pb[i].w));
            }
            __syncthreads();
        }
    }

    #pragma unroll
    for (int t = 0; t < 4; t++) {
        int r0 = m0 + mw * 64 + t * 16 + qd;
        #pragma unroll
        for (int u = 0; u < 4; u++) {
            int col = n0b + nw * 32 + u * 8 + pd * 2;
            float v0 = acc[t][u][0], v1 = acc[t][u][1];
            float v2 = acc[t][u][2], v3 = acc[t][u][3];
            if (Ch) {   // fp16 out, scaled
                *(uint32_t*)&Ch[(size_t)r0 * DM + col] = h2u(v0 * outScale, v1 * outScale);
                *(uint32_t*)&Ch[(size_t)(r0 + 8) * DM + col] = h2u(v2 * outScale, v3 * outScale);
            } else {
                if (sigmoidFlag) {
                    v0 = 1.f / (1.f + __expf(-v0));
                    v1 = 1.f / (1.f + __expf(-v1));
                    v2 = 1.f / (1.f + __expf(-v2));
                    v3 = 1.f / (1.f + __expf(-v3));
                }
                *(float2*)&Cf[(size_t)r0 * DM + col]       = make_float2(v0, v1);
                *(float2*)&Cf[(size_t)(r0 + 8) * DM + col] = make_float2(v2, v3);
            }
        }
    }
}

// ---------------- conv weight prep: W'[tap][192][72 halves], zero-padded ----------
__global__ void wprep_kernel(const float* __restrict__ w3, const float* __restrict__ w5,
                             const float* __restrict__ w7) {
    int idx = blockIdx.x * 256 + threadIdx.x;
    if (idx >= 7 * 192 * 72) return;
    int t = idx / (192 * 72);
    int rem = idx % (192 * 72);
    int c = rem / 72;
    int i = rem % 72;
    float v = 0.f;
    if (i < 64) {
        if (c < 64)       { if (t >= 2 && t <= 4) v = w3[(c * 64 + i) * 3 + (t - 2)]; }
        else if (c < 128) { int cc = c - 64; if (t >= 1 && t <= 5) v = w5[(cc * 64 + i) * 5 + (t - 1)]; }
        else              { int cc = c - 128; v = w7[(cc * 64 + i) * 7 + t]; }
    }
    ((__half*)g_wh)[idx] = __float2half_rn(v);
}

// ---------------- multi-scale conv as fp16 HMMA; weights read from L2 -------------
// block = 64 positions x 192 channels; 8 warps 2m x 4n (warp 32x48)
#define CXR 70                  // 64 + 6 halo rows
#define CXS 36                  // words per xv row (64 halves + pad)
#define CONV_SMEM (CXR * CXS * 4)   // 10080 B

__global__ void __launch_bounds__(256) conv_kernel(
    const float* __restrict__ xv, const float* __restrict__ b3,
    const float* __restrict__ b5, const float* __restrict__ b7) {
    extern __shared__ uint32_t csm[];
    uint32_t* xvs = csm;               // [70][36 words] halo tile fp16
    int blk = blockIdx.x;
    int b = blk >> 3;
    int s0 = (blk & 7) * 64;
    int tid = threadIdx.x;
    int lane = tid & 31, wid = tid >> 5;
    int mw = wid & 1, nw = wid >> 1;
    int qd = lane >> 2, pd = lane & 3;

    // stage xv tile (rows s0-3 .. s0+66), fp16, zero outside sequence
    for (int g = tid; g < CXR * 16; g += 256) {
        int row = g >> 4, c4 = g & 15;
        int s = s0 - 3 + row;
        float4 v = make_float4(0.f, 0.f, 0.f, 0.f);
        if (s >= 0 && s < MN) v = *(const float4*)&xv[((size_t)b * MN + s) * VD + c4 * 4];
        *(uint2*)&xvs[row * CXS + c4 * 2] = make_uint2(h2u(v.x, v.y), h2u(v.z, v.w));
    }
    __syncthreads();

    float acc[2][6][4];
    #pragma unroll
    for (int t = 0; t < 2; t++)
        #pragma unroll
        for (int u = 0; u < 6; u++)
            #pragma unroll
            for (int j = 0; j < 4; j++) acc[t][u][j] = 0.f;

    #pragma unroll
    for (int tp = 0; tp < 7; tp++) {
        const int abase = (tp >= 2 && tp <= 4) ? 0 : ((tp == 1 || tp == 5) ? 64 : 128);
        #pragma unroll
        for (int ks = 0; ks < 4; ks++) {
            uint2 bv[6];
            #pragma unroll
            for (int u = 0; u < 6; u++) {
                int c0 = nw * 48 + u * 8;
                if (c0 >= abase) {
                    int gi = (tp * 192 + c0 + qd) * 36 + ks * 8 + pd;
                    bv[u].x = __ldg(&g_wh[gi]);
                    bv[u].y = __ldg(&g_wh[gi + 4]);
                }
            }
            uint4 av[2];
            #pragma unroll
            for (int t = 0; t < 2; t++) {
                int r = mw * 32 + t * 16 + qd + tp;
                av[t].x = xvs[r * CXS + ks * 8 + pd];
                av[t].z = xvs[r * CXS + ks * 8 + pd + 4];
                av[t].y = xvs[(r + 8) * CXS + ks * 8 + pd];
                av[t].w = xvs[(r + 8) * CXS + ks * 8 + pd + 4];
            }
            #pragma unroll
            for (int u = 0; u < 6; u++) {
                int c0 = nw * 48 + u * 8;
                if (c0 >= abase) {
                    #pragma unroll
                    for (int t = 0; t < 2; t++)
                        mma_f16(acc[t][u], av[t], bv[u]);
                }
            }
        }
    }

    // epilogue: add per-scale bias, write g_xm float
    #pragma unroll
    for (int t = 0; t < 2; t++) {
        int s = s0 + mw * 32 + t * 16 + qd;
        #pragma unroll
        for (int u = 0; u < 6; u++) {
            int col = nw * 48 + u * 8 + pd * 2;
            float bb0 = col < 64 ? b3[col] : (col < 128 ? b5[col - 64] : b7[col - 128]);
            int c1 = col + 1;
            float bb1 = c1 < 64 ? b3[c1] : (c1 < 128 ? b5[c1 - 64] : b7[c1 - 128]);
            *(float2*)&g_xm[((size_t)b * MN + s) * D3 + col] =
                make_float2(acc[t][u][0] + bb0, acc[t][u][1] + bb1);
            *(float2*)&g_xm[((size_t)b * MN + s + 8) * D3 + col] =
                make_float2(acc[t][u][2] + bb0, acc[t][u][3] + bb1);
        }
    }
}

// ---------------- pos_sum[j,d] = sum_i emb[clip(j-i,-30,30)+30, d] ----------------
__global__ void possum_kernel(const float* __restrict__ emb) {
    int j = blockIdx.x;
    int d = threadIdx.x;   // 192 threads
    float acc = 0.f;
    #pragma unroll
    for (int delta = -29; delta <= 29; delta++) {
        int i = j - delta;
        if (i >= 0 && i < MN) acc += emb[(delta + 30) * D3 + d];
    }
    int cpos = j - 29;
    if (cpos > 0) acc += (float)cpos * emb[60 * D3 + d];
    int cneg = 482 - j;
    if (cneg > 0) acc += (float)cneg * emb[0 * D3 + d];
    g_pos_sum[j * D3 + d] = acc;
}

// ---------------- rel-pos encoding (closed form, elementwise) ----------------------
__global__ void pe_kernel(const float* __restrict__ emb,
                          const float* __restrict__ dww, const float* __restrict__ dwb) {
    int idx = blockIdx.x * 256 + threadIdx.x;
    if (idx >= BB * MN * D3) return;
    int d = idx % D3;
    int j = (idx / D3) & (MN - 1);
    float xc = g_xm[idx];
    float fC = xc + emb[30 * D3 + d];
    float fL = 0.f, fR = 0.f;
    if (j > 0)      fL = g_xm[idx - D3] + emb[29 * D3 + d];
    if (j < MN - 1) fR = g_xm[idx + D3] + emb[31 * D3 + d];
    float diag = fL * dww[d * 3 + 0] + fC * dww[d * 3 + 1] + fR * dww[d * 3 + 2] + dwb[d];
    g_pe[idx] = xc + (g_pos_sum[j * D3 + d] - fC + diag) * (1.0f / (float)MN);
}

// ---------------- attention on fp16 m16n8k16: Q/K/V already fp16 ------------------
#define AK_STRIDE 20    // words per K row
#define AV_STRIDE 260   // words per VT row
#define ATT_SMEM ((MN * AK_STRIDE + DK * AV_STRIDE) * 4)   // 74240 B

__global__ void __launch_bounds__(256, 2) attn_kernel() {
    extern __shared__ uint32_t ash[];
    uint32_t* Ks = ash;                    // [512][20 words]
    uint32_t* VT = ash + MN * AK_STRIDE;   // [32][260 words]
    int blk = blockIdx.x;                  // b*32 + h*4 + qblk
    int qblk = blk & 3;
    int h = (blk >> 2) & 7;
    int b = blk >> 5;
    int tid = threadIdx.x;
    int lane = tid & 31, wid = tid >> 5;
    int qd = lane >> 2, pd = lane & 3;

    // ---- stage K (pure copy) ----
    const __half* Kg = g_Kh + (size_t)b * MN * DM + h * DK;
    for (int i = tid; i < MN * 4; i += 256) {
        int s = i >> 2, c8 = i & 3;
        uint4 kv = *(const uint4*)&Kg[(size_t)s * DM + c8 * 8];
        *(uint4*)&Ks[s * AK_STRIDE + c8 * 4] = kv;
    }
    // ---- stage V transposed: half repacking with bit ops ----
    const __half* Vg = g_Vh + (size_t)b * MN * DM + h * DK;
    for (int g = tid; g < 1024; g += 256) {
        int spair = g >> 2, q = g & 3;
        int s = spair * 2;
        uint4 a = *(const uint4*)&Vg[(size_t)s * DM + q * 8];
        uint4 bq = *(const uint4*)&Vg[(size_t)(s + 1) * DM + q * 8];
        int d0 = q * 8;
        VT[(d0 + 0) * AV_STRIDE + spair] = (a.x & 0xFFFFu) | (bq.x << 16);
        VT[(d0 + 1) * AV_STRIDE + spair] = (a.x >> 16) | (bq.x & 0xFFFF0000u);
        VT[(d0 + 2) * AV_STRIDE + spair] = (a.y & 0xFFFFu) | (bq.y << 16);
        VT[(d0 + 3) * AV_STRIDE + spair] = (a.y >> 16) | (bq.y & 0xFFFF0000u);
        VT[(d0 + 4) * AV_STRIDE + spair] = (a.z & 0xFFFFu) | (bq.z << 16);
        VT[(d0 + 5) * AV_STRIDE + spair] = (a.z >> 16) | (bq.z & 0xFFFF0000u);
        VT[(d0 + 6) * AV_STRIDE + spair] = (a.w & 0xFFFFu) | (bq.w << 16);
        VT[(d0 + 7) * AV_STRIDE + spair] = (a.w >> 16) | (bq.w & 0xFFFF0000u);
    }
    __syncthreads();

    // ---- Q fragments (pre-scaled fp16 in gmem: raw loads) ----
    int m0 = qblk * 256 + wid * 32;
    const __half* Qg = g_Qh + ((size_t)b * LL + m0) * DM + h * DK;
    uint4 aq[2][2];
    #pragma unroll
    for (int t = 0; t < 2; t++)
        #pragma unroll
        for (int ks = 0; ks < 2; ks++) {
            int r = t * 16 + qd;
            int c = ks * 16 + pd * 2;
            aq[t][ks].x = *(const uint32_t*)&Qg[(size_t)r * DM + c];
            aq[t][ks].y = *(const uint32_t*)&Qg[(size_t)(r + 8) * DM + c];
            aq[t][ks].z = *(const uint32_t*)&Qg[(size_t)r * DM + c + 8];
            aq[t][ks].w = *(const uint32_t*)&Qg[(size_t)(r + 8) * DM + c + 8];
        }

    float o[2][4][4];
    #pragma unroll
    for (int t = 0; t < 2; t++)
        #pragma unroll
        for (int nv = 0; nv < 4; nv++)
            #pragma unroll
            for (int j = 0; j < 4; j++) o[t][nv][j] = 0.f;
    float rs[2][2] = {{0.f, 0.f}, {0.f, 0.f}};

    for (int s0 = 0; s0 < MN; s0 += 16) {
        uint2 bk[2][2];
        #pragma unroll
        for (int n = 0; n < 2; n++)
            #pragma unroll
            for (int ks = 0; ks < 2; ks++) {
                int w = (s0 + n * 8 + qd) * AK_STRIDE + ks * 8 + pd;
                bk[n][ks] = make_uint2(Ks[w], Ks[w + 4]);
            }

        float c[2][2][4];
        #pragma unroll
        for (int t = 0; t < 2; t++)
            #pragma unroll
            for (int n = 0; n < 2; n++) {
                #pragma unroll
                for (int j = 0; j < 4; j++) c[t][n][j] = 0.f;
                #pragma unroll
                for (int ks = 0; ks < 2; ks++)
                    mma_f16(c[t][n], aq[t][ks], bk[n][ks]);
            }

        uint4 ap[2];
        #pragma unroll
        for (int t = 0; t < 2; t++) {
            float p00 = __expf(c[t][0][0]), p01 = __expf(c[t][0][1]);
            float p02 = __expf(c[t][0][2]), p03 = __expf(c[t][0][3]);
            float p10 = __expf(c[t][1][0]), p11 = __expf(c[t][1][1]);
            float p12 = __expf(c[t][1][2]), p13 = __expf(c[t][1][3]);
            rs[t][0] += p00 + p01 + p10 + p11;
            rs[t][1] += p02 + p03 + p12 + p13;
            ap[t] = make_uint4(h2u(p00, p01), h2u(p02, p03),
                               h2u(p10, p11), h2u(p12, p13));
        }

        uint2 bv[4];
        #pragma unroll
        for (int nv = 0; nv < 4; nv++) {
            int w = (nv * 8 + qd) * AV_STRIDE + (s0 >> 1) + pd;
            bv[nv] = make_uint2(VT[w], VT[w + 4]);
        }

        #pragma unroll
        for (int t = 0; t < 2; t++)
            #pragma unroll
            for (int nv = 0; nv < 4; nv++)
                mma_f16(o[t][nv], ap[t], bv[nv]);
    }

    // ---- rowsum reduce, normalize, store fp16 ----
    __half* Ah = g_attnh;
    #pragma unroll
    for (int t = 0; t < 2; t++) {
        #pragma unroll
        for (int r = 0; r < 2; r++) {
            rs[t][r] += __shfl_xor_sync(0xFFFFFFFFu, rs[t][r], 1);
            rs[t][r] += __shfl_xor_sync(0xFFFFFFFFu, rs[t][r], 2);
        }
        float inv0 = 1.f / rs[t][0];
        float inv1 = 1.f / rs[t][1];
        int r0 = m0 + t * 16 + qd;
        #pragma unroll
        for (int nv = 0; nv < 4; nv++) {
            int col = h * DK + nv * 8 + pd * 2;
            *(uint32_t*)&Ah[((size_t)b * LL + r0) * DM + col] =
                h2u(o[t][nv][0] * inv0, o[t][nv][1] * inv0);
            *(uint32_t*)&Ah[((size_t)b * LL + r0 + 8) * DM + col] =
                h2u(o[t][nv][2] * inv1, o[t][nv][3] * inv1);
        }
    }
}

// ---------------- fc GEMM fused with gate + residual + LayerNorm ------------------
// block = 64 rows x 256 cols; 8 warps 2m x 4n (warp 32x64); A already fp16
#define FA_TILE (64 * GS_AS)     // 1280 words
#define FB_TILE (256 * GS_AS)    // 5120 words
#define FSM_BYTES ((2 * FA_TILE + 2 * FB_TILE + 512) * 4)   // 53248 B

__global__ void __launch_bounds__(256, 1) fcln_kernel(
    const float* __restrict__ Wf, const float* __restrict__ fb,
    const float* __restrict__ xs, const float* __restrict__ lnw,
    const float* __restrict__ lnb, float* __restrict__ out) {
    extern __shared__ uint32_t fsm[];
    float* red = (float*)(fsm + 2 * FA_TILE + 2 * FB_TILE);
    const __half* A = g_attnh;
    int tid = threadIdx.x;
    int lane = tid & 31, wid = tid >> 5;
    int mw = wid & 1, nw = wid >> 1;
    int qd = lane >> 2, pd = lane & 3;
    int row0 = blockIdx.x * 64;
    int b = row0 >> 10;
    const int NC = 8;   // K = 256

    float acc[2][8][4];
    #pragma unroll
    for (int t = 0; t < 2; t++)
        #pragma unroll
        for (int u = 0; u < 8; u++)
            #pragma unroll
            for (int j = 0; j < 4; j++) acc[t][u][j] = 0.f;

    {
        uint32_t* Ad = fsm;
        uint32_t* Bd = fsm + 2 * FA_TILE;
        #pragma unroll
        for (int i = 0; i < 10; i++) {
            int g = tid + i * 256;
            if (g < 512) {
                int row = g >> 3, q = g & 7;
                uint2 v = *(const uint2*)&A[(size_t)(row0 + row) * DM + q * 4];
                *(uint2*)&Ad[row * GS_AS + q * 2] = v;
            } else {
                int j = g - 512;
                int row = j >> 3, q = j & 7;
                float4 v = *(const float4*)&Wf[(size_t)row * DM + q * 4];
                *(uint2*)&Bd[row * GS_AS + q * 2] = make_uint2(h2u(v.x, v.y), h2u(v.z, v.w));
            }
        }
    }
    __syncthreads();

    for (int c = 0; c < NC; c++) {
        const uint32_t* As = fsm + (c & 1) * FA_TILE;
        const uint32_t* Bs = fsm + 2 * FA_TILE + (c & 1) * FB_TILE;

        uint2 pah[2];
        float4 pbf[8];
        if (c + 1 < NC) {
            int kk = (c + 1) * 32;
            #pragma unroll
            for (int i = 0; i < 2; i++) {
                int g = tid + i * 256;
                int row = g >> 3, q = g & 7;
                pah[i] = *(const uint2*)&A[(size_t)(row0 + row) * DM + kk + q * 4];
            }
            #pragma unroll
            for (int i = 2; i < 10; i++) {
                int j = tid + i * 256 - 512;
                int row = j >> 3, q = j & 7;
                pbf[i - 2] = *(const float4*)&Wf[(size_t)row * DM + kk + q * 4];
            }
        }

        #pragma unroll
        for (int ks = 0; ks < 2; ks++) {
            int kw = ks * 8 + pd;
            uint4 av[2];
            uint2 bv[8];
            #pragma unroll
            for (int t = 0; t < 2; t++) {
                int r = mw * 32 + t * 16 + qd;
                av[t].x = As[r * GS_AS + kw];
                av[t].y = As[(r + 8) * GS_AS + kw];
                av[t].z = As[r * GS_AS + kw + 4];
                av[t].w = As[(r + 8) * GS_AS + kw + 4];
            }
            #pragma unroll
            for (int u = 0; u < 8; u++) {
                int cl = nw * 64 + u * 8 + qd;
                bv[u].x = Bs[cl * GS_AS + kw];
                bv[u].y = Bs[cl * GS_AS + kw + 4];
            }
            #pragma unroll
            for (int t = 0; t < 2; t++)
                #pragma unroll
                for (int u = 0; u < 8; u++)
                    mma_f16(acc[t][u], av[t], bv[u]);
        }

        if (c + 1 < NC) {
            __syncthreads();
            uint32_t* Ad = fsm + ((c + 1) & 1) * FA_TILE;
            uint32_t* Bd = fsm + 2 * FA_TILE + ((c + 1) & 1) * FB_TILE;
            #pragma unroll
            for (int i = 0; i < 2; i++) {
                int g = tid + i * 256;
                int row = g >> 3, q = g & 7;
                *(uint2*)&Ad[row * GS_AS + q * 2] = pah[i];
            }
            #pragma unroll
            for (int i = 2; i < 10; i++) {
                int j = tid + i * 256 - 512;
                int row = j >> 3, q = j & 7;
                *(uint2*)&Bd[row * GS_AS + q * 2] =
                    make_uint2(h2u(pbf[i - 2].x, pbf[i - 2].y), h2u(pbf[i - 2].z, pbf[i - 2].w));
            }
            __syncthreads();
        }
    }

    // ---- epilogue: v = xs + gamma * (fc + bias); LayerNorm over 256 cols ----
    __syncthreads();   // staging buffers done; red region free
    #pragma unroll
    for (int t = 0; t < 2; t++) {
        #pragma unroll
        for (int hf = 0; hf < 2; hf++) {
            int lr = mw * 32 + t * 16 + qd + hf * 8;
            int r = row0 + lr;
            int l = r & 1023;
            const float* gam = g_gamma + ((size_t)b * MN + (l & (MN - 1))) * DM;
            const float* xr = xs + (size_t)r * DM;
            float s1 = 0.f, s2 = 0.f;
            #pragma unroll
            for (int u = 0; u < 8; u++) {
                int col = nw * 64 + u * 8 + pd * 2;
                int j0 = hf * 2;
                float v0 = xr[col] + gam[col] * (acc[t][u][j0] + fb[col]);
                float v1 = xr[col + 1] + gam[col + 1] * (acc[t][u][j0 + 1] + fb[col + 1]);
                acc[t][u][j0] = v0;
                acc[t][u][j0 + 1] = v1;
                s1 += v0 + v1;
                s2 += v0 * v0 + v1 * v1;
            }
            s1 += __shfl_xor_sync(0xFFFFFFFFu, s1, 1);
            s1 += __shfl_xor_sync(0xFFFFFFFFu, s1, 2);
            s2 += __shfl_xor_sync(0xFFFFFFFFu, s2, 1);
            s2 += __shfl_xor_sync(0xFFFFFFFFu, s2, 2);
            if (pd == 0) {
                red[nw * 64 + lr] = s1;
                red[256 + nw * 64 + lr] = s2;
            }
        }
    }
    __syncthreads();
    #pragma unroll
    for (int t = 0; t < 2; t++) {
        #pragma unroll
        for (int hf = 0; hf < 2; hf++) {
            int lr = mw * 32 + t * 16 + qd + hf * 8;
            int r = row0 + lr;
            float t1 = red[lr] + red[64 + lr] + red[128 + lr] + red[192 + lr];
            float t2 = red[256 + lr] + red[320 + lr] + red[384 + lr] + red[448 + lr];
            float mu = t1 * (1.f / 256.f);
            float var = t2 * (1.f / 256.f) - mu * mu;
            float rstd = rsqrtf(var + 1e-5f);
            #pragma unroll
            for (int u = 0; u < 8; u++) {
                int col = nw * 64 + u * 8 + pd * 2;
                int j0 = hf * 2;
                float v0 = (acc[t][u][j0] - mu) * rstd * lnw[col] + lnb[col];
                float v1 = (acc[t][u][j0 + 1] - mu) * rstd * lnw[col + 1] + lnb[col + 1];
                *(float2*)&out[(size_t)r * DM + col] = make_float2(v0, v1);
            }
        }
    }
}

// ---------------- launch -----------------------------------------------------------
extern "C" void kernel_launch(void* const* d_in, const int* in_sizes, int n_in,
                              void* d_out, int out_size) {
    const float* x_spatial  = (const float*)d_in[0];
    const float* x_velocity = (const float*)d_in[1];
    const float* Wg    = (const float*)d_in[2];
    const float* ms_w3 = (const float*)d_in[3];
    const float* ms_b3 = (const float*)d_in[4];
    const float* ms_w5 = (const float*)d_in[5];
    const float* ms_b5 = (const float*)d_in[6];
    const float* ms_w7 = (const float*)d_in[7];
    const float* ms_b7 = (const float*)d_in[8];
    const float* rel_emb = (const float*)d_in[9];
    const float* dw_w  = (const float*)d_in[10];
    const float* dw_b  = (const float*)d_in[11];
    const float* Wq    = (const float*)d_in[12];
    const float* Wk    = (const float*)d_in[13];
    const float* Wv    = (const float*)d_in[14];
    const float* fc_w  = (const float*)d_in[15];
    const float* fc_b  = (const float*)d_in[16];
    const float* ln_w  = (const float*)d_in[17];
    const float* ln_b  = (const float*)d_in[18];
    float* out = (float*)d_out;

    float *p_gamma, *p_pe;
    __half *p_Qh, *p_Kh, *p_Vh;
    cudaGetSymbolAddress((void**)&p_gamma, g_gamma);
    cudaGetSymbolAddress((void**)&p_pe,    g_pe);
    cudaGetSymbolAddress((void**)&p_Qh,    g_Qh);
    cudaGetSymbolAddress((void**)&p_Kh,    g_Kh);
    cudaGetSymbolAddress((void**)&p_Vh,    g_Vh);

    cudaFuncSetAttribute(conv_kernel,  cudaFuncAttributeMaxDynamicSharedMemorySize, CONV_SMEM);
    cudaFuncSetAttribute(attn_kernel,  cudaFuncAttributeMaxDynamicSharedMemorySize, ATT_SMEM);
    cudaFuncSetAttribute(mgemm_kernel, cudaFuncAttributeMaxDynamicSharedMemorySize, GSM_BYTES);
    cudaFuncSetAttribute(fcln_kernel,  cudaFuncAttributeMaxDynamicSharedMemorySize, FSM_BYTES);

    const float sc = 0.17677669529663687f;   // 1/sqrt(32)

    wprep_kernel<<<(7 * 192 * 72 + 255) / 256, 256>>>(ms_w3, ms_w5, ms_w7);
    possum_kernel<<<MN, D3>>>(rel_emb);

    // Gamma = sigmoid(x_velocity @ Wg^T)  (float out; Wg bias-free)
    mgemm_kernel<<<dim3(2, BB * MN / 128), 256, GSM_BYTES>>>(x_velocity, Wg,
                                                             p_gamma, nullptr, VD, 1, 1.f);
    conv_kernel<<<BB * 8, 256, CONV_SMEM>>>(x_velocity, ms_b3, ms_b5, ms_b7);
    pe_kernel<<<(BB * MN * D3 + 255) / 256, 256>>>(rel_emb, dw_w, dw_b);

    // Q / K / V projections -> fp16 (Q pre-scaled by 1/sqrt(dk))
    mgemm_kernel<<<dim3(2, BB * LL / 128), 256, GSM_BYTES>>>(x_spatial, Wq,
                                                             nullptr, p_Qh, SD, 0, sc);
    mgemm_kernel<<<dim3(2, BB * MN / 128), 256, GSM_BYTES>>>(p_pe, Wk,
                                                             nullptr, p_Kh, D3, 0, 1.f);
    mgemm_kernel<<<dim3(2, BB * MN / 128), 256, GSM_BYTES>>>(p_pe, Wv,
                                                             nullptr, p_Vh, D3, 0, 1.f);

    attn_kernel<<<BB * NH * 4, 256, ATT_SMEM>>>();

    fcln_kernel<<<BB * LL / 64, 256, FSM_BYTES>>>(fc_w, fc_b, x_spatial, ln_w, ln_b, out);
}

// round 9
// speedup vs baseline: 6.2504x; 1.2522x over previous
#include <cuda_runtime.h>
#include <cuda_fp16.h>
#include <math.h>
#include <stdint.h>

#define BB 32
#define LL 1024
#define MN 512
#define SD 256
#define VD 64
#define D3 192
#define DM 256
#define NH 8
#define DK 32

// ---------------- scratch (device globals; no allocation allowed) ----------------
__device__ float g_pos_sum[MN * D3];
__device__ float g_gamma[BB * MN * DM];
__device__ float g_xm[BB * MN * D3];
__device__ float g_pe[BB * MN * D3];
__device__ __half g_Qh[BB * LL * DM];
__device__ __half g_Kh[BB * MN * DM];
__device__ __half g_Vh[BB * MN * DM];
__device__ __half g_attnh[BB * LL * DM];
__device__ uint32_t g_wh[7 * 192 * 36];   // conv weights fp16: [tap][192 ch][72 halves]

// ================= fp16 mma helpers (sm_80+ features, base target OK) =============
__device__ __forceinline__ uint32_t h2u(float a, float b) {
    __half2 h = __floats2half2_rn(a, b);
    return *(uint32_t*)&h;
}
__device__ __forceinline__ float ex2f(float x) {
    float r;
    asm("ex2.approx.f32 %0, %1;" : "=f"(r) : "f"(x));
    return r;
}
__device__ __forceinline__ void mma_f16(float* c, uint4 a, uint2 b) {
    asm("mma.sync.aligned.m16n8k16.row.col.f32.f16.f16.f32 "
        "{%0,%1,%2,%3}, {%4,%5,%6,%7}, {%8,%9}, {%0,%1,%2,%3};"
        : "+f"(c[0]), "+f"(c[1]), "+f"(c[2]), "+f"(c[3])
        : "r"(a.x), "r"(a.y), "r"(a.z), "r"(a.w), "r"(b.x), "r"(b.y));
}

// GEMM smem: A/B half tiles, 128 rows x 32 halves, padded to 40 halves (20 words)
#define GS_AS 20
#define GS_TILE (128 * GS_AS)
#define GSM_BYTES (4 * GS_TILE * 4)   // 40960 B

// ---------------- tensor-core GEMM: C[M,256] = A[M,Kd] * W[256,Kd]^T ---------------
__global__ void __launch_bounds__(256, 2) mgemm_kernel(
    const float* __restrict__ A, const float* __restrict__ W,
    float* __restrict__ Cf, __half* __restrict__ Ch,
    int Kd, int sigmoidFlag, float outScale) {
    extern __shared__ uint32_t gsm[];
    int tid = threadIdx.x;
    int lane = tid & 31, wid = tid >> 5;
    int mw = wid & 1, nw = wid >> 1;
    int qd = lane >> 2, pd = lane & 3;
    int m0 = blockIdx.y * 128;
    int n0b = blockIdx.x * 128;
    int NC = Kd >> 5;

    float acc[4][4][4];
    #pragma unroll
    for (int t = 0; t < 4; t++)
        #pragma unroll
        for (int u = 0; u < 4; u++)
            #pragma unroll
            for (int j = 0; j < 4; j++) acc[t][u][j] = 0.f;

    {
        uint32_t* Ad = gsm;
        uint32_t* Bd = gsm + 2 * GS_TILE;
        #pragma unroll
        for (int i = 0; i < 4; i++) {
            int g = tid + i * 256;
            int row = g >> 3, q = g & 7;
            float4 va = *(const float4*)&A[(size_t)(m0 + row) * Kd + q * 4];
            float4 vb = *(const float4*)&W[(size_t)(n0b + row) * Kd + q * 4];
            *(uint2*)&Ad[row * GS_AS + q * 2] = make_uint2(h2u(va.x, va.y), h2u(va.z, va.w));
            *(uint2*)&Bd[row * GS_AS + q * 2] = make_uint2(h2u(vb.x, vb.y), h2u(vb.z, vb.w));
        }
    }
    __syncthreads();

    for (int c = 0; c < NC; c++) {
        const uint32_t* As = gsm + (c & 1) * GS_TILE;
        const uint32_t* Bs = gsm + 2 * GS_TILE + (c & 1) * GS_TILE;

        uint2 pah[4], pbh[4];   // prefetch already converted to half2 (reg-light)
        if (c + 1 < NC) {
            int kk = (c + 1) * 32;
            #pragma unroll
            for (int i = 0; i < 4; i++) {
                int g = tid + i * 256;
                int row = g >> 3, q = g & 7;
                float4 va = *(const float4*)&A[(size_t)(m0 + row) * Kd + kk + q * 4];
                float4 vb = *(const float4*)&W[(size_t)(n0b + row) * Kd + kk + q * 4];
                pah[i] = make_uint2(h2u(va.x, va.y), h2u(va.z, va.w));
                pbh[i] = make_uint2(h2u(vb.x, vb.y), h2u(vb.z, vb.w));
            }
        }

        #pragma unroll
        for (int ks = 0; ks < 2; ks++) {
            int kw = ks * 8 + pd;
            uint4 av[4];
            uint2 bv[4];
            #pragma unroll
            for (int t = 0; t < 4; t++) {
                int r = mw * 64 + t * 16 + qd;
                av[t].x = As[r * GS_AS + kw];
                av[t].y = As[(r + 8) * GS_AS + kw];
                av[t].z = As[r * GS_AS + kw + 4];
                av[t].w = As[(r + 8) * GS_AS + kw + 4];
            }
            #pragma unroll
            for (int u = 0; u < 4; u++) {
                int cl = nw * 32 + u * 8 + qd;
                bv[u].x = Bs[cl * GS_AS + kw];
                bv[u].y = Bs[cl * GS_AS + kw + 4];
            }
            #pragma unroll
            for (int t = 0; t < 4; t++)
                #pragma unroll
                for (int u = 0; u < 4; u++)
                    mma_f16(acc[t][u], av[t], bv[u]);
        }

        if (c + 1 < NC) {
            __syncthreads();
            uint32_t* Ad = gsm + ((c + 1) & 1) * GS_TILE;
            uint32_t* Bd = gsm + 2 * GS_TILE + ((c + 1) & 1) * GS_TILE;
            #pragma unroll
            for (int i = 0; i < 4; i++) {
                int g = tid + i * 256;
                int row = g >> 3, q = g & 7;
                *(uint2*)&Ad[row * GS_AS + q * 2] = pah[i];
                *(uint2*)&Bd[row * GS_AS + q * 2] = pbh[i];
            }
            __syncthreads();
        }
    }

    #pragma unroll
    for (int t = 0; t < 4; t++) {
        int r0 = m0 + mw * 64 + t * 16 + qd;
        #pragma unroll
        for (int u = 0; u < 4; u++) {
            int col = n0b + nw * 32 + u * 8 + pd * 2;
            float v0 = acc[t][u][0], v1 = acc[t][u][1];
            float v2 = acc[t][u][2], v3 = acc[t][u][3];
            if (Ch) {
                *(uint32_t*)&Ch[(size_t)r0 * DM + col] = h2u(v0 * outScale, v1 * outScale);
                *(uint32_t*)&Ch[(size_t)(r0 + 8) * DM + col] = h2u(v2 * outScale, v3 * outScale);
            } else {
                if (sigmoidFlag) {
                    v0 = 1.f / (1.f + __expf(-v0));
                    v1 = 1.f / (1.f + __expf(-v1));
                    v2 = 1.f / (1.f + __expf(-v2));
                    v3 = 1.f / (1.f + __expf(-v3));
                }
                *(float2*)&Cf[(size_t)r0 * DM + col]       = make_float2(v0, v1);
                *(float2*)&Cf[(size_t)(r0 + 8) * DM + col] = make_float2(v2, v3);
            }
        }
    }
}

// ---------------- conv weight prep: W'[tap][192][72 halves], zero-padded ----------
__global__ void wprep_kernel(const float* __restrict__ w3, const float* __restrict__ w5,
                             const float* __restrict__ w7) {
    int idx = blockIdx.x * 256 + threadIdx.x;
    if (idx >= 7 * 192 * 72) return;
    int t = idx / (192 * 72);
    int rem = idx % (192 * 72);
    int c = rem / 72;
    int i = rem % 72;
    float v = 0.f;
    if (i < 64) {
        if (c < 64)       { if (t >= 2 && t <= 4) v = w3[(c * 64 + i) * 3 + (t - 2)]; }
        else if (c < 128) { int cc = c - 64; if (t >= 1 && t <= 5) v = w5[(cc * 64 + i) * 5 + (t - 1)]; }
        else              { int cc = c - 128; v = w7[(cc * 64 + i) * 7 + t]; }
    }
    ((__half*)g_wh)[idx] = __float2half_rn(v);
}

// ---------------- multi-scale conv: 128-thr blocks, weight-frag pipelining --------
// block = 32 positions x 192 channels; 4 warps across n (warp 32x48)
#define CXR2 38                 // 32 + 6 halo rows
#define CXS 36                  // words per xv row (64 halves + pad)
#define CONV_SMEM (CXR2 * CXS * 4)   // 5472 B

__device__ __forceinline__ constexpr int conv_abase(int tp) {
    return (tp >= 2 && tp <= 4) ? 0 : ((tp == 1 || tp == 5) ? 64 : 128);
}

__global__ void __launch_bounds__(128) conv_kernel(
    const float* __restrict__ xv, const float* __restrict__ b3,
    const float* __restrict__ b5, const float* __restrict__ b7) {
    extern __shared__ uint32_t csm[];
    uint32_t* xvs = csm;               // [38][36 words] halo tile fp16
    int blk = blockIdx.x;
    int b = blk >> 4;
    int s0 = (blk & 15) * 32;
    int tid = threadIdx.x;
    int lane = tid & 31, nw = tid >> 5;
    int qd = lane >> 2, pd = lane & 3;

    for (int g = tid; g < CXR2 * 16; g += 128) {
        int row = g >> 4, c4 = g & 15;
        int s = s0 - 3 + row;
        float4 v = make_float4(0.f, 0.f, 0.f, 0.f);
        if (s >= 0 && s < MN) v = *(const float4*)&xv[((size_t)b * MN + s) * VD + c4 * 4];
        *(uint2*)&xvs[row * CXS + c4 * 2] = make_uint2(h2u(v.x, v.y), h2u(v.z, v.w));
    }
    __syncthreads();

    float acc[2][6][4];
    #pragma unroll
    for (int t = 0; t < 2; t++)
        #pragma unroll
        for (int u = 0; u < 6; u++)
            #pragma unroll
            for (int j = 0; j < 4; j++) acc[t][u][j] = 0.f;

    // flat (tap, ks) loop with double-buffered weight fragments
    uint2 bvb[2][6];
    {   // preload step 0: tp=0, ks=0
        const int ab0 = conv_abase(0);
        #pragma unroll
        for (int u = 0; u < 6; u++) {
            int c0 = nw * 48 + u * 8;
            if (c0 >= ab0) {
                int gi = (0 * 192 + c0 + qd) * 36 + 0 * 8 + pd;
                bvb[0][u].x = __ldg(&g_wh[gi]);
                bvb[0][u].y = __ldg(&g_wh[gi + 4]);
            }
        }
    }

    #pragma unroll
    for (int step = 0; step < 28; step++) {
        const int tp = step >> 2, ks = step & 3;
        const int abase = conv_abase(tp);

        // prefetch next step's fragments
        if (step + 1 < 28) {
            const int tp2 = (step + 1) >> 2, ks2 = (step + 1) & 3;
            const int ab2 = conv_abase(tp2);
            #pragma unroll
            for (int u = 0; u < 6; u++) {
                int c0 = nw * 48 + u * 8;
                if (c0 >= ab2) {
                    int gi = (tp2 * 192 + c0 + qd) * 36 + ks2 * 8 + pd;
                    bvb[(step + 1) & 1][u].x = __ldg(&g_wh[gi]);
                    bvb[(step + 1) & 1][u].y = __ldg(&g_wh[gi + 4]);
                }
            }
        }

        uint4 av[2];
        #pragma unroll
        for (int t = 0; t < 2; t++) {
            int r = t * 16 + qd + tp;
            av[t].x = xvs[r * CXS + ks * 8 + pd];
            av[t].z = xvs[r * CXS + ks * 8 + pd + 4];
            av[t].y = xvs[(r + 8) * CXS + ks * 8 + pd];
            av[t].w = xvs[(r + 8) * CXS + ks * 8 + pd + 4];
        }
        #pragma unroll
        for (int u = 0; u < 6; u++) {
            int c0 = nw * 48 + u * 8;
            if (c0 >= abase) {
                #pragma unroll
                for (int t = 0; t < 2; t++)
                    mma_f16(acc[t][u], av[t], bvb[step & 1][u]);
            }
        }
    }

    #pragma unroll
    for (int t = 0; t < 2; t++) {
        int s = s0 + t * 16 + qd;
        #pragma unroll
        for (int u = 0; u < 6; u++) {
            int col = nw * 48 + u * 8 + pd * 2;
            float bb0 = col < 64 ? b3[col] : (col < 128 ? b5[col - 64] : b7[col - 128]);
            int c1 = col + 1;
            float bb1 = c1 < 64 ? b3[c1] : (c1 < 128 ? b5[c1 - 64] : b7[c1 - 128]);
            *(float2*)&g_xm[((size_t)b * MN + s) * D3 + col] =
                make_float2(acc[t][u][0] + bb0, acc[t][u][1] + bb1);
            *(float2*)&g_xm[((size_t)b * MN + s + 8) * D3 + col] =
                make_float2(acc[t][u][2] + bb0, acc[t][u][3] + bb1);
        }
    }
}

// ---------------- pos_sum[j,d] = sum_i emb[clip(j-i,-30,30)+30, d] ----------------
__global__ void possum_kernel(const float* __restrict__ emb) {
    int j = blockIdx.x;
    int d = threadIdx.x;   // 192 threads
    float acc = 0.f;
    #pragma unroll
    for (int delta = -29; delta <= 29; delta++) {
        int i = j - delta;
        if (i >= 0 && i < MN) acc += emb[(delta + 30) * D3 + d];
    }
    int cpos = j - 29;
    if (cpos > 0) acc += (float)cpos * emb[60 * D3 + d];
    int cneg = 482 - j;
    if (cneg > 0) acc += (float)cneg * emb[0 * D3 + d];
    g_pos_sum[j * D3 + d] = acc;
}

// ---------------- rel-pos encoding: one (b,j) row per block, d = threadIdx --------
__global__ void pe_kernel(const float* __restrict__ emb,
                          const float* __restrict__ dww, const float* __restrict__ dwb) {
    int row = blockIdx.x;          // b*MN + j
    int j = row & (MN - 1);
    int d = threadIdx.x;           // 192
    size_t base = (size_t)row * D3 + d;
    float xc = g_xm[base];
    float fC = xc + emb[30 * D3 + d];
    float fL = (j > 0)      ? g_xm[base - D3] + emb[29 * D3 + d] : 0.f;
    float fR = (j < MN - 1) ? g_xm[base + D3] + emb[31 * D3 + d] : 0.f;
    float diag = fL * dww[d * 3 + 0] + fC * dww[d * 3 + 1] + fR * dww[d * 3 + 2] + dwb[d];
    g_pe[base] = xc + (g_pos_sum[j * D3 + d] - fC + diag) * (1.0f / (float)MN);
}

// ---------------- attention on fp16 m16n8k16: Q pre-scaled by log2e/sqrt(dk) ------
#define AK_STRIDE 20
#define AV_STRIDE 260
#define ATT_SMEM ((MN * AK_STRIDE + DK * AV_STRIDE) * 4)   // 74240 B

__global__ void __launch_bounds__(256, 2) attn_kernel() {
    extern __shared__ uint32_t ash[];
    uint32_t* Ks = ash;                    // [512][20 words]
    uint32_t* VT = ash + MN * AK_STRIDE;   // [32][260 words]
    int blk = blockIdx.x;                  // b*32 + h*4 + qblk
    int qblk = blk & 3;
    int h = (blk >> 2) & 7;
    int b = blk >> 5;
    int tid = threadIdx.x;
    int lane = tid & 31, wid = tid >> 5;
    int qd = lane >> 2, pd = lane & 3;

    const __half* Kg = g_Kh + (size_t)b * MN * DM + h * DK;
    for (int i = tid; i < MN * 4; i += 256) {
        int s = i >> 2, c8 = i & 3;
        uint4 kv = *(const uint4*)&Kg[(size_t)s * DM + c8 * 8];
        *(uint4*)&Ks[s * AK_STRIDE + c8 * 4] = kv;
    }
    const __half* Vg = g_Vh + (size_t)b * MN * DM + h * DK;
    for (int g = tid; g < 1024; g += 256) {
        int spair = g >> 2, q = g & 3;
        int s = spair * 2;
        uint4 a = *(const uint4*)&Vg[(size_t)s * DM + q * 8];
        uint4 bq = *(const uint4*)&Vg[(size_t)(s + 1) * DM + q * 8];
        int d0 = q * 8;
        VT[(d0 + 0) * AV_STRIDE + spair] = (a.x & 0xFFFFu) | (bq.x << 16);
        VT[(d0 + 1) * AV_STRIDE + spair] = (a.x >> 16) | (bq.x & 0xFFFF0000u);
        VT[(d0 + 2) * AV_STRIDE + spair] = (a.y & 0xFFFFu) | (bq.y << 16);
        VT[(d0 + 3) * AV_STRIDE + spair] = (a.y >> 16) | (bq.y & 0xFFFF0000u);
        VT[(d0 + 4) * AV_STRIDE + spair] = (a.z & 0xFFFFu) | (bq.z << 16);
        VT[(d0 + 5) * AV_STRIDE + spair] = (a.z >> 16) | (bq.z & 0xFFFF0000u);
        VT[(d0 + 6) * AV_STRIDE + spair] = (a.w & 0xFFFFu) | (bq.w << 16);
        VT[(d0 + 7) * AV_STRIDE + spair] = (a.w >> 16) | (bq.w & 0xFFFF0000u);
    }
    __syncthreads();

    int m0 = qblk * 256 + wid * 32;
    const __half* Qg = g_Qh + ((size_t)b * LL + m0) * DM + h * DK;
    uint4 aq[2][2];
    #pragma unroll
    for (int t = 0; t < 2; t++)
        #pragma unroll
        for (int ks = 0; ks < 2; ks++) {
            int r = t * 16 + qd;
            int c = ks * 16 + pd * 2;
            aq[t][ks].x = *(const uint32_t*)&Qg[(size_t)r * DM + c];
            aq[t][ks].y = *(const uint32_t*)&Qg[(size_t)(r + 8) * DM + c];
            aq[t][ks].z = *(const uint32_t*)&Qg[(size_t)r * DM + c + 8];
            aq[t][ks].w = *(const uint32_t*)&Qg[(size_t)(r + 8) * DM + c + 8];
        }

    float o[2][4][4];
    #pragma unroll
    for (int t = 0; t < 2; t++)
        #pragma unroll
        for (int nv = 0; nv < 4; nv++)
            #pragma unroll
            for (int j = 0; j < 4; j++) o[t][nv][j] = 0.f;
    float rs[2][2] = {{0.f, 0.f}, {0.f, 0.f}};

    for (int s0 = 0; s0 < MN; s0 += 16) {
        uint2 bk[2][2];
        #pragma unroll
        for (int n = 0; n < 2; n++)
            #pragma unroll
            for (int ks = 0; ks < 2; ks++) {
                int w = (s0 + n * 8 + qd) * AK_STRIDE + ks * 8 + pd;
                bk[n][ks] = make_uint2(Ks[w], Ks[w + 4]);
            }

        float c[2][2][4];
        #pragma unroll
        for (int t = 0; t < 2; t++)
            #pragma unroll
            for (int n = 0; n < 2; n++) {
                #pragma unroll
                for (int j = 0; j < 4; j++) c[t][n][j] = 0.f;
                #pragma unroll
                for (int ks = 0; ks < 2; ks++)
                    mma_f16(c[t][n], aq[t][ks], bk[n][ks]);
            }

        // logits already scaled by log2(e): p = 2^x (single MUFU)
        uint4 ap[2];
        #pragma unroll
        for (int t = 0; t < 2; t++) {
            float p00 = ex2f(c[t][0][0]), p01 = ex2f(c[t][0][1]);
            float p02 = ex2f(c[t][0][2]), p03 = ex2f(c[t][0][3]);
            float p10 = ex2f(c[t][1][0]), p11 = ex2f(c[t][1][1]);
            float p12 = ex2f(c[t][1][2]), p13 = ex2f(c[t][1][3]);
            rs[t][0] += p00 + p01 + p10 + p11;
            rs[t][1] += p02 + p03 + p12 + p13;
            ap[t] = make_uint4(h2u(p00, p01), h2u(p02, p03),
                               h2u(p10, p11), h2u(p12, p13));
        }

        uint2 bv[4];
        #pragma unroll
        for (int nv = 0; nv < 4; nv++) {
            int w = (nv * 8 + qd) * AV_STRIDE + (s0 >> 1) + pd;
            bv[nv] = make_uint2(VT[w], VT[w + 4]);
        }

        #pragma unroll
        for (int t = 0; t < 2; t++)
            #pragma unroll
            for (int nv = 0; nv < 4; nv++)
                mma_f16(o[t][nv], ap[t], bv[nv]);
    }

    __half* Ah = g_attnh;
    #pragma unroll
    for (int t = 0; t < 2; t++) {
        #pragma unroll
        for (int r = 0; r < 2; r++) {
            rs[t][r] += __shfl_xor_sync(0xFFFFFFFFu, rs[t][r], 1);
            rs[t][r] += __shfl_xor_sync(0xFFFFFFFFu, rs[t][r], 2);
        }
        float inv0 = 1.f / rs[t][0];
        float inv1 = 1.f / rs[t][1];
        int r0 = m0 + t * 16 + qd;
        #pragma unroll
        for (int nv = 0; nv < 4; nv++) {
            int col = h * DK + nv * 8 + pd * 2;
            *(uint32_t*)&Ah[((size_t)b * LL + r0) * DM + col] =
                h2u(o[t][nv][0] * inv0, o[t][nv][1] * inv0);
            *(uint32_t*)&Ah[((size_t)b * LL + r0 + 8) * DM + col] =
                h2u(o[t][nv][2] * inv1, o[t][nv][3] * inv1);
        }
    }
}

// ---------------- fc GEMM fused with gate + residual + LayerNorm ------------------
#define FA_TILE (64 * GS_AS)
#define FB_TILE (256 * GS_AS)
#define FSM_BYTES ((2 * FA_TILE + 2 * FB_TILE + 512) * 4)   // 53248 B

__global__ void __launch_bounds__(256, 2) fcln_kernel(
    const float* __restrict__ Wf, const float* __restrict__ fb,
    const float* __restrict__ xs, const float* __restrict__ lnw,
    const float* __restrict__ lnb, float* __restrict__ out) {
    extern __shared__ uint32_t fsm[];
    float* red = (float*)(fsm + 2 * FA_TILE + 2 * FB_TILE);
    const __half* A = g_attnh;
    int tid = threadIdx.x;
    int lane = tid & 31, wid = tid >> 5;
    int mw = wid & 1, nw = wid >> 1;
    int qd = lane >> 2, pd = lane & 3;
    int row0 = blockIdx.x * 64;
    int b = row0 >> 10;
    const int NC = 8;

    float acc[2][8][4];
    #pragma unroll
    for (int t = 0; t < 2; t++)
        #pragma unroll
        for (int u = 0; u < 8; u++)
            #pragma unroll
            for (int j = 0; j < 4; j++) acc[t][u][j] = 0.f;

    {
        uint32_t* Ad = fsm;
        uint32_t* Bd = fsm + 2 * FA_TILE;
        #pragma unroll
        for (int i = 0; i < 10; i++) {
            int g = tid + i * 256;
            if (g < 512) {
                int row = g >> 3, q = g & 7;
                uint2 v = *(const uint2*)&A[(size_t)(row0 + row) * DM + q * 4];
                *(uint2*)&Ad[row * GS_AS + q * 2] = v;
            } else {
                int j = g - 512;
                int row = j >> 3, q = j & 7;
                float4 v = *(const float4*)&Wf[(size_t)row * DM + q * 4];
                *(uint2*)&Bd[row * GS_AS + q * 2] = make_uint2(h2u(v.x, v.y), h2u(v.z, v.w));
            }
        }
    }
    __syncthreads();

    for (int c = 0; c < NC; c++) {
        const uint32_t* As = fsm + (c & 1) * FA_TILE;
        const uint32_t* Bs = fsm + 2 * FA_TILE + (c & 1) * FB_TILE;

        uint2 pah[2], pbh[8];
        if (c + 1 < NC) {
            int kk = (c + 1) * 32;
            #pragma unroll
            for (int i = 0; i < 2; i++) {
                int g = tid + i * 256;
                int row = g >> 3, q = g & 7;
                pah[i] = *(const uint2*)&A[(size_t)(row0 + row) * DM + kk + q * 4];
            }
            #pragma unroll
            for (int i = 2; i < 10; i++) {
                int j = tid + i * 256 - 512;
                int row = j >> 3, q = j & 7;
                float4 v = *(const float4*)&Wf[(size_t)row * DM + kk + q * 4];
                pbh[i - 2] = make_uint2(h2u(v.x, v.y), h2u(v.z, v.w));
            }
        }

        #pragma unroll
        for (int ks = 0; ks < 2; ks++) {
            int kw = ks * 8 + pd;
            uint4 av[2];
            uint2 bv[8];
            #pragma unroll
            for (int t = 0; t < 2; t++) {
                int r = mw * 32 + t * 16 + qd;
                av[t].x = As[r * GS_AS + kw];
                av[t].y = As[(r + 8) * GS_AS + kw];
                av[t].z = As[r * GS_AS + kw + 4];
                av[t].w = As[(r + 8) * GS_AS + kw + 4];
            }
            #pragma unroll
            for (int u = 0; u < 8; u++) {
                int cl = nw * 64 + u * 8 + qd;
                bv[u].x = Bs[cl * GS_AS + kw];
                bv[u].y = Bs[cl * GS_AS + kw + 4];
            }
            #pragma unroll
            for (int t = 0; t < 2; t++)
                #pragma unroll
                for (int u = 0; u < 8; u++)
                    mma_f16(acc[t][u], av[t], bv[u]);
        }

        if (c + 1 < NC) {
            __syncthreads();
            uint32_t* Ad = fsm + ((c + 1) & 1) * FA_TILE;
            uint32_t* Bd = fsm + 2 * FA_TILE + ((c + 1) & 1) * FB_TILE;
            #pragma unroll
            for (int i = 0; i < 2; i++) {
                int g = tid + i * 256;
                int row = g >> 3, q = g & 7;
                *(uint2*)&Ad[row * GS_AS + q * 2] = pah[i];
            }
            #pragma unroll
            for (int i = 2; i < 10; i++) {
                int j = tid + i * 256 - 512;
                int row = j >> 3, q = j & 7;
                *(uint2*)&Bd[row * GS_AS + q * 2] = pbh[i - 2];
            }
            __syncthreads();
        }
    }

    __syncthreads();
    #pragma unroll
    for (int t = 0; t < 2; t++) {
        #pragma unroll
        for (int hf = 0; hf < 2; hf++) {
            int lr = mw * 32 + t * 16 + qd + hf * 8;
            int r = row0 + lr;
            int l = r & 1023;
            const float* gam = g_gamma + ((size_t)b * MN + (l & (MN - 1))) * DM;
            const float* xr = xs + (size_t)r * DM;
            float s1 = 0.f, s2 = 0.f;
            #pragma unroll
            for (int u = 0; u < 8; u++) {
                int col = nw * 64 + u * 8 + pd * 2;
                int j0 = hf * 2;
                float v0 = xr[col] + gam[col] * (acc[t][u][j0] + fb[col]);
                float v1 = xr[col + 1] + gam[col + 1] * (acc[t][u][j0 + 1] + fb[col + 1]);
                acc[t][u][j0] = v0;
                acc[t][u][j0 + 1] = v1;
                s1 += v0 + v1;
                s2 += v0 * v0 + v1 * v1;
            }
            s1 += __shfl_xor_sync(0xFFFFFFFFu, s1, 1);
            s1 += __shfl_xor_sync(0xFFFFFFFFu, s1, 2);
            s2 += __shfl_xor_sync(0xFFFFFFFFu, s2, 1);
            s2 += __shfl_xor_sync(0xFFFFFFFFu, s2, 2);
            if (pd == 0) {
                red[nw * 64 + lr] = s1;
                red[256 + nw * 64 + lr] = s2;
            }
        }
    }
    __syncthreads();
    #pragma unroll
    for (int t = 0; t < 2; t++) {
        #pragma unroll
        for (int hf = 0; hf < 2; hf++) {
            int lr = mw * 32 + t * 16 + qd + hf * 8;
            int r = row0 + lr;
            float t1 = red[lr] + red[64 + lr] + red[128 + lr] + red[192 + lr];
            float t2 = red[256 + lr] + red[320 + lr] + red[384 + lr] + red[448 + lr];
            float mu = t1 * (1.f / 256.f);
            float var = t2 * (1.f / 256.f) - mu * mu;
            float rstd = rsqrtf(var + 1e-5f);
            #pragma unroll
            for (int u = 0; u < 8; u++) {
                int col = nw * 64 + u * 8 + pd * 2;
                int j0 = hf * 2;
                float v0 = (acc[t][u][j0] - mu) * rstd * lnw[col] + lnb[col];
                float v1 = (acc[t][u][j0 + 1] - mu) * rstd * lnw[col + 1] + lnb[col + 1];
                *(float2*)&out[(size_t)r * DM + col] = make_float2(v0, v1);
            }
        }
    }
}

// ---------------- launch: fork/join side stream for Q + Gamma ----------------------
extern "C" void kernel_launch(void* const* d_in, const int* in_sizes, int n_in,
                              void* d_out, int out_size) {
    const float* x_spatial  = (const float*)d_in[0];
    const float* x_velocity = (const float*)d_in[1];
    const float* Wg    = (const float*)d_in[2];
    const float* ms_w3 = (const float*)d_in[3];
    const float* ms_b3 = (const float*)d_in[4];
    const float* ms_w5 = (const float*)d_in[5];
    const float* ms_b5 = (const float*)d_in[6];
    const float* ms_w7 = (const float*)d_in[7];
    const float* ms_b7 = (const float*)d_in[8];
    const float* rel_emb = (const float*)d_in[9];
    const float* dw_w  = (const float*)d_in[10];
    const float* dw_b  = (const float*)d_in[11];
    const float* Wq    = (const float*)d_in[12];
    const float* Wk    = (const float*)d_in[13];
    const float* Wv    = (const float*)d_in[14];
    const float* fc_w  = (const float*)d_in[15];
    const float* fc_b  = (const float*)d_in[16];
    const float* ln_w  = (const float*)d_in[17];
    const float* ln_b  = (const float*)d_in[18];
    float* out = (float*)d_out;

    float *p_gamma, *p_pe;
    __half *p_Qh, *p_Kh, *p_Vh;
    cudaGetSymbolAddress((void**)&p_gamma, g_gamma);
    cudaGetSymbolAddress((void**)&p_pe,    g_pe);
    cudaGetSymbolAddress((void**)&p_Qh,    g_Qh);
    cudaGetSymbolAddress((void**)&p_Kh,    g_Kh);
    cudaGetSymbolAddress((void**)&p_Vh,    g_Vh);

    cudaFuncSetAttribute(conv_kernel,  cudaFuncAttributeMaxDynamicSharedMemorySize, CONV_SMEM);
    cudaFuncSetAttribute(attn_kernel,  cudaFuncAttributeMaxDynamicSharedMemorySize, ATT_SMEM);
    cudaFuncSetAttribute(mgemm_kernel, cudaFuncAttributeMaxDynamicSharedMemorySize, GSM_BYTES);
    cudaFuncSetAttribute(fcln_kernel,  cudaFuncAttributeMaxDynamicSharedMemorySize, FSM_BYTES);

    // side stream + fork/join events (created once; no device memory involved)
    static cudaStream_t s_side = nullptr;
    static cudaEvent_t ev_fork = nullptr, ev_join = nullptr;
    if (s_side == nullptr) {
        cudaStreamCreateWithFlags(&s_side, cudaStreamNonBlocking);
        cudaEventCreateWithFlags(&ev_fork, cudaEventDisableTiming);
        cudaEventCreateWithFlags(&ev_join, cudaEventDisableTiming);
    }

    // log2(e)/sqrt(dk): attention uses p = 2^x
    const float qsc = 0.17677669529663687f * 1.4426950408889634f;

    wprep_kernel<<<(7 * 192 * 72 + 255) / 256, 256>>>(ms_w3, ms_w5, ms_w7);
    possum_kernel<<<MN, D3>>>(rel_emb);

    // fork: Q projection + Gamma on side stream (independent of conv/pe chain)
    cudaEventRecord(ev_fork, 0);
    cudaStreamWaitEvent(s_side, ev_fork, 0);
    mgemm_kernel<<<dim3(2, BB * LL / 128), 256, GSM_BYTES, s_side>>>(
        x_spatial, Wq, nullptr, p_Qh, SD, 0, qsc);
    mgemm_kernel<<<dim3(2, BB * MN / 128), 256, GSM_BYTES, s_side>>>(
        x_velocity, Wg, p_gamma, nullptr, VD, 1, 1.f);
    cudaEventRecord(ev_join, s_side);

    // main chain: conv -> pe -> K/V
    conv_kernel<<<BB * 16, 128, CONV_SMEM>>>(x_velocity, ms_b3, ms_b5, ms_b7);
    pe_kernel<<<BB * MN, D3>>>(rel_emb, dw_w, dw_b);
    mgemm_kernel<<<dim3(2, BB * MN / 128), 256, GSM_BYTES>>>(p_pe, Wk,
                                                             nullptr, p_Kh, D3, 0, 1.f);
    mgemm_kernel<<<dim3(2, BB * MN / 128), 256, GSM_BYTES>>>(p_pe, Wv,
                                                             nullptr, p_Vh, D3, 0, 1.f);

    // join: attention needs Q (side) + K/V (main); fcln needs gamma (side) + attn
    cudaStreamWaitEvent(0, ev_join, 0);
    attn_kernel<<<BB * NH * 4, 256, ATT_SMEM>>>();
    fcln_kernel<<<BB * LL / 64, 256, FSM_BYTES>>>(fc_w, fc_b, x_spatial, ln_w, ln_b, out);
}

// round 10
// speedup vs baseline: 6.4121x; 1.0259x over previous
#include <cuda_runtime.h>
#include <cuda_fp16.h>
#include <math.h>
#include <stdint.h>

#define BB 32
#define LL 1024
#define MN 512
#define SD 256
#define VD 64
#define D3 192
#define DM 256
#define NH 8
#define DK 32

// ---------------- scratch (device globals; no allocation allowed) ----------------
__device__ float g_pos_sum[MN * D3];
__device__ float g_gamma[BB * MN * DM];
__device__ float g_xm[BB * MN * D3];
__device__ __half g_peh[BB * MN * D3];
__device__ __half g_Qh[BB * LL * DM];
__device__ __half g_Kh[BB * MN * DM];
__device__ __half g_Vh[BB * MN * DM];
__device__ __half g_attnh[BB * LL * DM];
__device__ __half g_Wkh[DM * D3];
__device__ __half g_Wvh[DM * D3];
__device__ __half g_Wfh[DM * DM];
__device__ uint32_t g_wh[7 * 192 * 36];   // conv weights fp16: [tap][192 ch][72 halves]

// ================= fp16 mma helpers (sm_80+ features, base target OK) =============
__device__ __forceinline__ uint32_t h2u(float a, float b) {
    __half2 h = __floats2half2_rn(a, b);
    return *(uint32_t*)&h;
}
__device__ __forceinline__ float ex2f(float x) {
    float r;
    asm("ex2.approx.f32 %0, %1;" : "=f"(r) : "f"(x));
    return r;
}
__device__ __forceinline__ void mma_f16(float* c, uint4 a, uint2 b) {
    asm("mma.sync.aligned.m16n8k16.row.col.f32.f16.f16.f32 "
        "{%0,%1,%2,%3}, {%4,%5,%6,%7}, {%8,%9}, {%0,%1,%2,%3};"
        : "+f"(c[0]), "+f"(c[1]), "+f"(c[2]), "+f"(c[3])
        : "r"(a.x), "r"(a.y), "r"(a.z), "r"(a.w), "r"(b.x), "r"(b.y));
}

// GEMM smem: A/B half tiles, 128 rows x 32 halves, padded to 40 halves (20 words)
#define GS_AS 20
#define GS_TILE (128 * GS_AS)
#define GSM_BYTES (4 * GS_TILE * 4)   // 40960 B

// ---------------- float-input GEMM (Q / Gamma; runs on side stream) ----------------
__global__ void __launch_bounds__(256, 2) mgemm_kernel(
    const float* __restrict__ A, const float* __restrict__ W,
    float* __restrict__ Cf, __half* __restrict__ Ch,
    int Kd, int sigmoidFlag, float outScale) {
    extern __shared__ uint32_t gsm[];
    int tid = threadIdx.x;
    int lane = tid & 31, wid = tid >> 5;
    int mw = wid & 1, nw = wid >> 1;
    int qd = lane >> 2, pd = lane & 3;
    int m0 = blockIdx.y * 128;
    int n0b = blockIdx.x * 128;
    int NC = Kd >> 5;

    float acc[4][4][4];
    #pragma unroll
    for (int t = 0; t < 4; t++)
        #pragma unroll
        for (int u = 0; u < 4; u++)
            #pragma unroll
            for (int j = 0; j < 4; j++) acc[t][u][j] = 0.f;

    {
        uint32_t* Ad = gsm;
        uint32_t* Bd = gsm + 2 * GS_TILE;
        #pragma unroll
        for (int i = 0; i < 4; i++) {
            int g = tid + i * 256;
            int row = g >> 3, q = g & 7;
            float4 va = *(const float4*)&A[(size_t)(m0 + row) * Kd + q * 4];
            float4 vb = *(const float4*)&W[(size_t)(n0b + row) * Kd + q * 4];
            *(uint2*)&Ad[row * GS_AS + q * 2] = make_uint2(h2u(va.x, va.y), h2u(va.z, va.w));
            *(uint2*)&Bd[row * GS_AS + q * 2] = make_uint2(h2u(vb.x, vb.y), h2u(vb.z, vb.w));
        }
    }
    __syncthreads();

    for (int c = 0; c < NC; c++) {
        const uint32_t* As = gsm + (c & 1) * GS_TILE;
        const uint32_t* Bs = gsm + 2 * GS_TILE + (c & 1) * GS_TILE;

        uint2 pah[4], pbh[4];
        if (c + 1 < NC) {
            int kk = (c + 1) * 32;
            #pragma unroll
            for (int i = 0; i < 4; i++) {
                int g = tid + i * 256;
                int row = g >> 3, q = g & 7;
                float4 va = *(const float4*)&A[(size_t)(m0 + row) * Kd + kk + q * 4];
                float4 vb = *(const float4*)&W[(size_t)(n0b + row) * Kd + kk + q * 4];
                pah[i] = make_uint2(h2u(va.x, va.y), h2u(va.z, va.w));
                pbh[i] = make_uint2(h2u(vb.x, vb.y), h2u(vb.z, vb.w));
            }
        }

        #pragma unroll
        for (int ks = 0; ks < 2; ks++) {
            int kw = ks * 8 + pd;
            uint4 av[4];
            uint2 bv[4];
            #pragma unroll
            for (int t = 0; t < 4; t++) {
                int r = mw * 64 + t * 16 + qd;
                av[t].x = As[r * GS_AS + kw];
                av[t].y = As[(r + 8) * GS_AS + kw];
                av[t].z = As[r * GS_AS + kw + 4];
                av[t].w = As[(r + 8) * GS_AS + kw + 4];
            }
            #pragma unroll
            for (int u = 0; u < 4; u++) {
                int cl = nw * 32 + u * 8 + qd;
                bv[u].x = Bs[cl * GS_AS + kw];
                bv[u].y = Bs[cl * GS_AS + kw + 4];
            }
            #pragma unroll
            for (int t = 0; t < 4; t++)
                #pragma unroll
                for (int u = 0; u < 4; u++)
                    mma_f16(acc[t][u], av[t], bv[u]);
        }

        if (c + 1 < NC) {
            __syncthreads();
            uint32_t* Ad = gsm + ((c + 1) & 1) * GS_TILE;
            uint32_t* Bd = gsm + 2 * GS_TILE + ((c + 1) & 1) * GS_TILE;
            #pragma unroll
            for (int i = 0; i < 4; i++) {
                int g = tid + i * 256;
                int row = g >> 3, q = g & 7;
                *(uint2*)&Ad[row * GS_AS + q * 2] = pah[i];
                *(uint2*)&Bd[row * GS_AS + q * 2] = pbh[i];
            }
            __syncthreads();
        }
    }

    #pragma unroll
    for (int t = 0; t < 4; t++) {
        int r0 = m0 + mw * 64 + t * 16 + qd;
        #pragma unroll
        for (int u = 0; u < 4; u++) {
            int col = n0b + nw * 32 + u * 8 + pd * 2;
            float v0 = acc[t][u][0], v1 = acc[t][u][1];
            float v2 = acc[t][u][2], v3 = acc[t][u][3];
            if (Ch) {
                *(uint32_t*)&Ch[(size_t)r0 * DM + col] = h2u(v0 * outScale, v1 * outScale);
                *(uint32_t*)&Ch[(size_t)(r0 + 8) * DM + col] = h2u(v2 * outScale, v3 * outScale);
            } else {
                if (sigmoidFlag) {
                    v0 = 1.f / (1.f + __expf(-v0));
                    v1 = 1.f / (1.f + __expf(-v1));
                    v2 = 1.f / (1.f + __expf(-v2));
                    v3 = 1.f / (1.f + __expf(-v3));
                }
                *(float2*)&Cf[(size_t)r0 * DM + col]       = make_float2(v0, v1);
                *(float2*)&Cf[(size_t)(r0 + 8) * DM + col] = make_float2(v2, v3);
            }
        }
    }
}

// ---------------- K+V fused GEMM: half A (pe), half W, pure-copy staging ----------
// grid (4, 128): bx&1 -> n-block, bx>>1 -> K vs V.  Kd = 192, NC = 6
__global__ void __launch_bounds__(256, 2) kvgemm_kernel() {
    extern __shared__ uint32_t gsm[];
    int tid = threadIdx.x;
    int lane = tid & 31, wid = tid >> 5;
    int mw = wid & 1, nw = wid >> 1;
    int qd = lane >> 2, pd = lane & 3;
    int bx = blockIdx.x;
    int n0b = (bx & 1) * 128;
    const __half* A = g_peh;
    const __half* W = (bx >> 1) ? g_Wvh : g_Wkh;
    __half* C = (bx >> 1) ? g_Vh : g_Kh;
    int m0 = blockIdx.y * 128;
    const int NC = 6;

    float acc[4][4][4];
    #pragma unroll
    for (int t = 0; t < 4; t++)
        #pragma unroll
        for (int u = 0; u < 4; u++)
            #pragma unroll
            for (int j = 0; j < 4; j++) acc[t][u][j] = 0.f;

    {   // stage chunk 0: A 512 uint4 + B 512 uint4 -> 4 per thread
        uint32_t* Ad = gsm;
        uint32_t* Bd = gsm + 2 * GS_TILE;
        #pragma unroll
        for (int i = 0; i < 2; i++) {
            int g = tid + i * 256;
            int row = g >> 2, q = g & 3;
            *(uint4*)&Ad[row * GS_AS + q * 4] =
                *(const uint4*)&A[(size_t)(m0 + row) * D3 + q * 8];
            *(uint4*)&Bd[row * GS_AS + q * 4] =
                *(const uint4*)&W[(size_t)(n0b + row) * D3 + q * 8];
        }
    }
    __syncthreads();

    for (int c = 0; c < NC; c++) {
        const uint32_t* As = gsm + (c & 1) * GS_TILE;
        const uint32_t* Bs = gsm + 2 * GS_TILE + (c & 1) * GS_TILE;

        uint4 pah[2], pbh[2];
        if (c + 1 < NC) {
            int kk = (c + 1) * 32;
            #pragma unroll
            for (int i = 0; i < 2; i++) {
                int g = tid + i * 256;
                int row = g >> 2, q = g & 3;
                pah[i] = *(const uint4*)&A[(size_t)(m0 + row) * D3 + kk + q * 8];
                pbh[i] = *(const uint4*)&W[(size_t)(n0b + row) * D3 + kk + q * 8];
            }
        }

        #pragma unroll
        for (int ks = 0; ks < 2; ks++) {
            int kw = ks * 8 + pd;
            uint4 av[4];
            uint2 bv[4];
            #pragma unroll
            for (int t = 0; t < 4; t++) {
                int r = mw * 64 + t * 16 + qd;
                av[t].x = As[r * GS_AS + kw];
                av[t].y = As[(r + 8) * GS_AS + kw];
                av[t].z = As[r * GS_AS + kw + 4];
                av[t].w = As[(r + 8) * GS_AS + kw + 4];
            }
            #pragma unroll
            for (int u = 0; u < 4; u++) {
                int cl = nw * 32 + u * 8 + qd;
                bv[u].x = Bs[cl * GS_AS + kw];
                bv[u].y = Bs[cl * GS_AS + kw + 4];
            }
            #pragma unroll
            for (int t = 0; t < 4; t++)
                #pragma unroll
                for (int u = 0; u < 4; u++)
                    mma_f16(acc[t][u], av[t], bv[u]);
        }

        if (c + 1 < NC) {
            __syncthreads();
            uint32_t* Ad = gsm + ((c + 1) & 1) * GS_TILE;
            uint32_t* Bd = gsm + 2 * GS_TILE + ((c + 1) & 1) * GS_TILE;
            #pragma unroll
            for (int i = 0; i < 2; i++) {
                int g = tid + i * 256;
                int row = g >> 2, q = g & 3;
                *(uint4*)&Ad[row * GS_AS + q * 4] = pah[i];
                *(uint4*)&Bd[row * GS_AS + q * 4] = pbh[i];
            }
            __syncthreads();
        }
    }

    #pragma unroll
    for (int t = 0; t < 4; t++) {
        int r0 = m0 + mw * 64 + t * 16 + qd;
        #pragma unroll
        for (int u = 0; u < 4; u++) {
            int col = n0b + nw * 32 + u * 8 + pd * 2;
            *(uint32_t*)&C[(size_t)r0 * DM + col] = h2u(acc[t][u][0], acc[t][u][1]);
            *(uint32_t*)&C[(size_t)(r0 + 8) * DM + col] = h2u(acc[t][u][2], acc[t][u][3]);
        }
    }
}

// ---------------- weight prep kernels ---------------------------------------------
__global__ void wprep_kernel(const float* __restrict__ w3, const float* __restrict__ w5,
                             const float* __restrict__ w7) {
    int idx = blockIdx.x * 256 + threadIdx.x;
    if (idx >= 7 * 192 * 72) return;
    int t = idx / (192 * 72);
    int rem = idx % (192 * 72);
    int c = rem / 72;
    int i = rem % 72;
    float v = 0.f;
    if (i < 64) {
        if (c < 64)       { if (t >= 2 && t <= 4) v = w3[(c * 64 + i) * 3 + (t - 2)]; }
        else if (c < 128) { int cc = c - 64; if (t >= 1 && t <= 5) v = w5[(cc * 64 + i) * 5 + (t - 1)]; }
        else              { int cc = c - 128; v = w7[(cc * 64 + i) * 7 + t]; }
    }
    ((__half*)g_wh)[idx] = __float2half_rn(v);
}

__global__ void wprep2_kernel(const float* __restrict__ Wk, const float* __restrict__ Wv,
                              const float* __restrict__ Wf) {
    int idx = blockIdx.x * 256 + threadIdx.x;
    const int NK = DM * D3;   // 49152
    if (idx < NK) g_Wkh[idx] = __float2half_rn(Wk[idx]);
    else if (idx < 2 * NK) g_Wvh[idx - NK] = __float2half_rn(Wv[idx - NK]);
    else if (idx < 2 * NK + DM * DM) g_Wfh[idx - 2 * NK] = __float2half_rn(Wf[idx - 2 * NK]);
}

// ---------------- multi-scale conv: 128-thr blocks, weight-frag pipelining --------
#define CXR2 38
#define CXS 36
#define CONV_SMEM (CXR2 * CXS * 4)   // 5472 B

__device__ __forceinline__ constexpr int conv_abase(int tp) {
    return (tp >= 2 && tp <= 4) ? 0 : ((tp == 1 || tp == 5) ? 64 : 128);
}

__global__ void __launch_bounds__(128) conv_kernel(
    const float* __restrict__ xv, const float* __restrict__ b3,
    const float* __restrict__ b5, const float* __restrict__ b7) {
    extern __shared__ uint32_t csm[];
    uint32_t* xvs = csm;
    int blk = blockIdx.x;
    int b = blk >> 4;
    int s0 = (blk & 15) * 32;
    int tid = threadIdx.x;
    int lane = tid & 31, nw = tid >> 5;
    int qd = lane >> 2, pd = lane & 3;

    for (int g = tid; g < CXR2 * 16; g += 128) {
        int row = g >> 4, c4 = g & 15;
        int s = s0 - 3 + row;
        float4 v = make_float4(0.f, 0.f, 0.f, 0.f);
        if (s >= 0 && s < MN) v = *(const float4*)&xv[((size_t)b * MN + s) * VD + c4 * 4];
        *(uint2*)&xvs[row * CXS + c4 * 2] = make_uint2(h2u(v.x, v.y), h2u(v.z, v.w));
    }
    __syncthreads();

    float acc[2][6][4];
    #pragma unroll
    for (int t = 0; t < 2; t++)
        #pragma unroll
        for (int u = 0; u < 6; u++)
            #pragma unroll
            for (int j = 0; j < 4; j++) acc[t][u][j] = 0.f;

    uint2 bvb[2][6];
    {
        const int ab0 = conv_abase(0);
        #pragma unroll
        for (int u = 0; u < 6; u++) {
            int c0 = nw * 48 + u * 8;
            if (c0 >= ab0) {
                int gi = (0 * 192 + c0 + qd) * 36 + 0 * 8 + pd;
                bvb[0][u].x = __ldg(&g_wh[gi]);
                bvb[0][u].y = __ldg(&g_wh[gi + 4]);
            }
        }
    }

    #pragma unroll
    for (int step = 0; step < 28; step++) {
        const int tp = step >> 2, ks = step & 3;
        const int abase = conv_abase(tp);

        if (step + 1 < 28) {
            const int tp2 = (step + 1) >> 2, ks2 = (step + 1) & 3;
            const int ab2 = conv_abase(tp2);
            #pragma unroll
            for (int u = 0; u < 6; u++) {
                int c0 = nw * 48 + u * 8;
                if (c0 >= ab2) {
                    int gi = (tp2 * 192 + c0 + qd) * 36 + ks2 * 8 + pd;
                    bvb[(step + 1) & 1][u].x = __ldg(&g_wh[gi]);
                    bvb[(step + 1) & 1][u].y = __ldg(&g_wh[gi + 4]);
                }
            }
        }

        uint4 av[2];
        #pragma unroll
        for (int t = 0; t < 2; t++) {
            int r = t * 16 + qd + tp;
            av[t].x = xvs[r * CXS + ks * 8 + pd];
            av[t].z = xvs[r * CXS + ks * 8 + pd + 4];
            av[t].y = xvs[(r + 8) * CXS + ks * 8 + pd];
            av[t].w = xvs[(r + 8) * CXS + ks * 8 + pd + 4];
        }
        #pragma unroll
        for (int u = 0; u < 6; u++) {
            int c0 = nw * 48 + u * 8;
            if (c0 >= abase) {
                #pragma unroll
                for (int t = 0; t < 2; t++)
                    mma_f16(acc[t][u], av[t], bvb[step & 1][u]);
            }
        }
    }

    #pragma unroll
    for (int t = 0; t < 2; t++) {
        int s = s0 + t * 16 + qd;
        #pragma unroll
        for (int u = 0; u < 6; u++) {
            int col = nw * 48 + u * 8 + pd * 2;
            float bb0 = col < 64 ? b3[col] : (col < 128 ? b5[col - 64] : b7[col - 128]);
            int c1 = col + 1;
            float bb1 = c1 < 64 ? b3[c1] : (c1 < 128 ? b5[c1 - 64] : b7[c1 - 128]);
            *(float2*)&g_xm[((size_t)b * MN + s) * D3 + col] =
                make_float2(acc[t][u][0] + bb0, acc[t][u][1] + bb1);
            *(float2*)&g_xm[((size_t)b * MN + s + 8) * D3 + col] =
                make_float2(acc[t][u][2] + bb0, acc[t][u][3] + bb1);
        }
    }
}

// ---------------- pos_sum[j,d] = sum_i emb[clip(j-i,-30,30)+30, d] ----------------
__global__ void possum_kernel(const float* __restrict__ emb) {
    int j = blockIdx.x;
    int d = threadIdx.x;
    float acc = 0.f;
    #pragma unroll
    for (int delta = -29; delta <= 29; delta++) {
        int i = j - delta;
        if (i >= 0 && i < MN) acc += emb[(delta + 30) * D3 + d];
    }
    int cpos = j - 29;
    if (cpos > 0) acc += (float)cpos * emb[60 * D3 + d];
    int cneg = 482 - j;
    if (cneg > 0) acc += (float)cneg * emb[0 * D3 + d];
    g_pos_sum[j * D3 + d] = acc;
}

// ---------------- rel-pos encoding -> fp16 output ----------------------------------
__global__ void pe_kernel(const float* __restrict__ emb,
                          const float* __restrict__ dww, const float* __restrict__ dwb) {
    int row = blockIdx.x;          // b*MN + j
    int j = row & (MN - 1);
    int d = threadIdx.x;           // 192
    size_t base = (size_t)row * D3 + d;
    float xc = g_xm[base];
    float fC = xc + emb[30 * D3 + d];
    float fL = (j > 0)      ? g_xm[base - D3] + emb[29 * D3 + d] : 0.f;
    float fR = (j < MN - 1) ? g_xm[base + D3] + emb[31 * D3 + d] : 0.f;
    float diag = fL * dww[d * 3 + 0] + fC * dww[d * 3 + 1] + fR * dww[d * 3 + 2] + dwb[d];
    g_peh[base] = __float2half_rn(xc + (g_pos_sum[j * D3 + d] - fC + diag) * (1.0f / (float)MN));
}

// ---------------- attention on fp16 m16n8k16 ---------------------------------------
#define AK_STRIDE 20
#define AV_STRIDE 260
#define ATT_SMEM ((MN * AK_STRIDE + DK * AV_STRIDE) * 4)   // 74240 B

__global__ void __launch_bounds__(256, 2) attn_kernel() {
    extern __shared__ uint32_t ash[];
    uint32_t* Ks = ash;
    uint32_t* VT = ash + MN * AK_STRIDE;
    int blk = blockIdx.x;
    int qblk = blk & 3;
    int h = (blk >> 2) & 7;
    int b = blk >> 5;
    int tid = threadIdx.x;
    int lane = tid & 31, wid = tid >> 5;
    int qd = lane >> 2, pd = lane & 3;

    const __half* Kg = g_Kh + (size_t)b * MN * DM + h * DK;
    for (int i = tid; i < MN * 4; i += 256) {
        int s = i >> 2, c8 = i & 3;
        uint4 kv = *(const uint4*)&Kg[(size_t)s * DM + c8 * 8];
        *(uint4*)&Ks[s * AK_STRIDE + c8 * 4] = kv;
    }
    const __half* Vg = g_Vh + (size_t)b * MN * DM + h * DK;
    for (int g = tid; g < 1024; g += 256) {
        int spair = g >> 2, q = g & 3;
        int s = spair * 2;
        uint4 a = *(const uint4*)&Vg[(size_t)s * DM + q * 8];
        uint4 bq = *(const uint4*)&Vg[(size_t)(s + 1) * DM + q * 8];
        int d0 = q * 8;
        VT[(d0 + 0) * AV_STRIDE + spair] = (a.x & 0xFFFFu) | (bq.x << 16);
        VT[(d0 + 1) * AV_STRIDE + spair] = (a.x >> 16) | (bq.x & 0xFFFF0000u);
        VT[(d0 + 2) * AV_STRIDE + spair] = (a.y & 0xFFFFu) | (bq.y << 16);
        VT[(d0 + 3) * AV_STRIDE + spair] = (a.y >> 16) | (bq.y & 0xFFFF0000u);
        VT[(d0 + 4) * AV_STRIDE + spair] = (a.z & 0xFFFFu) | (bq.z << 16);
        VT[(d0 + 5) * AV_STRIDE + spair] = (a.z >> 16) | (bq.z & 0xFFFF0000u);
        VT[(d0 + 6) * AV_STRIDE + spair] = (a.w & 0xFFFFu) | (bq.w << 16);
        VT[(d0 + 7) * AV_STRIDE + spair] = (a.w >> 16) | (bq.w & 0xFFFF0000u);
    }
    __syncthreads();

    int m0 = qblk * 256 + wid * 32;
    const __half* Qg = g_Qh + ((size_t)b * LL + m0) * DM + h * DK;
    uint4 aq[2][2];
    #pragma unroll
    for (int t = 0; t < 2; t++)
        #pragma unroll
        for (int ks = 0; ks < 2; ks++) {
            int r = t * 16 + qd;
            int c = ks * 16 + pd * 2;
            aq[t][ks].x = *(const uint32_t*)&Qg[(size_t)r * DM + c];
            aq[t][ks].y = *(const uint32_t*)&Qg[(size_t)(r + 8) * DM + c];
            aq[t][ks].z = *(const uint32_t*)&Qg[(size_t)r * DM + c + 8];
            aq[t][ks].w = *(const uint32_t*)&Qg[(size_t)(r + 8) * DM + c + 8];
        }

    float o[2][4][4];
    #pragma unroll
    for (int t = 0; t < 2; t++)
        #pragma unroll
        for (int nv = 0; nv < 4; nv++)
            #pragma unroll
            for (int j = 0; j < 4; j++) o[t][nv][j] = 0.f;
    float rs[2][2] = {{0.f, 0.f}, {0.f, 0.f}};

    for (int s0 = 0; s0 < MN; s0 += 16) {
        uint2 bk[2][2];
        #pragma unroll
        for (int n = 0; n < 2; n++)
            #pragma unroll
            for (int ks = 0; ks < 2; ks++) {
                int w = (s0 + n * 8 + qd) * AK_STRIDE + ks * 8 + pd;
                bk[n][ks] = make_uint2(Ks[w], Ks[w + 4]);
            }

        float c[2][2][4];
        #pragma unroll
        for (int t = 0; t < 2; t++)
            #pragma unroll
            for (int n = 0; n < 2; n++) {
                #pragma unroll
                for (int j = 0; j < 4; j++) c[t][n][j] = 0.f;
                #pragma unroll
                for (int ks = 0; ks < 2; ks++)
                    mma_f16(c[t][n], aq[t][ks], bk[n][ks]);
            }

        uint4 ap[2];
        #pragma unroll
        for (int t = 0; t < 2; t++) {
            float p00 = ex2f(c[t][0][0]), p01 = ex2f(c[t][0][1]);
            float p02 = ex2f(c[t][0][2]), p03 = ex2f(c[t][0][3]);
            float p10 = ex2f(c[t][1][0]), p11 = ex2f(c[t][1][1]);
            float p12 = ex2f(c[t][1][2]), p13 = ex2f(c[t][1][3]);
            rs[t][0] += p00 + p01 + p10 + p11;
            rs[t][1] += p02 + p03 + p12 + p13;
            ap[t] = make_uint4(h2u(p00, p01), h2u(p02, p03),
                               h2u(p10, p11), h2u(p12, p13));
        }

        uint2 bv[4];
        #pragma unroll
        for (int nv = 0; nv < 4; nv++) {
            int w = (nv * 8 + qd) * AV_STRIDE + (s0 >> 1) + pd;
            bv[nv] = make_uint2(VT[w], VT[w + 4]);
        }

        #pragma unroll
        for (int t = 0; t < 2; t++)
            #pragma unroll
            for (int nv = 0; nv < 4; nv++)
                mma_f16(o[t][nv], ap[t], bv[nv]);
    }

    __half* Ah = g_attnh;
    #pragma unroll
    for (int t = 0; t < 2; t++) {
        #pragma unroll
        for (int r = 0; r < 2; r++) {
            rs[t][r] += __shfl_xor_sync(0xFFFFFFFFu, rs[t][r], 1);
            rs[t][r] += __shfl_xor_sync(0xFFFFFFFFu, rs[t][r], 2);
        }
        float inv0 = 1.f / rs[t][0];
        float inv1 = 1.f / rs[t][1];
        int r0 = m0 + t * 16 + qd;
        #pragma unroll
        for (int nv = 0; nv < 4; nv++) {
            int col = h * DK + nv * 8 + pd * 2;
            *(uint32_t*)&Ah[((size_t)b * LL + r0) * DM + col] =
                h2u(o[t][nv][0] * inv0, o[t][nv][1] * inv0);
            *(uint32_t*)&Ah[((size_t)b * LL + r0 + 8) * DM + col] =
                h2u(o[t][nv][2] * inv1, o[t][nv][3] * inv1);
        }
    }
}

// ---------------- fc GEMM fused with gate + residual + LayerNorm ------------------
#define FA_TILE (64 * GS_AS)
#define FB_TILE (256 * GS_AS)
#define FSM_BYTES ((2 * FA_TILE + 2 * FB_TILE + 512) * 4)   // 53248 B

__global__ void __launch_bounds__(256, 2) fcln_kernel(
    const float* __restrict__ fb, const float* __restrict__ xs,
    const float* __restrict__ lnw, const float* __restrict__ lnb,
    float* __restrict__ out) {
    extern __shared__ uint32_t fsm[];
    float* red = (float*)(fsm + 2 * FA_TILE + 2 * FB_TILE);
    const __half* A = g_attnh;
    const __half* Wf = g_Wfh;
    int tid = threadIdx.x;
    int lane = tid & 31, wid = tid >> 5;
    int mw = wid & 1, nw = wid >> 1;
    int qd = lane >> 2, pd = lane & 3;
    int row0 = blockIdx.x * 64;
    int b = row0 >> 10;
    const int NC = 8;

    float acc[2][8][4];
    #pragma unroll
    for (int t = 0; t < 2; t++)
        #pragma unroll
        for (int u = 0; u < 8; u++)
            #pragma unroll
            for (int j = 0; j < 4; j++) acc[t][u][j] = 0.f;

    {   // A: 256 uint4, B: 1024 uint4 -> 5 per thread
        uint32_t* Ad = fsm;
        uint32_t* Bd = fsm + 2 * FA_TILE;
        #pragma unroll
        for (int i = 0; i < 5; i++) {
            int g = tid + i * 256;
            if (g < 256) {
                int row = g >> 2, q = g & 3;
                *(uint4*)&Ad[row * GS_AS + q * 4] =
                    *(const uint4*)&A[(size_t)(row0 + row) * DM + q * 8];
            } else {
                int j = g - 256;
                int row = j >> 2, q = j & 3;
                *(uint4*)&Bd[row * GS_AS + q * 4] =
                    *(const uint4*)&Wf[(size_t)row * DM + q * 8];
            }
        }
    }
    __syncthreads();

    for (int c = 0; c < NC; c++) {
        const uint32_t* As = fsm + (c & 1) * FA_TILE;
        const uint32_t* Bs = fsm + 2 * FA_TILE + (c & 1) * FB_TILE;

        uint4 pf[5];
        if (c + 1 < NC) {
            int kk = (c + 1) * 32;
            #pragma unroll
            for (int i = 0; i < 5; i++) {
                int g = tid + i * 256;
                if (g < 256) {
                    int row = g >> 2, q = g & 3;
                    pf[i] = *(const uint4*)&A[(size_t)(row0 + row) * DM + kk + q * 8];
                } else {
                    int j = g - 256;
                    int row = j >> 2, q = j & 3;
                    pf[i] = *(const uint4*)&Wf[(size_t)row * DM + kk + q * 8];
                }
            }
        }

        #pragma unroll
        for (int ks = 0; ks < 2; ks++) {
            int kw = ks * 8 + pd;
            uint4 av[2];
            uint2 bv[8];
            #pragma unroll
            for (int t = 0; t < 2; t++) {
                int r = mw * 32 + t * 16 + qd;
                av[t].x = As[r * GS_AS + kw];
                av[t].y = As[(r + 8) * GS_AS + kw];
                av[t].z = As[r * GS_AS + kw + 4];
                av[t].w = As[(r + 8) * GS_AS + kw + 4];
            }
            #pragma unroll
            for (int u = 0; u < 8; u++) {
                int cl = nw * 64 + u * 8 + qd;
                bv[u].x = Bs[cl * GS_AS + kw];
                bv[u].y = Bs[cl * GS_AS + kw + 4];
            }
            #pragma unroll
            for (int t = 0; t < 2; t++)
                #pragma unroll
                for (int u = 0; u < 8; u++)
                    mma_f16(acc[t][u], av[t], bv[u]);
        }

        if (c + 1 < NC) {
            __syncthreads();
            uint32_t* Ad = fsm + ((c + 1) & 1) * FA_TILE;
            uint32_t* Bd = fsm + 2 * FA_TILE + ((c + 1) & 1) * FB_TILE;
            #pragma unroll
            for (int i = 0; i < 5; i++) {
                int g = tid + i * 256;
                if (g < 256) {
                    int row = g >> 2, q = g & 3;
                    *(uint4*)&Ad[row * GS_AS + q * 4] = pf[i];
                } else {
                    int j = g - 256;
                    int row = j >> 2, q = j & 3;
                    *(uint4*)&Bd[row * GS_AS + q * 4] = pf[i];
                }
            }
            __syncthreads();
        }
    }

    __syncthreads();
    #pragma unroll
    for (int t = 0; t < 2; t++) {
        #pragma unroll
        for (int hf = 0; hf < 2; hf++) {
            int lr = mw * 32 + t * 16 + qd + hf * 8;
            int r = row0 + lr;
            int l = r & 1023;
            const float* gam = g_gamma + ((size_t)b * MN + (l & (MN - 1))) * DM;
            const float* xr = xs + (size_t)r * DM;
            float s1 = 0.f, s2 = 0.f;
            #pragma unroll
            for (int u = 0; u < 8; u++) {
                int col = nw * 64 + u * 8 + pd * 2;
                int j0 = hf * 2;
                float v0 = xr[col] + gam[col] * (acc[t][u][j0] + fb[col]);
                float v1 = xr[col + 1] + gam[col + 1] * (acc[t][u][j0 + 1] + fb[col + 1]);
                acc[t][u][j0] = v0;
                acc[t][u][j0 + 1] = v1;
                s1 += v0 + v1;
                s2 += v0 * v0 + v1 * v1;
            }
            s1 += __shfl_xor_sync(0xFFFFFFFFu, s1, 1);
            s1 += __shfl_xor_sync(0xFFFFFFFFu, s1, 2);
            s2 += __shfl_xor_sync(0xFFFFFFFFu, s2, 1);
            s2 += __shfl_xor_sync(0xFFFFFFFFu, s2, 2);
            if (pd == 0) {
                red[nw * 64 + lr] = s1;
                red[256 + nw * 64 + lr] = s2;
            }
        }
    }
    __syncthreads();
    #pragma unroll
    for (int t = 0; t < 2; t++) {
        #pragma unroll
        for (int hf = 0; hf < 2; hf++) {
            int lr = mw * 32 + t * 16 + qd + hf * 8;
            int r = row0 + lr;
            float t1 = red[lr] + red[64 + lr] + red[128 + lr] + red[192 + lr];
            float t2 = red[256 + lr] + red[320 + lr] + red[384 + lr] + red[448 + lr];
            float mu = t1 * (1.f / 256.f);
            float var = t2 * (1.f / 256.f) - mu * mu;
            float rstd = rsqrtf(var + 1e-5f);
            #pragma unroll
            for (int u = 0; u < 8; u++) {
                int col = nw * 64 + u * 8 + pd * 2;
                int j0 = hf * 2;
                float v0 = (acc[t][u][j0] - mu) * rstd * lnw[col] + lnb[col];
                float v1 = (acc[t][u][j0 + 1] - mu) * rstd * lnw[col + 1] + lnb[col + 1];
                *(float2*)&out[(size_t)r * DM + col] = make_float2(v0, v1);
            }
        }
    }
}

// ---------------- launch: fork/join side stream for Q + Gamma ----------------------
extern "C" void kernel_launch(void* const* d_in, const int* in_sizes, int n_in,
                              void* d_out, int out_size) {
    const float* x_spatial  = (const float*)d_in[0];
    const float* x_velocity = (const float*)d_in[1];
    const float* Wg    = (const float*)d_in[2];
    const float* ms_w3 = (const float*)d_in[3];
    const float* ms_b3 = (const float*)d_in[4];
    const float* ms_w5 = (const float*)d_in[5];
    const float* ms_b5 = (const float*)d_in[6];
    const float* ms_w7 = (const float*)d_in[7];
    const float* ms_b7 = (const float*)d_in[8];
    const float* rel_emb = (const float*)d_in[9];
    const float* dw_w  = (const float*)d_in[10];
    const float* dw_b  = (const float*)d_in[11];
    const float* Wq    = (const float*)d_in[12];
    const float* Wk    = (const float*)d_in[13];
    const float* Wv    = (const float*)d_in[14];
    const float* fc_w  = (const float*)d_in[15];
    const float* fc_b  = (const float*)d_in[16];
    const float* ln_w  = (const float*)d_in[17];
    const float* ln_b  = (const float*)d_in[18];
    float* out = (float*)d_out;

    float *p_gamma;
    __half *p_Qh;
    cudaGetSymbolAddress((void**)&p_gamma, g_gamma);
    cudaGetSymbolAddress((void**)&p_Qh,    g_Qh);

    cudaFuncSetAttribute(conv_kernel,   cudaFuncAttributeMaxDynamicSharedMemorySize, CONV_SMEM);
    cudaFuncSetAttribute(attn_kernel,   cudaFuncAttributeMaxDynamicSharedMemorySize, ATT_SMEM);
    cudaFuncSetAttribute(mgemm_kernel,  cudaFuncAttributeMaxDynamicSharedMemorySize, GSM_BYTES);
    cudaFuncSetAttribute(kvgemm_kernel, cudaFuncAttributeMaxDynamicSharedMemorySize, GSM_BYTES);
    cudaFuncSetAttribute(fcln_kernel,   cudaFuncAttributeMaxDynamicSharedMemorySize, FSM_BYTES);

    static cudaStream_t s_side = nullptr;
    static cudaEvent_t ev_fork = nullptr, ev_join = nullptr;
    if (s_side == nullptr) {
        cudaStreamCreateWithFlags(&s_side, cudaStreamNonBlocking);
        cudaEventCreateWithFlags(&ev_fork, cudaEventDisableTiming);
        cudaEventCreateWithFlags(&ev_join, cudaEventDisableTiming);
    }

    const float qsc = 0.17677669529663687f * 1.4426950408889634f;   // log2e/sqrt(dk)

    wprep_kernel<<<(7 * 192 * 72 + 255) / 256, 256>>>(ms_w3, ms_w5, ms_w7);
    wprep2_kernel<<<(2 * DM * D3 + DM * DM + 255) / 256, 256>>>(Wk, Wv, fc_w);
    possum_kernel<<<MN, D3>>>(rel_emb);

    // fork: Q projection + Gamma on side stream
    cudaEventRecord(ev_fork, 0);
    cudaStreamWaitEvent(s_side, ev_fork, 0);
    mgemm_kernel<<<dim3(2, BB * LL / 128), 256, GSM_BYTES, s_side>>>(
        x_spatial, Wq, nullptr, p_Qh, SD, 0, qsc);
    mgemm_kernel<<<dim3(2, BB * MN / 128), 256, GSM_BYTES, s_side>>>(
        x_velocity, Wg, p_gamma, nullptr, VD, 1, 1.f);
    cudaEventRecord(ev_join, s_side);

    // main chain: conv -> pe -> K+V (fused launch)
    conv_kernel<<<BB * 16, 128, CONV_SMEM>>>(x_velocity, ms_b3, ms_b5, ms_b7);
    pe_kernel<<<BB * MN, D3>>>(rel_emb, dw_w, dw_b);
    kvgemm_kernel<<<dim3(4, BB * MN / 128), 256, GSM_BYTES>>>();

    cudaStreamWaitEvent(0, ev_join, 0);
    attn_kernel<<<BB * NH * 4, 256, ATT_SMEM>>>();
    fcln_kernel<<<BB * LL / 64, 256, FSM_BYTES>>>(fc_b, x_spatial, ln_w, ln_b, out);
}

// round 11
// speedup vs baseline: 6.7919x; 1.0592x over previous
#include <cuda_runtime.h>
#include <cuda_fp16.h>
#include <math.h>
#include <stdint.h>

#define BB 32
#define LL 1024
#define MN 512
#define SD 256
#define VD 64
#define D3 192
#define DM 256
#define NH 8
#define DK 32

// ---------------- scratch (device globals; no allocation allowed) ----------------
__device__ float g_pos_sum[MN * D3];
__device__ float g_gamma[BB * MN * DM];
__device__ __half g_xmh[BB * MN * D3];
__device__ __half g_peh[BB * MN * D3];
__device__ __half g_Qh[BB * LL * DM];
__device__ __half g_Kh[BB * MN * DM];
__device__ __half g_Vh[BB * MN * DM];
__device__ __half g_attnh[BB * LL * DM];
__device__ __half g_Wkh[DM * D3];
__device__ __half g_Wvh[DM * D3];
__device__ __half g_Wfh[DM * DM];
__device__ uint32_t g_wh[7 * 192 * 36];   // conv weights fp16: [tap][192 ch][72 halves]

// ================= helpers =========================================================
__device__ __forceinline__ uint32_t h2u(float a, float b) {
    __half2 h = __floats2half2_rn(a, b);
    return *(uint32_t*)&h;
}
__device__ __forceinline__ float2 u2f2(uint32_t u) {
    return __half22float2(*(__half2*)&u);
}
__device__ __forceinline__ float ex2f(float x) {
    float r;
    asm("ex2.approx.f32 %0, %1;" : "=f"(r) : "f"(x));
    return r;
}
__device__ __forceinline__ void mma_f16(float* c, uint4 a, uint2 b) {
    asm("mma.sync.aligned.m16n8k16.row.col.f32.f16.f16.f32 "
        "{%0,%1,%2,%3}, {%4,%5,%6,%7}, {%8,%9}, {%0,%1,%2,%3};"
        : "+f"(c[0]), "+f"(c[1]), "+f"(c[2]), "+f"(c[3])
        : "r"(a.x), "r"(a.y), "r"(a.z), "r"(a.w), "r"(b.x), "r"(b.y));
}
__device__ __forceinline__ void ldmx4(uint4& v, uint32_t addr) {
    asm volatile("ldmatrix.sync.aligned.m8n8.x4.shared.b16 {%0,%1,%2,%3}, [%4];"
        : "=r"(v.x), "=r"(v.y), "=r"(v.z), "=r"(v.w) : "r"(addr));
}
__device__ __forceinline__ uint32_t smem_u32(const void* p) {
    uint32_t a;
    asm("{ .reg .u64 t; cvta.to.shared.u64 t, %1; cvt.u32.u64 %0, t; }" : "=r"(a) : "l"(p));
    return a;
}

// lane-constant fragment offsets (A m16k16 / B 2x(n8k16) ldmatrix.x4 maps)
#define LANE_FRAG_OFFS(lane)                                   \
    int rowA = (lane) & 15;                                    \
    int kA = ((lane) >> 4) * 16;          /* bytes */          \
    int rowB = ((lane) & 7) + (((lane) >> 4) << 3);            \
    int kB = ((lane) & 8) * 2;            /* bytes */

// GEMM smem: half tiles, 128 rows x 32 halves, padded to 40 halves (80 B/row)
#define GS_AS 20
#define GS_TILE (128 * GS_AS)
#define GSM_BYTES (4 * GS_TILE * 4)   // 40960 B

// ---------------- float-input GEMM (Q / Gamma; side stream) ------------------------
__global__ void __launch_bounds__(256, 2) mgemm_kernel(
    const float* __restrict__ A, const float* __restrict__ W,
    float* __restrict__ Cf, __half* __restrict__ Ch,
    int Kd, int sigmoidFlag, float outScale) {
    extern __shared__ uint32_t gsm[];
    uint32_t sb = smem_u32(gsm);
    int tid = threadIdx.x;
    int lane = tid & 31, wid = tid >> 5;
    int mw = wid & 1, nw = wid >> 1;
    int qd = lane >> 2, pd = lane & 3;
    LANE_FRAG_OFFS(lane);
    int m0 = blockIdx.y * 128;
    int n0b = blockIdx.x * 128;
    int NC = Kd >> 5;

    float acc[4][4][4];
    #pragma unroll
    for (int t = 0; t < 4; t++)
        #pragma unroll
        for (int u = 0; u < 4; u++)
            #pragma unroll
            for (int j = 0; j < 4; j++) acc[t][u][j] = 0.f;

    {
        uint32_t* Ad = gsm;
        uint32_t* Bd = gsm + 2 * GS_TILE;
        #pragma unroll
        for (int i = 0; i < 4; i++) {
            int g = tid + i * 256;
            int row = g >> 3, q = g & 7;
            float4 va = *(const float4*)&A[(size_t)(m0 + row) * Kd + q * 4];
            float4 vb = *(const float4*)&W[(size_t)(n0b + row) * Kd + q * 4];
            *(uint2*)&Ad[row * GS_AS + q * 2] = make_uint2(h2u(va.x, va.y), h2u(va.z, va.w));
            *(uint2*)&Bd[row * GS_AS + q * 2] = make_uint2(h2u(vb.x, vb.y), h2u(vb.z, vb.w));
        }
    }
    __syncthreads();

    for (int c = 0; c < NC; c++) {
        uint32_t Ab = sb + ((c & 1) ? GS_TILE * 4 : 0);
        uint32_t Bb = sb + 2 * GS_TILE * 4 + ((c & 1) ? GS_TILE * 4 : 0);

        uint2 pah[4], pbh[4];
        if (c + 1 < NC) {
            int kk = (c + 1) * 32;
            #pragma unroll
            for (int i = 0; i < 4; i++) {
                int g = tid + i * 256;
                int row = g >> 3, q = g & 7;
                float4 va = *(const float4*)&A[(size_t)(m0 + row) * Kd + kk + q * 4];
                float4 vb = *(const float4*)&W[(size_t)(n0b + row) * Kd + kk + q * 4];
                pah[i] = make_uint2(h2u(va.x, va.y), h2u(va.z, va.w));
                pbh[i] = make_uint2(h2u(vb.x, vb.y), h2u(vb.z, vb.w));
            }
        }

        #pragma unroll
        for (int ks = 0; ks < 2; ks++) {
            uint4 av[4];
            uint2 bv[4];
            #pragma unroll
            for (int t = 0; t < 4; t++)
                ldmx4(av[t], Ab + (mw * 64 + t * 16 + rowA) * 80 + ks * 32 + kA);
            uint4 b01, b23;
            ldmx4(b01, Bb + (nw * 32 + rowB) * 80 + ks * 32 + kB);
            ldmx4(b23, Bb + (nw * 32 + 16 + rowB) * 80 + ks * 32 + kB);
            bv[0] = make_uint2(b01.x, b01.y); bv[1] = make_uint2(b01.z, b01.w);
            bv[2] = make_uint2(b23.x, b23.y); bv[3] = make_uint2(b23.z, b23.w);
            #pragma unroll
            for (int t = 0; t < 4; t++)
                #pragma unroll
                for (int u = 0; u < 4; u++)
                    mma_f16(acc[t][u], av[t], bv[u]);
        }

        if (c + 1 < NC) {
            __syncthreads();
            uint32_t* Ad = gsm + (((c + 1) & 1) ? GS_TILE : 0);
            uint32_t* Bd = gsm + 2 * GS_TILE + (((c + 1) & 1) ? GS_TILE : 0);
            #pragma unroll
            for (int i = 0; i < 4; i++) {
                int g = tid + i * 256;
                int row = g >> 3, q = g & 7;
                *(uint2*)&Ad[row * GS_AS + q * 2] = pah[i];
                *(uint2*)&Bd[row * GS_AS + q * 2] = pbh[i];
            }
            __syncthreads();
        }
    }

    #pragma unroll
    for (int t = 0; t < 4; t++) {
        int r0 = m0 + mw * 64 + t * 16 + qd;
        #pragma unroll
        for (int u = 0; u < 4; u++) {
            int col = n0b + nw * 32 + u * 8 + pd * 2;
            float v0 = acc[t][u][0], v1 = acc[t][u][1];
            float v2 = acc[t][u][2], v3 = acc[t][u][3];
            if (Ch) {
                *(uint32_t*)&Ch[(size_t)r0 * DM + col] = h2u(v0 * outScale, v1 * outScale);
                *(uint32_t*)&Ch[(size_t)(r0 + 8) * DM + col] = h2u(v2 * outScale, v3 * outScale);
            } else {
                if (sigmoidFlag) {
                    v0 = 1.f / (1.f + __expf(-v0));
                    v1 = 1.f / (1.f + __expf(-v1));
                    v2 = 1.f / (1.f + __expf(-v2));
                    v3 = 1.f / (1.f + __expf(-v3));
                }
                *(float2*)&Cf[(size_t)r0 * DM + col]       = make_float2(v0, v1);
                *(float2*)&Cf[(size_t)(r0 + 8) * DM + col] = make_float2(v2, v3);
            }
        }
    }
}

// ---------------- K+V fused GEMM: half A (pe), half W, ldmatrix fragments ----------
__global__ void __launch_bounds__(256, 2) kvgemm_kernel() {
    extern __shared__ uint32_t gsm[];
    uint32_t sb = smem_u32(gsm);
    int tid = threadIdx.x;
    int lane = tid & 31, wid = tid >> 5;
    int mw = wid & 1, nw = wid >> 1;
    int qd = lane >> 2, pd = lane & 3;
    LANE_FRAG_OFFS(lane);
    int bx = blockIdx.x;
    int n0b = (bx & 1) * 128;
    const __half* A = g_peh;
    const __half* W = (bx >> 1) ? g_Wvh : g_Wkh;
    __half* C = (bx >> 1) ? g_Vh : g_Kh;
    int m0 = blockIdx.y * 128;
    const int NC = 6;

    float acc[4][4][4];
    #pragma unroll
    for (int t = 0; t < 4; t++)
        #pragma unroll
        for (int u = 0; u < 4; u++)
            #pragma unroll
            for (int j = 0; j < 4; j++) acc[t][u][j] = 0.f;

    {
        uint32_t* Ad = gsm;
        uint32_t* Bd = gsm + 2 * GS_TILE;
        #pragma unroll
        for (int i = 0; i < 2; i++) {
            int g = tid + i * 256;
            int row = g >> 2, q = g & 3;
            *(uint4*)&Ad[row * GS_AS + q * 4] =
                *(const uint4*)&A[(size_t)(m0 + row) * D3 + q * 8];
            *(uint4*)&Bd[row * GS_AS + q * 4] =
                *(const uint4*)&W[(size_t)(n0b + row) * D3 + q * 8];
        }
    }
    __syncthreads();

    for (int c = 0; c < NC; c++) {
        uint32_t Ab = sb + ((c & 1) ? GS_TILE * 4 : 0);
        uint32_t Bb = sb + 2 * GS_TILE * 4 + ((c & 1) ? GS_TILE * 4 : 0);

        uint4 pah[2], pbh[2];
        if (c + 1 < NC) {
            int kk = (c + 1) * 32;
            #pragma unroll
            for (int i = 0; i < 2; i++) {
                int g = tid + i * 256;
                int row = g >> 2, q = g & 3;
                pah[i] = *(const uint4*)&A[(size_t)(m0 + row) * D3 + kk + q * 8];
                pbh[i] = *(const uint4*)&W[(size_t)(n0b + row) * D3 + kk + q * 8];
            }
        }

        #pragma unroll
        for (int ks = 0; ks < 2; ks++) {
            uint4 av[4];
            uint2 bv[4];
            #pragma unroll
            for (int t = 0; t < 4; t++)
                ldmx4(av[t], Ab + (mw * 64 + t * 16 + rowA) * 80 + ks * 32 + kA);
            uint4 b01, b23;
            ldmx4(b01, Bb + (nw * 32 + rowB) * 80 + ks * 32 + kB);
            ldmx4(b23, Bb + (nw * 32 + 16 + rowB) * 80 + ks * 32 + kB);
            bv[0] = make_uint2(b01.x, b01.y); bv[1] = make_uint2(b01.z, b01.w);
            bv[2] = make_uint2(b23.x, b23.y); bv[3] = make_uint2(b23.z, b23.w);
            #pragma unroll
            for (int t = 0; t < 4; t++)
                #pragma unroll
                for (int u = 0; u < 4; u++)
                    mma_f16(acc[t][u], av[t], bv[u]);
        }

        if (c + 1 < NC) {
            __syncthreads();
            uint32_t* Ad = gsm + (((c + 1) & 1) ? GS_TILE : 0);
            uint32_t* Bd = gsm + 2 * GS_TILE + (((c + 1) & 1) ? GS_TILE : 0);
            #pragma unroll
            for (int i = 0; i < 2; i++) {
                int g = tid + i * 256;
                int row = g >> 2, q = g & 3;
                *(uint4*)&Ad[row * GS_AS + q * 4] = pah[i];
                *(uint4*)&Bd[row * GS_AS + q * 4] = pbh[i];
            }
            __syncthreads();
        }
    }

    #pragma unroll
    for (int t = 0; t < 4; t++) {
        int r0 = m0 + mw * 64 + t * 16 + qd;
        #pragma unroll
        for (int u = 0; u < 4; u++) {
            int col = n0b + nw * 32 + u * 8 + pd * 2;
            *(uint32_t*)&C[(size_t)r0 * DM + col] = h2u(acc[t][u][0], acc[t][u][1]);
            *(uint32_t*)&C[(size_t)(r0 + 8) * DM + col] = h2u(acc[t][u][2], acc[t][u][3]);
        }
    }
}

// ---------------- fused prep: conv weights + Wk/Wv/Wf halves + pos_sum -------------
__global__ void prep_kernel(const float* __restrict__ w3, const float* __restrict__ w5,
                            const float* __restrict__ w7, const float* __restrict__ Wk,
                            const float* __restrict__ Wv, const float* __restrict__ Wf,
                            const float* __restrict__ emb) {
    int bid = blockIdx.x;
    int tid = threadIdx.x;
    if (bid < 378) {                       // conv weights: 7*192*72 = 96768 halves
        int idx = bid * 256 + tid;
        int t = idx / (192 * 72);
        int rem = idx % (192 * 72);
        int c = rem / 72;
        int i = rem % 72;
        float v = 0.f;
        if (i < 64) {
            if (c < 64)       { if (t >= 2 && t <= 4) v = w3[(c * 64 + i) * 3 + (t - 2)]; }
            else if (c < 128) { int cc = c - 64; if (t >= 1 && t <= 5) v = w5[(cc * 64 + i) * 5 + (t - 1)]; }
            else              { int cc = c - 128; v = w7[(cc * 64 + i) * 7 + t]; }
        }
        ((__half*)g_wh)[idx] = __float2half_rn(v);
    } else if (bid < 378 + 640) {          // Wk/Wv/Wf: 163840 halves
        int idx = (bid - 378) * 256 + tid;
        const int NK = DM * D3;
        if (idx < NK) g_Wkh[idx] = __float2half_rn(Wk[idx]);
        else if (idx < 2 * NK) g_Wvh[idx - NK] = __float2half_rn(Wv[idx - NK]);
        else if (idx < 2 * NK + DM * DM) g_Wfh[idx - 2 * NK] = __float2half_rn(Wf[idx - 2 * NK]);
    } else {                               // pos_sum: 512 rows x 192
        int j = bid - (378 + 640);
        int d = tid;
        if (d < D3) {
            float acc = 0.f;
            #pragma unroll
            for (int delta = -29; delta <= 29; delta++) {
                int i = j - delta;
                if (i >= 0 && i < MN) acc += emb[(delta + 30) * D3 + d];
            }
            int cpos = j - 29;
            if (cpos > 0) acc += (float)cpos * emb[60 * D3 + d];
            int cneg = 482 - j;
            if (cneg > 0) acc += (float)cneg * emb[0 * D3 + d];
            g_pos_sum[j * D3 + d] = acc;
        }
    }
}

// ---------------- multi-scale conv: ldmatrix A frags, L2 weight B frags ------------
#define CXR2 38
#define CXS 36                  // words per xv row (72 halves = 144 B)
#define CONV_SMEM (CXR2 * CXS * 4)   // 5472 B

__device__ __forceinline__ constexpr int conv_abase(int tp) {
    return (tp >= 2 && tp <= 4) ? 0 : ((tp == 1 || tp == 5) ? 64 : 128);
}

__global__ void __launch_bounds__(128) conv_kernel(
    const float* __restrict__ xv, const float* __restrict__ b3,
    const float* __restrict__ b5, const float* __restrict__ b7) {
    extern __shared__ uint32_t csm[];
    uint32_t* xvs = csm;
    uint32_t xb = smem_u32(csm);
    int blk = blockIdx.x;
    int b = blk >> 4;
    int s0 = (blk & 15) * 32;
    int tid = threadIdx.x;
    int lane = tid & 31, nw = tid >> 5;
    int qd = lane >> 2, pd = lane & 3;
    LANE_FRAG_OFFS(lane);

    for (int g = tid; g < CXR2 * 16; g += 128) {
        int row = g >> 4, c4 = g & 15;
        int s = s0 - 3 + row;
        float4 v = make_float4(0.f, 0.f, 0.f, 0.f);
        if (s >= 0 && s < MN) v = *(const float4*)&xv[((size_t)b * MN + s) * VD + c4 * 4];
        *(uint2*)&xvs[row * CXS + c4 * 2] = make_uint2(h2u(v.x, v.y), h2u(v.z, v.w));
    }
    __syncthreads();

    float acc[2][6][4];
    #pragma unroll
    for (int t = 0; t < 2; t++)
        #pragma unroll
        for (int u = 0; u < 6; u++)
            #pragma unroll
            for (int j = 0; j < 4; j++) acc[t][u][j] = 0.f;

    uint2 bvb[2][6];
    {
        const int ab0 = conv_abase(0);
        #pragma unroll
        for (int u = 0; u < 6; u++) {
            int c0 = nw * 48 + u * 8;
            if (c0 >= ab0) {
                int gi = (0 * 192 + c0 + qd) * 36 + 0 * 8 + pd;
                bvb[0][u].x = __ldg(&g_wh[gi]);
                bvb[0][u].y = __ldg(&g_wh[gi + 4]);
            }
        }
    }

    #pragma unroll
    for (int step = 0; step < 28; step++) {
        const int tp = step >> 2, ks = step & 3;
        const int abase = conv_abase(tp);

        if (step + 1 < 28) {
            const int tp2 = (step + 1) >> 2, ks2 = (step + 1) & 3;
            const int ab2 = conv_abase(tp2);
            #pragma unroll
            for (int u = 0; u < 6; u++) {
                int c0 = nw * 48 + u * 8;
                if (c0 >= ab2) {
                    int gi = (tp2 * 192 + c0 + qd) * 36 + ks2 * 8 + pd;
                    bvb[(step + 1) & 1][u].x = __ldg(&g_wh[gi]);
                    bvb[(step + 1) & 1][u].y = __ldg(&g_wh[gi + 4]);
                }
            }
        }

        uint4 av[2];
        #pragma unroll
        for (int t = 0; t < 2; t++)
            ldmx4(av[t], xb + (t * 16 + rowA + tp) * 144 + ks * 32 + kA);
        #pragma unroll
        for (int u = 0; u < 6; u++) {
            int c0 = nw * 48 + u * 8;
            if (c0 >= abase) {
                #pragma unroll
                for (int t = 0; t < 2; t++)
                    mma_f16(acc[t][u], av[t], bvb[step & 1][u]);
            }
        }
    }

    #pragma unroll
    for (int t = 0; t < 2; t++) {
        int s = s0 + t * 16 + qd;
        #pragma unroll
        for (int u = 0; u < 6; u++) {
            int col = nw * 48 + u * 8 + pd * 2;
            float bb0 = col < 64 ? b3[col] : (col < 128 ? b5[col - 64] : b7[col - 128]);
            int c1 = col + 1;
            float bb1 = c1 < 64 ? b3[c1] : (c1 < 128 ? b5[c1 - 64] : b7[c1 - 128]);
            *(uint32_t*)&g_xmh[((size_t)b * MN + s) * D3 + col] =
                h2u(acc[t][u][0] + bb0, acc[t][u][1] + bb1);
            *(uint32_t*)&g_xmh[((size_t)b * MN + s + 8) * D3 + col] =
                h2u(acc[t][u][2] + bb0, acc[t][u][3] + bb1);
        }
    }
}

// ---------------- rel-pos encoding: half2-vectorized -------------------------------
__global__ void pe_kernel(const float* __restrict__ emb,
                          const float* __restrict__ dww, const float* __restrict__ dwb) {
    int idx = blockIdx.x * 256 + threadIdx.x;   // half2 index; total BB*MN*96
    int d2 = idx % 96;
    int r = idx / 96;
    int j = r & (MN - 1);
    int d = d2 * 2;
    const uint32_t* xm2 = (const uint32_t*)g_xmh;
    uint32_t* pe2 = (uint32_t*)g_peh;
    float2 xc = u2f2(xm2[idx]);
    float fC0 = xc.x + emb[30 * D3 + d];
    float fC1 = xc.y + emb[30 * D3 + d + 1];
    float fL0 = 0.f, fL1 = 0.f, fR0 = 0.f, fR1 = 0.f;
    if (j > 0) {
        float2 xl = u2f2(xm2[idx - 96]);
        fL0 = xl.x + emb[29 * D3 + d];
        fL1 = xl.y + emb[29 * D3 + d + 1];
    }
    if (j < MN - 1) {
        float2 xr = u2f2(xm2[idx + 96]);
        fR0 = xr.x + emb[31 * D3 + d];
        fR1 = xr.y + emb[31 * D3 + d + 1];
    }
    float dg0 = fL0 * dww[d * 3 + 0] + fC0 * dww[d * 3 + 1] + fR0 * dww[d * 3 + 2] + dwb[d];
    float dg1 = fL1 * dww[d * 3 + 3] + fC1 * dww[d * 3 + 4] + fR1 * dww[d * 3 + 5] + dwb[d + 1];
    float o0 = xc.x + (g_pos_sum[j * D3 + d] - fC0 + dg0) * (1.0f / (float)MN);
    float o1 = xc.y + (g_pos_sum[j * D3 + d + 1] - fC1 + dg1) * (1.0f / (float)MN);
    pe2[idx] = h2u(o0, o1);
}

// ---------------- attention: ldmatrix K/V fragments --------------------------------
#define AK_STRIDE 20
#define AV_STRIDE 260
#define ATT_SMEM ((MN * AK_STRIDE + DK * AV_STRIDE) * 4)   // 74240 B

__global__ void __launch_bounds__(256, 2) attn_kernel() {
    extern __shared__ uint32_t ash[];
    uint32_t* Ks = ash;
    uint32_t* VT = ash + MN * AK_STRIDE;
    uint32_t Kb = smem_u32(ash);
    uint32_t Vb = Kb + MN * AK_STRIDE * 4;
    int blk = blockIdx.x;
    int qblk = blk & 3;
    int h = (blk >> 2) & 7;
    int b = blk >> 5;
    int tid = threadIdx.x;
    int lane = tid & 31, wid = tid >> 5;
    int qd = lane >> 2, pd = lane & 3;
    LANE_FRAG_OFFS(lane);
    (void)rowA; (void)kA;

    const __half* Kg = g_Kh + (size_t)b * MN * DM + h * DK;
    for (int i = tid; i < MN * 4; i += 256) {
        int s = i >> 2, c8 = i & 3;
        uint4 kv = *(const uint4*)&Kg[(size_t)s * DM + c8 * 8];
        *(uint4*)&Ks[s * AK_STRIDE + c8 * 4] = kv;
    }
    const __half* Vg = g_Vh + (size_t)b * MN * DM + h * DK;
    for (int g = tid; g < 1024; g += 256) {
        int spair = g >> 2, q = g & 3;
        int s = spair * 2;
        uint4 a = *(const uint4*)&Vg[(size_t)s * DM + q * 8];
        uint4 bq = *(const uint4*)&Vg[(size_t)(s + 1) * DM + q * 8];
        int d0 = q * 8;
        VT[(d0 + 0) * AV_STRIDE + spair] = (a.x & 0xFFFFu) | (bq.x << 16);
        VT[(d0 + 1) * AV_STRIDE + spair] = (a.x >> 16) | (bq.x & 0xFFFF0000u);
        VT[(d0 + 2) * AV_STRIDE + spair] = (a.y & 0xFFFFu) | (bq.y << 16);
        VT[(d0 + 3) * AV_STRIDE + spair] = (a.y >> 16) | (bq.y & 0xFFFF0000u);
        VT[(d0 + 4) * AV_STRIDE + spair] = (a.z & 0xFFFFu) | (bq.z << 16);
        VT[(d0 + 5) * AV_STRIDE + spair] = (a.z >> 16) | (bq.z & 0xFFFF0000u);
        VT[(d0 + 6) * AV_STRIDE + spair] = (a.w & 0xFFFFu) | (bq.w << 16);
        VT[(d0 + 7) * AV_STRIDE + spair] = (a.w >> 16) | (bq.w & 0xFFFF0000u);
    }
    __syncthreads();

    int m0 = qblk * 256 + wid * 32;
    const __half* Qg = g_Qh + ((size_t)b * LL + m0) * DM + h * DK;
    uint4 aq[2][2];
    #pragma unroll
    for (int t = 0; t < 2; t++)
        #pragma unroll
        for (int ks = 0; ks < 2; ks++) {
            int r = t * 16 + qd;
            int c = ks * 16 + pd * 2;
            aq[t][ks].x = *(const uint32_t*)&Qg[(size_t)r * DM + c];
            aq[t][ks].y = *(const uint32_t*)&Qg[(size_t)(r + 8) * DM + c];
            aq[t][ks].z = *(const uint32_t*)&Qg[(size_t)r * DM + c + 8];
            aq[t][ks].w = *(const uint32_t*)&Qg[(size_t)(r + 8) * DM + c + 8];
        }

    float o[2][4][4];
    #pragma unroll
    for (int t = 0; t < 2; t++)
        #pragma unroll
        for (int nv = 0; nv < 4; nv++)
            #pragma unroll
            for (int j = 0; j < 4; j++) o[t][nv][j] = 0.f;
    float rs[2][2] = {{0.f, 0.f}, {0.f, 0.f}};

    for (int s0 = 0; s0 < MN; s0 += 16) {
        uint2 bk[2][2];
        #pragma unroll
        for (int ks = 0; ks < 2; ks++) {
            uint4 m;
            ldmx4(m, Kb + (s0 + rowB) * 80 + ks * 32 + kB);
            bk[0][ks] = make_uint2(m.x, m.y);
            bk[1][ks] = make_uint2(m.z, m.w);
        }

        float c[2][2][4];
        #pragma unroll
        for (int t = 0; t < 2; t++)
            #pragma unroll
            for (int n = 0; n < 2; n++) {
                #pragma unroll
                for (int j = 0; j < 4; j++) c[t][n][j] = 0.f;
                #pragma unroll
                for (int ks = 0; ks < 2; ks++)
                    mma_f16(c[t][n], aq[t][ks], bk[n][ks]);
            }

        uint4 ap[2];
        #pragma unroll
        for (int t = 0; t < 2; t++) {
            float p00 = ex2f(c[t][0][0]), p01 = ex2f(c[t][0][1]);
            float p02 = ex2f(c[t][0][2]), p03 = ex2f(c[t][0][3]);
            float p10 = ex2f(c[t][1][0]), p11 = ex2f(c[t][1][1]);
            float p12 = ex2f(c[t][1][2]), p13 = ex2f(c[t][1][3]);
            rs[t][0] += p00 + p01 + p10 + p11;
            rs[t][1] += p02 + p03 + p12 + p13;
            ap[t] = make_uint4(h2u(p00, p01), h2u(p02, p03),
                               h2u(p10, p11), h2u(p12, p13));
        }

        uint2 bv[4];
        {
            uint4 m0v, m1v;
            ldmx4(m0v, Vb + rowB * 1040 + s0 * 2 + kB);
            ldmx4(m1v, Vb + (16 + rowB) * 1040 + s0 * 2 + kB);
            bv[0] = make_uint2(m0v.x, m0v.y); bv[1] = make_uint2(m0v.z, m0v.w);
            bv[2] = make_uint2(m1v.x, m1v.y); bv[3] = make_uint2(m1v.z, m1v.w);
        }

        #pragma unroll
        for (int t = 0; t < 2; t++)
            #pragma unroll
            for (int nv = 0; nv < 4; nv++)
                mma_f16(o[t][nv], ap[t], bv[nv]);
    }

    __half* Ah = g_attnh;
    #pragma unroll
    for (int t = 0; t < 2; t++) {
        #pragma unroll
        for (int r = 0; r < 2; r++) {
            rs[t][r] += __shfl_xor_sync(0xFFFFFFFFu, rs[t][r], 1);
            rs[t][r] += __shfl_xor_sync(0xFFFFFFFFu, rs[t][r], 2);
        }
        float inv0 = 1.f / rs[t][0];
        float inv1 = 1.f / rs[t][1];
        int r0 = m0 + t * 16 + qd;
        #pragma unroll
        for (int nv = 0; nv < 4; nv++) {
            int col = h * DK + nv * 8 + pd * 2;
            *(uint32_t*)&Ah[((size_t)b * LL + r0) * DM + col] =
                h2u(o[t][nv][0] * inv0, o[t][nv][1] * inv0);
            *(uint32_t*)&Ah[((size_t)b * LL + r0 + 8) * DM + col] =
                h2u(o[t][nv][2] * inv1, o[t][nv][3] * inv1);
        }
    }
}

// ---------------- fc GEMM fused with gate + residual + LayerNorm ------------------
#define FA_TILE (64 * GS_AS)
#define FB_TILE (256 * GS_AS)
#define FSM_BYTES ((2 * FA_TILE + 2 * FB_TILE + 512) * 4)   // 53248 B

__global__ void __launch_bounds__(256, 2) fcln_kernel(
    const float* __restrict__ fb, const float* __restrict__ xs,
    const float* __restrict__ lnw, const float* __restrict__ lnb,
    float* __restrict__ out) {
    extern __shared__ uint32_t fsm[];
    uint32_t sb = smem_u32(fsm);
    float* red = (float*)(fsm + 2 * FA_TILE + 2 * FB_TILE);
    const __half* A = g_attnh;
    const __half* Wf = g_Wfh;
    int tid = threadIdx.x;
    int lane = tid & 31, wid = tid >> 5;
    int mw = wid & 1, nw = wid >> 1;
    int qd = lane >> 2, pd = lane & 3;
    LANE_FRAG_OFFS(lane);
    int row0 = blockIdx.x * 64;
    int b = row0 >> 10;
    const int NC = 8;

    float acc[2][8][4];
    #pragma unroll
    for (int t = 0; t < 2; t++)
        #pragma unroll
        for (int u = 0; u < 8; u++)
            #pragma unroll
            for (int j = 0; j < 4; j++) acc[t][u][j] = 0.f;

    {
        uint32_t* Ad = fsm;
        uint32_t* Bd = fsm + 2 * FA_TILE;
        #pragma unroll
        for (int i = 0; i < 5; i++) {
            int g = tid + i * 256;
            if (g < 256) {
                int row = g >> 2, q = g & 3;
                *(uint4*)&Ad[row * GS_AS + q * 4] =
                    *(const uint4*)&A[(size_t)(row0 + row) * DM + q * 8];
            } else {
                int j = g - 256;
                int row = j >> 2, q = j & 3;
                *(uint4*)&Bd[row * GS_AS + q * 4] =
                    *(const uint4*)&Wf[(size_t)row * DM + q * 8];
            }
        }
    }
    __syncthreads();

    for (int c = 0; c < NC; c++) {
        uint32_t Ab = sb + ((c & 1) ? FA_TILE * 4 : 0);
        uint32_t Bb = sb + 2 * FA_TILE * 4 + ((c & 1) ? FB_TILE * 4 : 0);

        uint4 pf[5];
        if (c + 1 < NC) {
            int kk = (c + 1) * 32;
            #pragma unroll
            for (int i = 0; i < 5; i++) {
                int g = tid + i * 256;
                if (g < 256) {
                    int row = g >> 2, q = g & 3;
                    pf[i] = *(const uint4*)&A[(size_t)(row0 + row) * DM + kk + q * 8];
                } else {
                    int j = g - 256;
                    int row = j >> 2, q = j & 3;
                    pf[i] = *(const uint4*)&Wf[(size_t)row * DM + kk + q * 8];
                }
            }
        }

        #pragma unroll
        for (int ks = 0; ks < 2; ks++) {
            uint4 av[2];
            uint2 bv[8];
            #pragma unroll
            for (int t = 0; t < 2; t++)
                ldmx4(av[t], Ab + (mw * 32 + t * 16 + rowA) * 80 + ks * 32 + kA);
            #pragma unroll
            for (int u2 = 0; u2 < 4; u2++) {
                uint4 m;
                ldmx4(m, Bb + (nw * 64 + u2 * 16 + rowB) * 80 + ks * 32 + kB);
                bv[u2 * 2] = make_uint2(m.x, m.y);
                bv[u2 * 2 + 1] = make_uint2(m.z, m.w);
            }
            #pragma unroll
            for (int t = 0; t < 2; t++)
                #pragma unroll
                for (int u = 0; u < 8; u++)
                    mma_f16(acc[t][u], av[t], bv[u]);
        }

        if (c + 1 < NC) {
            __syncthreads();
            uint32_t* Ad = fsm + (((c + 1) & 1) ? FA_TILE : 0);
            uint32_t* Bd = fsm + 2 * FA_TILE + (((c + 1) & 1) ? FB_TILE : 0);
            #pragma unroll
            for (int i = 0; i < 5; i++) {
                int g = tid + i * 256;
                if (g < 256) {
                    int row = g >> 2, q = g & 3;
                    *(uint4*)&Ad[row * GS_AS + q * 4] = pf[i];
                } else {
                    int j = g - 256;
                    int row = j >> 2, q = j & 3;
                    *(uint4*)&Bd[row * GS_AS + q * 4] = pf[i];
                }
            }
            __syncthreads();
        }
    }

    __syncthreads();
    #pragma unroll
    for (int t = 0; t < 2; t++) {
        #pragma unroll
        for (int hf = 0; hf < 2; hf++) {
            int lr = mw * 32 + t * 16 + qd + hf * 8;
            int r = row0 + lr;
            int l = r & 1023;
            const float* gam = g_gamma + ((size_t)b * MN + (l & (MN - 1))) * DM;
            const float* xr = xs + (size_t)r * DM;
            float s1 = 0.f, s2 = 0.f;
            #pragma unroll
            for (int u = 0; u < 8; u++) {
                int col = nw * 64 + u * 8 + pd * 2;
                int j0 = hf * 2;
                float v0 = xr[col] + gam[col] * (acc[t][u][j0] + fb[col]);
                float v1 = xr[col + 1] + gam[col + 1] * (acc[t][u][j0 + 1] + fb[col + 1]);
                acc[t][u][j0] = v0;
                acc[t][u][j0 + 1] = v1;
                s1 += v0 + v1;
                s2 += v0 * v0 + v1 * v1;
            }
            s1 += __shfl_xor_sync(0xFFFFFFFFu, s1, 1);
            s1 += __shfl_xor_sync(0xFFFFFFFFu, s1, 2);
            s2 += __shfl_xor_sync(0xFFFFFFFFu, s2, 1);
            s2 += __shfl_xor_sync(0xFFFFFFFFu, s2, 2);
            if (pd == 0) {
                red[nw * 64 + lr] = s1;
                red[256 + nw * 64 + lr] = s2;
            }
        }
    }
    __syncthreads();
    #pragma unroll
    for (int t = 0; t < 2; t++) {
        #pragma unroll
        for (int hf = 0; hf < 2; hf++) {
            int lr = mw * 32 + t * 16 + qd + hf * 8;
            int r = row0 + lr;
            float t1 = red[lr] + red[64 + lr] + red[128 + lr] + red[192 + lr];
            float t2 = red[256 + lr] + red[320 + lr] + red[384 + lr] + red[448 + lr];
            float mu = t1 * (1.f / 256.f);
            float var = t2 * (1.f / 256.f) - mu * mu;
            float rstd = rsqrtf(var + 1e-5f);
            #pragma unroll
            for (int u = 0; u < 8; u++) {
                int col = nw * 64 + u * 8 + pd * 2;
                int j0 = hf * 2;
                float v0 = (acc[t][u][j0] - mu) * rstd * lnw[col] + lnb[col];
                float v1 = (acc[t][u][j0 + 1] - mu) * rstd * lnw[col + 1] + lnb[col + 1];
                *(float2*)&out[(size_t)r * DM + col] = make_float2(v0, v1);
            }
        }
    }
}

// ---------------- launch: fork/join side stream for Q + Gamma ----------------------
extern "C" void kernel_launch(void* const* d_in, const int* in_sizes, int n_in,
                              void* d_out, int out_size) {
    const float* x_spatial  = (const float*)d_in[0];
    const float* x_velocity = (const float*)d_in[1];
    const float* Wg    = (const float*)d_in[2];
    const float* ms_w3 = (const float*)d_in[3];
    const float* ms_b3 = (const float*)d_in[4];
    const float* ms_w5 = (const float*)d_in[5];
    const float* ms_b5 = (const float*)d_in[6];
    const float* ms_w7 = (const float*)d_in[7];
    const float* ms_b7 = (const float*)d_in[8];
    const float* rel_emb = (const float*)d_in[9];
    const float* dw_w  = (const float*)d_in[10];
    const float* dw_b  = (const float*)d_in[11];
    const float* Wq    = (const float*)d_in[12];
    const float* Wk    = (const float*)d_in[13];
    const float* Wv    = (const float*)d_in[14];
    const float* fc_w  = (const float*)d_in[15];
    const float* fc_b  = (const float*)d_in[16];
    const float* ln_w  = (const float*)d_in[17];
    const float* ln_b  = (const float*)d_in[18];
    float* out = (float*)d_out;

    float *p_gamma;
    __half *p_Qh;
    cudaGetSymbolAddress((void**)&p_gamma, g_gamma);
    cudaGetSymbolAddress((void**)&p_Qh,    g_Qh);

    cudaFuncSetAttribute(conv_kernel,   cudaFuncAttributeMaxDynamicSharedMemorySize, CONV_SMEM);
    cudaFuncSetAttribute(attn_kernel,   cudaFuncAttributeMaxDynamicSharedMemorySize, ATT_SMEM);
    cudaFuncSetAttribute(mgemm_kernel,  cudaFuncAttributeMaxDynamicSharedMemorySize, GSM_BYTES);
    cudaFuncSetAttribute(kvgemm_kernel, cudaFuncAttributeMaxDynamicSharedMemorySize, GSM_BYTES);
    cudaFuncSetAttribute(fcln_kernel,   cudaFuncAttributeMaxDynamicSharedMemorySize, FSM_BYTES);

    static cudaStream_t s_side = nullptr;
    static cudaEvent_t ev_fork = nullptr, ev_join = nullptr;
    if (s_side == nullptr) {
        cudaStreamCreateWithFlags(&s_side, cudaStreamNonBlocking);
        cudaEventCreateWithFlags(&ev_fork, cudaEventDisableTiming);
        cudaEventCreateWithFlags(&ev_join, cudaEventDisableTiming);
    }

    const float qsc = 0.17677669529663687f * 1.4426950408889634f;   // log2e/sqrt(dk)

    prep_kernel<<<378 + 640 + 512, 256>>>(ms_w3, ms_w5, ms_w7, Wk, Wv, fc_w, rel_emb);

    // fork: Q projection + Gamma on side stream
    cudaEventRecord(ev_fork, 0);
    cudaStreamWaitEvent(s_side, ev_fork, 0);
    mgemm_kernel<<<dim3(2, BB * LL / 128), 256, GSM_BYTES, s_side>>>(
        x_spatial, Wq, nullptr, p_Qh, SD, 0, qsc);
    mgemm_kernel<<<dim3(2, BB * MN / 128), 256, GSM_BYTES, s_side>>>(
        x_velocity, Wg, p_gamma, nullptr, VD, 1, 1.f);
    cudaEventRecord(ev_join, s_side);

    // main chain: conv -> pe -> K+V
    conv_kernel<<<BB * 16, 128, CONV_SMEM>>>(x_velocity, ms_b3, ms_b5, ms_b7);
    pe_kernel<<<BB * MN * 96 / 256, 256>>>(rel_emb, dw_w, dw_b);
    kvgemm_kernel<<<dim3(4, BB * MN / 128), 256, GSM_BYTES>>>();

    cudaStreamWaitEvent(0, ev_join, 0);
    attn_kernel<<<BB * NH * 4, 256, ATT_SMEM>>>();
    fcln_kernel<<<BB * LL / 64, 256, FSM_BYTES>>>(fc_b, x_spatial, ln_w, ln_b, out);
}